// round 1
// baseline (speedup 1.0000x reference)
#include <cuda_runtime.h>
#include <math.h>

#define STRIDE 132   // 128 + 4 padding (floats)
#define SMEM_FLOATS (256*STRIDE + 128*STRIDE + 2048 + 128*17 + 512 + 32)
#define SMEM_BYTES (SMEM_FLOATS * 4)

#define LD4(p) (*reinterpret_cast<const float4*>(p))
#define ST4(p) (*reinterpret_cast<float4*>(p))

// Accurate full-range sin/cos: the argument x*2^f is exactly representable in
// fp32, so reduce mod 2*pi in double (exact enough to ~1e-10 abs for |phi|<1e6),
// then evaluate sincosf on the small reduced argument. Robust even under
// -use_fast_math (where sincosf degrades only for large args).
__device__ __forceinline__ void sincos_acc(float phi, float* s, float* c) {
    double p = (double)phi;
    double k = rint(p * 0.15915494309189535);               // 1/(2*pi)
    float r = (float)fma(-k, 6.283185307179586476925287, p);
    sincosf(r, s, c);
}

__global__ void __launch_bounds__(256, 1)
nerf_fused(const float* __restrict__ rays_o, const float* __restrict__ rays_d,
           const float* __restrict__ W1, const float* __restrict__ b1,
           const float* __restrict__ W2, const float* __restrict__ b2,
           const float* __restrict__ W3, const float* __restrict__ b3,
           const float* __restrict__ Wc1, const float* __restrict__ bc1,
           const float* __restrict__ Wc2, const float* __restrict__ bc2,
           float* __restrict__ out)
{
    extern __shared__ float smf[];
    float* H1t  = smf;                     // [256][STRIDE]  layer1 output, transposed
    float* Bt   = H1t + 256*STRIDE;        // [128][STRIDE]  posenc X / relu(H2) chunk / color wts
    float* Wbuf = Bt + 128*STRIDE;         // [16][128] = 2048 floats, weight staging
    float* geo  = Wbuf + 2048;             // [128][17]
    float* comp = geo + 128*17;            // [128][4]  alpha, r, g, b
    float* dirs = comp + 512;              // [32] dir posenc (27 used)

    const int ray = blockIdx.x;
    const int tid = threadIdx.x;
    const int tx = tid & 15;
    const int ty = tid >> 4;
    const int m0 = ty * 8;

    // ---------------- ray setup (all threads, redundant, cheap) ----------------
    float ox = rays_o[ray*3+0], oy = rays_o[ray*3+1], oz = rays_o[ray*3+2];
    float rdx = rays_d[ray*3+0], rdy = rays_d[ray*3+1], rdz = rays_d[ray*3+2];
    float inv_norm = 1.0f / sqrtf(rdx*rdx + rdy*rdy + rdz*rdz);
    float dx = rdx*inv_norm, dy = rdy*inv_norm, dz = rdz*inv_norm;

    float near_t, far_t;
    {
        float dd;
        dd = (fabsf(dx) < 1e-8f) ? 1e-8f : dx; float i0 = 1.0f/dd;
        dd = (fabsf(dy) < 1e-8f) ? 1e-8f : dy; float i1 = 1.0f/dd;
        dd = (fabsf(dz) < 1e-8f) ? 1e-8f : dz; float i2 = 1.0f/dd;
        float t0x=(-1.f-ox)*i0, t1x=(1.f-ox)*i0;
        float t0y=(-1.f-oy)*i1, t1y=(1.f-oy)*i1;
        float t0z=(-1.f-oz)*i2, t1z=(1.f-oz)*i2;
        float nx=fminf(t0x,t1x), fx=fmaxf(t0x,t1x);
        float ny=fminf(t0y,t1y), fy=fmaxf(t0y,t1y);
        float nz=fminf(t0z,t1z), fz=fmaxf(t0z,t1z);
        near_t = fmaxf(fmaxf(nx, fmaxf(ny, nz)), 0.02f);
        far_t  = fminf(fmaxf(fx, fmaxf(fy, fz)), 1000.f);
        far_t  = fmaxf(far_t, near_t + 0.001f);
    }
    const float dtv = (far_t - near_t) * (1.0f/128.0f);

    // ---------------- positional encoding into Bt (used as Xt[64][STRIDE]) ------
    if (tid < 128) {
        int m = tid;
        float t = near_t + ((float)m + 0.5f) * dtv;
        float px = ox + t*dx, py = oy + t*dy, pz = oz + t*dz;
        Bt[0*STRIDE+m] = px;
        Bt[1*STRIDE+m] = py;
        Bt[2*STRIDE+m] = pz;
        Bt[63*STRIDE+m] = 0.f;     // zero pad row (K padded 63 -> 64)
        float pv[3] = {px, py, pz};
        #pragma unroll
        for (int i = 0; i < 3; i++) {
            float f = 1.f;
            #pragma unroll
            for (int q = 0; q < 10; q++) {
                float s, c;
                sincos_acc(pv[i]*f, &s, &c);
                Bt[(3  + i*10 + q)*STRIDE + m] = s;
                Bt[(33 + i*10 + q)*STRIDE + m] = c;
                f *= 2.f;
            }
        }
    } else if (tid < 128 + 27) {
        int j = tid - 128;
        float dv[3] = {dx, dy, dz};
        float v;
        if (j < 3) v = dv[j];
        else if (j < 15) { int jj = j-3;  float s,c; sincos_acc(dv[jj>>2]*(float)(1<<(jj&3)), &s, &c); v = s; }
        else             { int jj = j-15; float s,c; sincos_acc(dv[jj>>2]*(float)(1<<(jj&3)), &s, &c); v = c; }
        dirs[j] = v;
    }
    __syncthreads();

    // ---------------- Layer 1: H1t = relu(X @ W1 + b1), K=63(->64), N=256 ------
    for (int nc = 0; nc < 2; nc++) {
        const int n0 = nc * 128;
        float acc[8][8];
        #pragma unroll
        for (int i = 0; i < 8; i++)
            #pragma unroll
            for (int j = 0; j < 8; j++) acc[i][j] = 0.f;

        for (int k0 = 0; k0 < 64; k0 += 16) {
            { // stage W1[k0:k0+16, n0:n0+128] into Wbuf (zero row k=63)
                int e = tid * 8;
                int kk = e >> 7;
                int k = k0 + kk;
                int n = e & 127;
                if (k < 63) {
                    const float* src = W1 + k*256 + n0 + n;
                    ST4(&Wbuf[e])   = LD4(src);
                    ST4(&Wbuf[e+4]) = LD4(src+4);
                } else {
                    ST4(&Wbuf[e])   = make_float4(0.f,0.f,0.f,0.f);
                    ST4(&Wbuf[e+4]) = make_float4(0.f,0.f,0.f,0.f);
                }
            }
            __syncthreads();
            #pragma unroll
            for (int kk = 0; kk < 16; kk++) {
                const float* Ar = &Bt[(k0+kk)*STRIDE + m0];
                float4 A0 = LD4(Ar), A1 = LD4(Ar+4);
                const float* Br = &Wbuf[kk*128 + tx*8];
                float4 B0 = LD4(Br), B1 = LD4(Br+4);
                float av[8] = {A0.x,A0.y,A0.z,A0.w,A1.x,A1.y,A1.z,A1.w};
                float bv[8] = {B0.x,B0.y,B0.z,B0.w,B1.x,B1.y,B1.z,B1.w};
                #pragma unroll
                for (int i = 0; i < 8; i++)
                    #pragma unroll
                    for (int j = 0; j < 8; j++)
                        acc[i][j] = fmaf(av[i], bv[j], acc[i][j]);
            }
            __syncthreads();
        }
        // bias + relu + store transposed into H1t
        #pragma unroll
        for (int j = 0; j < 8; j++) {
            int n = n0 + tx*8 + j;
            float bb = b1[n];
            float v0 = fmaxf(acc[0][j]+bb, 0.f), v1 = fmaxf(acc[1][j]+bb, 0.f);
            float v2 = fmaxf(acc[2][j]+bb, 0.f), v3 = fmaxf(acc[3][j]+bb, 0.f);
            float v4 = fmaxf(acc[4][j]+bb, 0.f), v5 = fmaxf(acc[5][j]+bb, 0.f);
            float v6 = fmaxf(acc[6][j]+bb, 0.f), v7 = fmaxf(acc[7][j]+bb, 0.f);
            ST4(&H1t[n*STRIDE + m0])   = make_float4(v0,v1,v2,v3);
            ST4(&H1t[n*STRIDE + m0+4]) = make_float4(v4,v5,v6,v7);
        }
    }
    __syncthreads();

    // ---------------- Layer 2 + 3 fused: GEO = relu(H1 @ W2 + b2) @ W3 ---------
    float geo_acc[8];
    #pragma unroll
    for (int i = 0; i < 8; i++) geo_acc[i] = 0.f;

    for (int nc = 0; nc < 2; nc++) {
        const int n0 = nc * 128;
        float acc[8][8];
        #pragma unroll
        for (int i = 0; i < 8; i++)
            #pragma unroll
            for (int j = 0; j < 8; j++) acc[i][j] = 0.f;

        for (int k0 = 0; k0 < 256; k0 += 16) {
            { // stage W2[k0:k0+16, n0:n0+128]
                int e = tid * 8;
                int kk = e >> 7;
                int n = e & 127;
                const float* src = W2 + (k0+kk)*256 + n0 + n;
                ST4(&Wbuf[e])   = LD4(src);
                ST4(&Wbuf[e+4]) = LD4(src+4);
            }
            __syncthreads();
            #pragma unroll
            for (int kk = 0; kk < 16; kk++) {
                const float* Ar = &H1t[(k0+kk)*STRIDE + m0];
                float4 A0 = LD4(Ar), A1 = LD4(Ar+4);
                const float* Br = &Wbuf[kk*128 + tx*8];
                float4 B0 = LD4(Br), B1 = LD4(Br+4);
                float av[8] = {A0.x,A0.y,A0.z,A0.w,A1.x,A1.y,A1.z,A1.w};
                float bv[8] = {B0.x,B0.y,B0.z,B0.w,B1.x,B1.y,B1.z,B1.w};
                #pragma unroll
                for (int i = 0; i < 8; i++)
                    #pragma unroll
                    for (int j = 0; j < 8; j++)
                        acc[i][j] = fmaf(av[i], bv[j], acc[i][j]);
            }
            __syncthreads();
        }
        // bias + relu -> Bt (transposed: Bt[nl][m]), nl local 0..127
        #pragma unroll
        for (int j = 0; j < 8; j++) {
            int nl = tx*8 + j;
            float bb = b2[n0 + nl];
            float v0 = fmaxf(acc[0][j]+bb, 0.f), v1 = fmaxf(acc[1][j]+bb, 0.f);
            float v2 = fmaxf(acc[2][j]+bb, 0.f), v3 = fmaxf(acc[3][j]+bb, 0.f);
            float v4 = fmaxf(acc[4][j]+bb, 0.f), v5 = fmaxf(acc[5][j]+bb, 0.f);
            float v6 = fmaxf(acc[6][j]+bb, 0.f), v7 = fmaxf(acc[7][j]+bb, 0.f);
            ST4(&Bt[nl*STRIDE + m0])   = make_float4(v0,v1,v2,v3);
            ST4(&Bt[nl*STRIDE + m0+4]) = make_float4(v4,v5,v6,v7);
        }
        __syncthreads();
        { // stage W3 chunk [n0:n0+128][16] -> Wbuf (contiguous 2048 floats)
            int e = tid * 8;
            const float* src = W3 + n0*16 + e;
            ST4(&Wbuf[e])   = LD4(src);
            ST4(&Wbuf[e+4]) = LD4(src+4);
        }
        __syncthreads();
        // layer-3 partial: geo[m][c] += relu(H2)[m][k] * W3[k][c], c = tx
        #pragma unroll 4
        for (int k = 0; k < 128; k++) {
            const float* Ar = &Bt[k*STRIDE + m0];
            float4 A0 = LD4(Ar), A1 = LD4(Ar+4);
            float w = Wbuf[k*16 + tx];
            geo_acc[0] = fmaf(A0.x, w, geo_acc[0]);
            geo_acc[1] = fmaf(A0.y, w, geo_acc[1]);
            geo_acc[2] = fmaf(A0.z, w, geo_acc[2]);
            geo_acc[3] = fmaf(A0.w, w, geo_acc[3]);
            geo_acc[4] = fmaf(A1.x, w, geo_acc[4]);
            geo_acc[5] = fmaf(A1.y, w, geo_acc[5]);
            geo_acc[6] = fmaf(A1.z, w, geo_acc[6]);
            geo_acc[7] = fmaf(A1.w, w, geo_acc[7]);
        }
        __syncthreads();
    }
    { // store GEO (+ b3) to smem: geo[m][c], stride 17
        float bb = b3[tx];
        #pragma unroll
        for (int i = 0; i < 8; i++)
            geo[(m0+i)*17 + tx] = geo_acc[i] + bb;
    }
    __syncthreads();

    // ---------------- stage color weights into Bt (now free) --------------------
    float* Wc1s = Bt;            // 42*64 = 2688
    float* Wc2s = Bt + 2688;     // 64*3  = 192
    float* bc1s = Bt + 2880;     // 64
    float* bc2s = Bt + 2944;     // 3
    for (int e = tid; e < 2688; e += 256) Wc1s[e] = Wc1[e];
    for (int e = tid; e < 192;  e += 256) Wc2s[e] = Wc2[e];
    if (tid < 64) bc1s[tid] = bc1[tid];
    if (tid < 3)  bc2s[tid] = bc2[tid];
    __syncthreads();

    // ---------------- color head + alpha per sample -----------------------------
    if (tid < 128) {
        int m = tid;
        float inp[42];
        #pragma unroll
        for (int i = 0; i < 27; i++) inp[i] = dirs[i];
        #pragma unroll
        for (int i = 0; i < 15; i++) inp[27+i] = geo[m*17 + 1 + i];
        float sx = geo[m*17 + 0];
        float sigma = (sx > 20.f) ? sx : log1pf(expf(sx));

        float a0 = bc2s[0], a1 = bc2s[1], a2 = bc2s[2];
        for (int j = 0; j < 64; j++) {
            float h = bc1s[j];
            #pragma unroll
            for (int i = 0; i < 42; i++)
                h = fmaf(inp[i], Wc1s[i*64 + j], h);
            h = fmaxf(h, 0.f);
            a0 = fmaf(h, Wc2s[j*3+0], a0);
            a1 = fmaf(h, Wc2s[j*3+1], a1);
            a2 = fmaf(h, Wc2s[j*3+2], a2);
        }
        float alpha = 1.f - expf(-sigma * dtv);
        comp[m*4+0] = alpha;
        comp[m*4+1] = 1.f/(1.f + expf(-a0));
        comp[m*4+2] = 1.f/(1.f + expf(-a1));
        comp[m*4+3] = 1.f/(1.f + expf(-a2));
    }
    __syncthreads();

    // ---------------- composite (sequential scan, 1 thread) ---------------------
    if (tid == 0) {
        float T = 1.f, wsum = 0.f, dsum = 0.f;
        float r = 0.f, g = 0.f, b = 0.f;
        for (int m = 0; m < 128; m++) {
            float alpha = comp[m*4+0];
            float w = (T > 1e-4f) ? alpha * T : 0.f;
            wsum += w;
            float tsv = near_t + ((float)m + 0.5f) * dtv;
            dsum += w * tsv;
            r += w * comp[m*4+1];
            g += w * comp[m*4+2];
            b += w * comp[m*4+3];
            T *= (1.f - alpha + 1e-10f);
        }
        float bgw = 1.f - wsum;
        out[ray*3+0] = r + bgw;
        out[ray*3+1] = g + bgw;
        out[ray*3+2] = b + bgw;
        out[4096*3 + ray] = dsum;
        out[4096*4 + ray] = fminf(fmaxf(wsum, 1e-12f), 1000.f);
    }
}

extern "C" void kernel_launch(void* const* d_in, const int* in_sizes, int n_in,
                              void* d_out, int out_size) {
    const float* rays_o = (const float*)d_in[0];
    const float* rays_d = (const float*)d_in[1];
    const float* W1  = (const float*)d_in[2];
    const float* b1  = (const float*)d_in[3];
    const float* W2  = (const float*)d_in[4];
    const float* b2  = (const float*)d_in[5];
    const float* W3  = (const float*)d_in[6];
    const float* b3  = (const float*)d_in[7];
    const float* Wc1 = (const float*)d_in[8];
    const float* bc1 = (const float*)d_in[9];
    const float* Wc2 = (const float*)d_in[10];
    const float* bc2 = (const float*)d_in[11];
    float* out = (float*)d_out;

    cudaFuncSetAttribute(nerf_fused, cudaFuncAttributeMaxDynamicSharedMemorySize, SMEM_BYTES);
    nerf_fused<<<4096, 256, SMEM_BYTES>>>(rays_o, rays_d, W1, b1, W2, b2,
                                          W3, b3, Wc1, bc1, Wc2, bc2, out);
}

// round 3
// speedup vs baseline: 2.2265x; 2.2265x over previous
#include <cuda_runtime.h>
#include <cuda_bf16.h>
#include <math.h>
#include <stdint.h>

// ===================== asm helpers (all plain sm_100-safe) =====================
__device__ __forceinline__ uint32_t smem_u32(const void* p) {
    uint32_t a;
    asm("{ .reg .u64 t; cvta.to.shared.u64 t, %1; cvt.u32.u64 %0, t; }" : "=r"(a) : "l"(p));
    return a;
}
#define CP16(dst_u32, src_ptr) \
    asm volatile("cp.async.cg.shared.global [%0], [%1], 16;" :: "r"(dst_u32), "l"(src_ptr) : "memory")
#define CP_COMMIT() asm volatile("cp.async.commit_group;" ::: "memory")
#define CP_WAIT(n)  asm volatile("cp.async.wait_group %0;" :: "n"(n) : "memory")

#define MMA(d, a0, a1, a2, a3, b0, b1) \
    asm("mma.sync.aligned.m16n8k16.row.col.f32.bf16.bf16.f32 " \
        "{%0,%1,%2,%3}, {%4,%5,%6,%7}, {%8,%9}, {%0,%1,%2,%3};" \
        : "+f"((d)[0]), "+f"((d)[1]), "+f"((d)[2]), "+f"((d)[3]) \
        : "r"(a0), "r"(a1), "r"(a2), "r"(a3), "r"(b0), "r"(b1))

// ===================== problem constants =====================
// smem byte offsets
#define SM_WA    0          // 65536  weight buffer A
#define SM_WB    65536      // 65536  weight buffer B
#define SM_W3    131072     // 16384  W3 packed (hi 8K | lo 8K)
#define SM_X     147456     // 34816  X posenc fp32 [128][68]
#define SM_WC1   182272     // 10752
#define SM_WC2   193024     // 768
#define SM_BC1   193792     // 256
#define SM_BC2   194048     // 16
#define SM_B1    194064     // 1024
#define SM_B2    195088     // 1024
#define SM_B3    196112     // 64
#define SM_DIR   196176     // 128
#define SM_GEO   196304     // 8192  [128][16] fp32
#define SM_COMP  204496     // 2048
#define SM_CPART 206544     // 2048
#define SMEM_BYTES 208592

// packed weight image: chunks 0..4 are 64KB each (hi 32K | lo 32K), P3 is 16KB
__device__ __align__(128) uint32_t g_pack[86016];   // 336KB

__device__ __forceinline__ void bf16_split2(float x, float y, uint32_t& h, uint32_t& l) {
    __nv_bfloat16 hx = __float2bfloat16(x), hy = __float2bfloat16(y);
    h = (uint32_t)__bfloat16_as_ushort(hx) | ((uint32_t)__bfloat16_as_ushort(hy) << 16);
    __nv_bfloat16 lx = __float2bfloat16(x - __bfloat162float(hx));
    __nv_bfloat16 ly = __float2bfloat16(y - __bfloat162float(hy));
    l = (uint32_t)__bfloat16_as_ushort(lx) | ((uint32_t)__bfloat16_as_ushort(ly) << 16);
}

__device__ __forceinline__ void sincos_acc(float phi, float* s, float* c) {
    double p = (double)phi;
    double k = rint(p * 0.15915494309189535);
    float r = (float)fma(-k, 6.283185307179586476925287, p);
    sincosf(r, s, c);
}

// ===================== prep kernel: pack weights into fragment order =====================
// Fragment pack per (tile, lane): pair0 = {W[kb+2q, n], W[kb+2q+1, n]}, pair1 = {+8, +9}
// where q = lane&3, n = ntile*8 + lane>>2.
__global__ void prep_pack(const float* __restrict__ W1, const float* __restrict__ W2,
                          const float* __restrict__ W3) {
    int s = blockIdx.x * 256 + threadIdx.x;
    if (s >= 21504) return;
    int lane = s & 31;
    int qn = lane >> 2, qk = (lane & 3) * 2;
    const float* W; int kbase, n, ldn, kmax; uint32_t base, idx, hsz;
    if (s < 4096) {                       // P1: 4 kt x 32 nt
        int t = s >> 5;
        int nt = t & 31, kt = t >> 5;
        kbase = kt * 16; n = nt * 8 + qn; W = W1; ldn = 256; kmax = 63;
        base = 0; idx = (uint32_t)((kt * 32 + nt) * 32 + lane); hsz = 8192;
    } else if (s < 20480) {               // P2: 4 chunks x (8 ktl x 16 ntl)
        int t = (s - 4096) >> 5;
        int ntl = t & 15, ktl = (t >> 4) & 7, cr = t >> 7;   // cr = h*2 + p
        int h = cr >> 1, p = cr & 1;
        kbase = (p * 8 + ktl) * 16; n = (h * 16 + ntl) * 8 + qn; W = W2; ldn = 256; kmax = 256;
        base = 16384u * (1 + cr); idx = (uint32_t)((ktl * 16 + ntl) * 32 + lane); hsz = 8192;
    } else {                              // P3: 16 kt x 2 nt
        int t = (s - 20480) >> 5;
        int nt = t & 1, kt = t >> 1;
        kbase = kt * 16; n = nt * 8 + qn; W = W3; ldn = 16; kmax = 256;
        base = 81920; idx = (uint32_t)((kt * 2 + nt) * 32 + lane); hsz = 2048;
    }
    int ks[4] = {kbase + qk, kbase + qk + 1, kbase + qk + 8, kbase + qk + 9};
    float e[4];
    #pragma unroll
    for (int j = 0; j < 4; j++) e[j] = (ks[j] < kmax) ? W[ks[j] * ldn + n] : 0.f;
    uint32_t h0, l0, h1, l1;
    bf16_split2(e[0], e[1], h0, l0);
    bf16_split2(e[2], e[3], h1, l1);
    g_pack[base + idx * 2]           = h0;
    g_pack[base + idx * 2 + 1]       = h1;
    g_pack[base + hsz + idx * 2]     = l0;
    g_pack[base + hsz + idx * 2 + 1] = l1;
}

// ===================== copies =====================
__device__ __forceinline__ void copy64k(uint32_t dst, const void* src, int tid) {
    #pragma unroll
    for (int j = 0; j < 16; j++)
        CP16(dst + (uint32_t)(tid + j * 256) * 16, (const char*)src + (tid + j * 256) * 16);
    CP_COMMIT();
}
__device__ __forceinline__ void copy16k(uint32_t dst, const void* src, int tid) {
    #pragma unroll
    for (int j = 0; j < 4; j++)
        CP16(dst + (uint32_t)(tid + j * 256) * 16, (const char*)src + (tid + j * 256) * 16);
    CP_COMMIT();
}

// ===================== layer 2 half (+ chained layer 3 partial) =====================
__device__ __forceinline__ void layer2_half(
    const uint2* Bp0, const uint2* Bp1, int h2, int lane,
    const uint32_t* h1h, const uint32_t* h1l,
    const float* b2s, const uint2* W3b, float geo[2][4], int qk)
{
    float acc[16][4];
    #pragma unroll
    for (int i = 0; i < 16; i++)
        #pragma unroll
        for (int j = 0; j < 4; j++) acc[i][j] = 0.f;

    #pragma unroll
    for (int p = 0; p < 2; p++) {
        const uint2* B = p ? Bp1 : Bp0;
        if (p == 1) { CP_WAIT(0); __syncthreads(); }
        #pragma unroll
        for (int ktl = 0; ktl < 8; ktl++) {
            int kt = p * 8 + ktl;
            uint32_t a0 = h1h[4*kt], a1 = h1h[4*kt+1], a2 = h1h[4*kt+2], a3 = h1h[4*kt+3];
            uint32_t c0 = h1l[4*kt], c1 = h1l[4*kt+1], c2 = h1l[4*kt+2], c3 = h1l[4*kt+3];
            #pragma unroll
            for (int i = 0; i < 16; i++) {
                const uint2* pb = B + (ktl * 16 + i) * 32 + lane;
                uint2 bh = *pb;
                MMA(acc[i], a0, a1, a2, a3, bh.x, bh.y);
                MMA(acc[i], c0, c1, c2, c3, bh.x, bh.y);
                uint2 bl = *(pb + 4096);
                MMA(acc[i], a0, a1, a2, a3, bl.x, bl.y);
            }
        }
    }
    // bias + relu + split -> A fragments for layer 3
    uint32_t s2h[32], s2l[32];
    #pragma unroll
    for (int i = 0; i < 16; i++) {
        int n0 = h2 * 128 + i * 8 + qk;
        float2 bb = *(const float2*)(b2s + n0);
        float v0 = fmaxf(acc[i][0] + bb.x, 0.f);
        float v1 = fmaxf(acc[i][1] + bb.y, 0.f);
        float v2 = fmaxf(acc[i][2] + bb.x, 0.f);
        float v3 = fmaxf(acc[i][3] + bb.y, 0.f);
        bf16_split2(v0, v1, s2h[i*2],   s2l[i*2]);
        bf16_split2(v2, v3, s2h[i*2+1], s2l[i*2+1]);
    }
    // layer 3 partial: k-tiles h2*8 .. h2*8+7
    #pragma unroll
    for (int ktl = 0; ktl < 8; ktl++) {
        int kt3 = h2 * 8 + ktl;
        uint32_t a0 = s2h[4*ktl], a1 = s2h[4*ktl+1], a2 = s2h[4*ktl+2], a3 = s2h[4*ktl+3];
        uint32_t c0 = s2l[4*ktl], c1 = s2l[4*ktl+1], c2 = s2l[4*ktl+2], c3 = s2l[4*ktl+3];
        #pragma unroll
        for (int nt = 0; nt < 2; nt++) {
            const uint2* pb = W3b + (kt3 * 2 + nt) * 32 + lane;
            uint2 bh = *pb;
            MMA(geo[nt], a0, a1, a2, a3, bh.x, bh.y);
            MMA(geo[nt], c0, c1, c2, c3, bh.x, bh.y);
            uint2 bl = *(pb + 1024);
            MMA(geo[nt], a0, a1, a2, a3, bl.x, bl.y);
        }
    }
}

// ===================== main kernel =====================
__global__ void __launch_bounds__(256, 1)
nerf_mma(const float* __restrict__ rays_o, const float* __restrict__ rays_d,
         const float* __restrict__ b1, const float* __restrict__ b2,
         const float* __restrict__ b3,
         const float* __restrict__ Wc1, const float* __restrict__ bc1,
         const float* __restrict__ Wc2, const float* __restrict__ bc2,
         float* __restrict__ out)
{
    extern __shared__ char smem[];
    const int tid = threadIdx.x;
    const int lane = tid & 31;
    const int w = tid >> 5;
    const int ray = blockIdx.x;
    const int qn = lane >> 2;          (void)qn;
    const int qk = (lane & 3) * 2;
    const int r0 = w * 16 + (lane >> 2);

    float* Xs   = (float*)(smem + SM_X);
    float* wc1s = (float*)(smem + SM_WC1);
    float* wc2s = (float*)(smem + SM_WC2);
    float* bc1s = (float*)(smem + SM_BC1);
    float* bc2s = (float*)(smem + SM_BC2);
    float* b1s  = (float*)(smem + SM_B1);
    float* b2s  = (float*)(smem + SM_B2);
    float* b3s  = (float*)(smem + SM_B3);
    float* dirs = (float*)(smem + SM_DIR);
    float* geos = (float*)(smem + SM_GEO);
    float* comp = (float*)(smem + SM_COMP);
    float* cpart= (float*)(smem + SM_CPART);
    const uint2* WA  = (const uint2*)(smem + SM_WA);
    const uint2* WB  = (const uint2*)(smem + SM_WB);
    const uint2* W3b = (const uint2*)(smem + SM_W3);

    const uint32_t sWA = smem_u32(smem + SM_WA);
    const uint32_t sWB = smem_u32(smem + SM_WB);
    const uint32_t sW3 = smem_u32(smem + SM_W3);
    const char* gp = (const char*)g_pack;

    // kick off async weight staging: c0->A (g1), c1->B (g2), P3 (g3)
    copy64k(sWA, gp,            tid);
    copy64k(sWB, gp + 65536,    tid);
    copy16k(sW3, gp + 327680,   tid);

    // small constants
    if (tid < 256) { b1s[tid] = b1[tid]; b2s[tid] = b2[tid]; }
    if (tid < 16) b3s[tid] = b3[tid];
    for (int e = tid; e < 2688; e += 256) wc1s[e] = Wc1[e];
    for (int e = tid; e < 192; e += 256) wc2s[e] = Wc2[e];
    if (tid < 64) bc1s[tid] = bc1[tid];
    if (tid < 3) bc2s[tid] = bc2[tid];

    // ---------------- ray setup ----------------
    float ox = rays_o[ray*3+0], oy = rays_o[ray*3+1], oz = rays_o[ray*3+2];
    float rdx = rays_d[ray*3+0], rdy = rays_d[ray*3+1], rdz = rays_d[ray*3+2];
    float inv_norm = 1.0f / sqrtf(rdx*rdx + rdy*rdy + rdz*rdz);
    float dx = rdx*inv_norm, dy = rdy*inv_norm, dz = rdz*inv_norm;
    float near_t, far_t;
    {
        float dd;
        dd = (fabsf(dx) < 1e-8f) ? 1e-8f : dx; float i0 = 1.0f/dd;
        dd = (fabsf(dy) < 1e-8f) ? 1e-8f : dy; float i1 = 1.0f/dd;
        dd = (fabsf(dz) < 1e-8f) ? 1e-8f : dz; float i2 = 1.0f/dd;
        float t0x=(-1.f-ox)*i0, t1x=(1.f-ox)*i0;
        float t0y=(-1.f-oy)*i1, t1y=(1.f-oy)*i1;
        float t0z=(-1.f-oz)*i2, t1z=(1.f-oz)*i2;
        float nx=fminf(t0x,t1x), fx=fmaxf(t0x,t1x);
        float ny=fminf(t0y,t1y), fy=fmaxf(t0y,t1y);
        float nz=fminf(t0z,t1z), fz=fmaxf(t0z,t1z);
        near_t = fmaxf(fmaxf(nx, fmaxf(ny, nz)), 0.02f);
        far_t  = fminf(fmaxf(fx, fmaxf(fy, fz)), 1000.f);
        far_t  = fmaxf(far_t, near_t + 0.001f);
    }
    const float dtv = (far_t - near_t) * (1.0f/128.0f);

    // ---------------- posenc -> Xs (fp32, stride 68), dirs ----------------
    if (tid < 128) {
        float* xr = Xs + tid * 68;
        float t = near_t + ((float)tid + 0.5f) * dtv;
        float px = ox + t*dx, py = oy + t*dy, pz = oz + t*dz;
        xr[0] = px; xr[1] = py; xr[2] = pz; xr[63] = 0.f;
        float pv[3] = {px, py, pz};
        #pragma unroll
        for (int i = 0; i < 3; i++) {
            float f = 1.f;
            #pragma unroll
            for (int q = 0; q < 10; q++) {
                float s, c;
                sincos_acc(pv[i]*f, &s, &c);
                xr[3  + i*10 + q] = s;
                xr[33 + i*10 + q] = c;
                f *= 2.f;
            }
        }
    } else if (tid < 128 + 27) {
        int j = tid - 128;
        float dv[3] = {dx, dy, dz};
        float v;
        if (j < 3) v = dv[j];
        else if (j < 15) { int jj = j-3;  float s,c; sincos_acc(dv[jj>>2]*(float)(1<<(jj&3)), &s, &c); v = s; }
        else             { int jj = j-15; float s,c; sincos_acc(dv[jj>>2]*(float)(1<<(jj&3)), &s, &c); v = c; }
        dirs[j] = v;
    }

    // wait for P1 (g1): outstanding <= 2 (g2, g3)
    CP_WAIT(2);
    __syncthreads();

    // ---------------- Layer 1: H1 = relu(X @ W1 + b1), chained to regs ----------------
    uint32_t h1h[64], h1l[64];
    #pragma unroll
    for (int h = 0; h < 2; h++) {
        float acc[16][4];
        #pragma unroll
        for (int i = 0; i < 16; i++)
            #pragma unroll
            for (int j = 0; j < 4; j++) acc[i][j] = 0.f;

        #pragma unroll
        for (int kt = 0; kt < 4; kt++) {
            float2 x0 = *(const float2*)(Xs + r0*68       + kt*16 + qk);
            float2 x1 = *(const float2*)(Xs + (r0+8)*68   + kt*16 + qk);
            float2 x2 = *(const float2*)(Xs + r0*68       + kt*16 + qk + 8);
            float2 x3 = *(const float2*)(Xs + (r0+8)*68   + kt*16 + qk + 8);
            uint32_t ah0, al0, ah1, al1, ah2, al2, ah3, al3;
            bf16_split2(x0.x, x0.y, ah0, al0);
            bf16_split2(x1.x, x1.y, ah1, al1);
            bf16_split2(x2.x, x2.y, ah2, al2);
            bf16_split2(x3.x, x3.y, ah3, al3);
            #pragma unroll
            for (int i = 0; i < 16; i++) {
                const uint2* pb = WA + (kt*32 + h*16 + i)*32 + lane;
                uint2 bh = *pb;
                MMA(acc[i], ah0, ah1, ah2, ah3, bh.x, bh.y);
                MMA(acc[i], al0, al1, al2, al3, bh.x, bh.y);
                uint2 bl = *(pb + 4096);
                MMA(acc[i], ah0, ah1, ah2, ah3, bl.x, bl.y);
            }
        }
        #pragma unroll
        for (int i = 0; i < 16; i++) {
            int n0 = h*128 + i*8 + qk;
            float2 bb = *(const float2*)(b1s + n0);
            float v0 = fmaxf(acc[i][0] + bb.x, 0.f);
            float v1 = fmaxf(acc[i][1] + bb.y, 0.f);
            float v2 = fmaxf(acc[i][2] + bb.x, 0.f);
            float v3 = fmaxf(acc[i][3] + bb.y, 0.f);
            int idx = (h*16 + i) * 2;
            bf16_split2(v0, v1, h1h[idx],   h1l[idx]);
            bf16_split2(v2, v3, h1h[idx+1], h1l[idx+1]);
        }
    }
    __syncthreads();

    // stage c2 -> A (g4)
    copy64k(sWA, gp + 2*65536, tid);
    // wait g2 (B = P2 h0 p0) and g3 (W3): outstanding <= 1 (g4)
    CP_WAIT(1);
    __syncthreads();

    float geo[2][4];
    #pragma unroll
    for (int nt = 0; nt < 2; nt++)
        #pragma unroll
        for (int j = 0; j < 4; j++) geo[nt][j] = 0.f;

    // ---------------- Layer 2+3 half 0 ----------------
    layer2_half(WB, WA, 0, lane, h1h, h1l, b2s, W3b, geo, qk);
    __syncthreads();

    // stage c3 -> B (g5), c4 -> A (g6)
    copy64k(sWB, gp + 3*65536, tid);
    copy64k(sWA, gp + 4*65536, tid);
    CP_WAIT(1);           // g5 done
    __syncthreads();

    // ---------------- Layer 2+3 half 1 ----------------
    layer2_half(WB, WA, 1, lane, h1h, h1l, b2s, W3b, geo, qk);

    // ---------------- geo -> smem ----------------
    #pragma unroll
    for (int nt = 0; nt < 2; nt++) {
        int c = nt*8 + qk;
        *(float2*)(geos + r0*16 + c)     = make_float2(geo[nt][0], geo[nt][1]);
        *(float2*)(geos + (r0+8)*16 + c) = make_float2(geo[nt][2], geo[nt][3]);
    }
    __syncthreads();

    // ---------------- color head ----------------
    {
        int m = tid & 127;
        float inp[42];
        #pragma unroll
        for (int i = 0; i < 27; i++) inp[i] = dirs[i];
        #pragma unroll
        for (int i = 0; i < 15; i++) inp[27 + i] = geos[m*16 + 1 + i] + b3s[1 + i];
        int j0 = (tid < 128) ? 0 : 32;
        float a0 = 0.f, a1 = 0.f, a2 = 0.f;
        for (int j = j0; j < j0 + 32; j++) {
            float hcc = bc1s[j];
            #pragma unroll
            for (int i = 0; i < 42; i++)
                hcc = fmaf(inp[i], wc1s[i*64 + j], hcc);
            hcc = fmaxf(hcc, 0.f);
            a0 = fmaf(hcc, wc2s[j*3+0], a0);
            a1 = fmaf(hcc, wc2s[j*3+1], a1);
            a2 = fmaf(hcc, wc2s[j*3+2], a2);
        }
        if (tid >= 128) {
            cpart[m*4+0] = a0; cpart[m*4+1] = a1; cpart[m*4+2] = a2;
        }
        __syncthreads();
        if (tid < 128) {
            a0 += cpart[m*4+0] + bc2s[0];
            a1 += cpart[m*4+1] + bc2s[1];
            a2 += cpart[m*4+2] + bc2s[2];
            float sx = geos[m*16] + b3s[0];
            float sigma = (sx > 20.f) ? sx : log1pf(expf(sx));
            float alpha = 1.f - expf(-sigma * dtv);
            comp[m*4+0] = alpha;
            comp[m*4+1] = 1.f / (1.f + expf(-a0));
            comp[m*4+2] = 1.f / (1.f + expf(-a1));
            comp[m*4+3] = 1.f / (1.f + expf(-a2));
        }
    }
    __syncthreads();

    // ---------------- composite ----------------
    if (tid == 0) {
        float T = 1.f, wsum = 0.f, dsum = 0.f;
        float r = 0.f, g = 0.f, b = 0.f;
        for (int m = 0; m < 128; m++) {
            float alpha = comp[m*4+0];
            float wgt = (T > 1e-4f) ? alpha * T : 0.f;
            wsum += wgt;
            float tsv = near_t + ((float)m + 0.5f) * dtv;
            dsum += wgt * tsv;
            r += wgt * comp[m*4+1];
            g += wgt * comp[m*4+2];
            b += wgt * comp[m*4+3];
            T *= (1.f - alpha + 1e-10f);
        }
        float bgw = 1.f - wsum;
        out[ray*3+0] = r + bgw;
        out[ray*3+1] = g + bgw;
        out[ray*3+2] = b + bgw;
        out[4096*3 + ray] = dsum;
        out[4096*4 + ray] = fminf(fmaxf(wsum, 1e-12f), 1000.f);
    }
}

// ===================== launch =====================
extern "C" void kernel_launch(void* const* d_in, const int* in_sizes, int n_in,
                              void* d_out, int out_size) {
    const float* rays_o = (const float*)d_in[0];
    const float* rays_d = (const float*)d_in[1];
    const float* W1  = (const float*)d_in[2];
    const float* b1  = (const float*)d_in[3];
    const float* W2  = (const float*)d_in[4];
    const float* b2  = (const float*)d_in[5];
    const float* W3  = (const float*)d_in[6];
    const float* b3  = (const float*)d_in[7];
    const float* Wc1 = (const float*)d_in[8];
    const float* bc1 = (const float*)d_in[9];
    const float* Wc2 = (const float*)d_in[10];
    const float* bc2 = (const float*)d_in[11];
    float* out = (float*)d_out;

    prep_pack<<<84, 256>>>(W1, W2, W3);
    cudaFuncSetAttribute(nerf_mma, cudaFuncAttributeMaxDynamicSharedMemorySize, SMEM_BYTES);
    nerf_mma<<<4096, 256, SMEM_BYTES>>>(rays_o, rays_d, b1, b2, b3,
                                        Wc1, bc1, Wc2, bc2, out);
}

// round 4
// speedup vs baseline: 2.2478x; 1.0096x over previous
#include <cuda_runtime.h>
#include <cuda_bf16.h>
#include <math.h>
#include <stdint.h>

// ===================== asm helpers (plain sm_100-safe) =====================
__device__ __forceinline__ uint32_t smem_u32(const void* p) {
    uint32_t a;
    asm("{ .reg .u64 t; cvta.to.shared.u64 t, %1; cvt.u32.u64 %0, t; }" : "=r"(a) : "l"(p));
    return a;
}
#define CP16(dst_u32, src_ptr) \
    asm volatile("cp.async.cg.shared.global [%0], [%1], 16;" :: "r"(dst_u32), "l"(src_ptr) : "memory")
#define CP_COMMIT() asm volatile("cp.async.commit_group;" ::: "memory")
#define CP_WAIT(n)  asm volatile("cp.async.wait_group %0;" :: "n"(n) : "memory")

#define MMA(d, a0, a1, a2, a3, b0, b1) \
    asm("mma.sync.aligned.m16n8k16.row.col.f32.bf16.bf16.f32 " \
        "{%0,%1,%2,%3}, {%4,%5,%6,%7}, {%8,%9}, {%0,%1,%2,%3};" \
        : "+f"((d)[0]), "+f"((d)[1]), "+f"((d)[2]), "+f"((d)[3]) \
        : "r"(a0), "r"(a1), "r"(a2), "r"(a3), "r"(b0), "r"(b1))

// ===================== smem byte offsets =====================
#define SM_WA    0          // 65536  weight buffer A
#define SM_WB    65536      // 65536  weight buffer B
#define SM_W3    131072     // 16384  W3 packed (hi 8K | lo 8K)
#define SM_XH    147456     // 16640  X posenc hi packed [32 pairs][130]
#define SM_XL    164096     // 16640  lo
#define SM_WC1   180736     // 10752
#define SM_WC2   191488     // 768
#define SM_BC1   192256     // 256
#define SM_BC2   192512     // 16
#define SM_B1    192528     // 1024
#define SM_B2    193552     // 1024
#define SM_B3    194576     // 64
#define SM_DIR   194640     // 128
#define SM_GEO   194768     // 8192  [128][16] fp32
#define SM_COMP  202960     // 2048
#define SM_CPART 205008     // 2048
#define SMEM_BYTES 207056

// packed weight image: chunks 0..4 are 64KB each (hi 32K | lo 32K), P3 is 16KB
__device__ __align__(128) uint32_t g_pack[86016];   // 336KB

__device__ __forceinline__ void bf16_split2(float x, float y, uint32_t& h, uint32_t& l) {
    __nv_bfloat16 hx = __float2bfloat16(x), hy = __float2bfloat16(y);
    h = (uint32_t)__bfloat16_as_ushort(hx) | ((uint32_t)__bfloat16_as_ushort(hy) << 16);
    __nv_bfloat16 lx = __float2bfloat16(x - __bfloat162float(hx));
    __nv_bfloat16 ly = __float2bfloat16(y - __bfloat162float(hy));
    l = (uint32_t)__bfloat16_as_ushort(lx) | ((uint32_t)__bfloat16_as_ushort(ly) << 16);
}

// fp32 Cody-Waite 2-term range reduction mod 2*pi, then sincosf on small arg.
__device__ __forceinline__ void sincos_acc(float phi, float* s, float* c) {
    float k = rintf(phi * 0.15915494309f);
    float r = fmaf(-k, 6.2831854820251465f, phi);      // 2pi hi (fp32)
    r = fmaf(-k, -1.7484556000744263e-07f, r);         // 2pi lo
    sincosf(r, s, c);
}

// ===================== prep kernel: pack weights into fragment order =====================
__global__ void prep_pack(const float* __restrict__ W1, const float* __restrict__ W2,
                          const float* __restrict__ W3) {
    int s = blockIdx.x * 256 + threadIdx.x;
    if (s >= 21504) return;
    int lane = s & 31;
    int qn = lane >> 2, qk = (lane & 3) * 2;
    const float* W; int kbase, n, ldn, kmax; uint32_t base, idx, hsz;
    if (s < 4096) {                       // P1: 4 kt x 32 nt
        int t = s >> 5;
        int nt = t & 31, kt = t >> 5;
        kbase = kt * 16; n = nt * 8 + qn; W = W1; ldn = 256; kmax = 63;
        base = 0; idx = (uint32_t)((kt * 32 + nt) * 32 + lane); hsz = 8192;
    } else if (s < 20480) {               // P2: 4 chunks x (8 ktl x 16 ntl)
        int t = (s - 4096) >> 5;
        int ntl = t & 15, ktl = (t >> 4) & 7, cr = t >> 7;   // cr = h*2 + p
        int h = cr >> 1, p = cr & 1;
        kbase = (p * 8 + ktl) * 16; n = (h * 16 + ntl) * 8 + qn; W = W2; ldn = 256; kmax = 256;
        base = 16384u * (1 + cr); idx = (uint32_t)((ktl * 16 + ntl) * 32 + lane); hsz = 8192;
    } else {                              // P3: 16 kt x 2 nt
        int t = (s - 20480) >> 5;
        int nt = t & 1, kt = t >> 1;
        kbase = kt * 16; n = nt * 8 + qn; W = W3; ldn = 16; kmax = 256;
        base = 81920; idx = (uint32_t)((kt * 2 + nt) * 32 + lane); hsz = 2048;
    }
    int ks[4] = {kbase + qk, kbase + qk + 1, kbase + qk + 8, kbase + qk + 9};
    float e[4];
    #pragma unroll
    for (int j = 0; j < 4; j++) e[j] = (ks[j] < kmax) ? W[ks[j] * ldn + n] : 0.f;
    uint32_t h0, l0, h1, l1;
    bf16_split2(e[0], e[1], h0, l0);
    bf16_split2(e[2], e[3], h1, l1);
    g_pack[base + idx * 2]           = h0;
    g_pack[base + idx * 2 + 1]       = h1;
    g_pack[base + hsz + idx * 2]     = l0;
    g_pack[base + hsz + idx * 2 + 1] = l1;
}

// ===================== copies =====================
__device__ __forceinline__ void copy64k(uint32_t dst, const void* src, int tid) {
    #pragma unroll
    for (int j = 0; j < 16; j++)
        CP16(dst + (uint32_t)(tid + j * 256) * 16, (const char*)src + (tid + j * 256) * 16);
    CP_COMMIT();
}
__device__ __forceinline__ void copy16k(uint32_t dst, const void* src, int tid) {
    #pragma unroll
    for (int j = 0; j < 4; j++)
        CP16(dst + (uint32_t)(tid + j * 256) * 16, (const char*)src + (tid + j * 256) * 16);
    CP_COMMIT();
}

// ===================== layer 2 half (+ fused layer 3) =====================
__device__ __forceinline__ void layer2_half(
    const uint2* Bp0, const uint2* Bp1, int h2, int lane,
    const uint32_t* h1h, const uint32_t* h1l,
    const float* b2s, const uint2* W3b, float geo[2][4], int qk)
{
    float acc[16][4];
    #pragma unroll
    for (int i = 0; i < 16; i++)
        #pragma unroll
        for (int j = 0; j < 4; j++) acc[i][j] = 0.f;

    #pragma unroll
    for (int p = 0; p < 2; p++) {
        const uint2* B = p ? Bp1 : Bp0;
        if (p == 1) { CP_WAIT(0); __syncthreads(); }
        #pragma unroll
        for (int ktl = 0; ktl < 8; ktl++) {
            int kt = p * 8 + ktl;
            uint32_t a0 = h1h[4*kt], a1 = h1h[4*kt+1], a2 = h1h[4*kt+2], a3 = h1h[4*kt+3];
            uint32_t c0 = h1l[4*kt], c1 = h1l[4*kt+1], c2 = h1l[4*kt+2], c3 = h1l[4*kt+3];
            #pragma unroll
            for (int i = 0; i < 16; i++) {
                const uint2* pb = B + (ktl * 16 + i) * 32 + lane;
                uint2 bh = *pb;
                MMA(acc[i], a0, a1, a2, a3, bh.x, bh.y);
                MMA(acc[i], c0, c1, c2, c3, bh.x, bh.y);
                uint2 bl = *(pb + 4096);
                MMA(acc[i], a0, a1, a2, a3, bl.x, bl.y);
            }
        }
    }
    // fused epilogue + layer-3: process acc tiles in pairs, keep only 8 s2 words live
    #pragma unroll
    for (int ii = 0; ii < 8; ii++) {
        int i0 = 2 * ii, i1 = i0 + 1;
        uint32_t s0h, s0l, s1h, s1l, s2h, s2l, s3h, s3l;
        {
            int n0 = h2 * 128 + i0 * 8 + qk;
            float2 bb = *(const float2*)(b2s + n0);
            float v0 = fmaxf(acc[i0][0] + bb.x, 0.f);
            float v1 = fmaxf(acc[i0][1] + bb.y, 0.f);
            float v2 = fmaxf(acc[i0][2] + bb.x, 0.f);
            float v3 = fmaxf(acc[i0][3] + bb.y, 0.f);
            bf16_split2(v0, v1, s0h, s0l);
            bf16_split2(v2, v3, s1h, s1l);
        }
        {
            int n1 = h2 * 128 + i1 * 8 + qk;
            float2 bb = *(const float2*)(b2s + n1);
            float v0 = fmaxf(acc[i1][0] + bb.x, 0.f);
            float v1 = fmaxf(acc[i1][1] + bb.y, 0.f);
            float v2 = fmaxf(acc[i1][2] + bb.x, 0.f);
            float v3 = fmaxf(acc[i1][3] + bb.y, 0.f);
            bf16_split2(v0, v1, s2h, s2l);
            bf16_split2(v2, v3, s3h, s3l);
        }
        int kt3 = h2 * 8 + ii;
        #pragma unroll
        for (int nt = 0; nt < 2; nt++) {
            const uint2* pb = W3b + (kt3 * 2 + nt) * 32 + lane;
            uint2 bh = *pb;
            MMA(geo[nt], s0h, s1h, s2h, s3h, bh.x, bh.y);
            MMA(geo[nt], s0l, s1l, s2l, s3l, bh.x, bh.y);
            uint2 bl = *(pb + 1024);
            MMA(geo[nt], s0h, s1h, s2h, s3h, bl.x, bl.y);
        }
    }
}

// ===================== main kernel =====================
__global__ void __launch_bounds__(256, 1)
nerf_mma(const float* __restrict__ rays_o, const float* __restrict__ rays_d,
         const float* __restrict__ b1, const float* __restrict__ b2,
         const float* __restrict__ b3,
         const float* __restrict__ Wc1, const float* __restrict__ bc1,
         const float* __restrict__ Wc2, const float* __restrict__ bc2,
         float* __restrict__ out)
{
    extern __shared__ char smem[];
    const int tid = threadIdx.x;
    const int lane = tid & 31;
    const int w = tid >> 5;
    const int ray = blockIdx.x;
    const int qk = (lane & 3) * 2;
    const int r0 = w * 16 + (lane >> 2);

    float* wc1s = (float*)(smem + SM_WC1);
    float* wc2s = (float*)(smem + SM_WC2);
    float* bc1s = (float*)(smem + SM_BC1);
    float* bc2s = (float*)(smem + SM_BC2);
    float* b1s  = (float*)(smem + SM_B1);
    float* b2s  = (float*)(smem + SM_B2);
    float* b3s  = (float*)(smem + SM_B3);
    float* dirs = (float*)(smem + SM_DIR);
    float* geos = (float*)(smem + SM_GEO);
    float* comp = (float*)(smem + SM_COMP);
    float* cpart= (float*)(smem + SM_CPART);
    uint32_t* XsH = (uint32_t*)(smem + SM_XH);
    uint32_t* XsL = (uint32_t*)(smem + SM_XL);
    const uint2* WA  = (const uint2*)(smem + SM_WA);
    const uint2* WB  = (const uint2*)(smem + SM_WB);
    const uint2* W3b = (const uint2*)(smem + SM_W3);

    const uint32_t sWA = smem_u32(smem + SM_WA);
    const uint32_t sWB = smem_u32(smem + SM_WB);
    const uint32_t sW3 = smem_u32(smem + SM_W3);
    const char* gp = (const char*)g_pack;

    // kick off async weight staging: c0->A (g1), c1->B (g2), P3 (g3)
    copy64k(sWA, gp,            tid);
    copy64k(sWB, gp + 65536,    tid);
    copy16k(sW3, gp + 327680,   tid);

    // small constants
    if (tid < 256) { b1s[tid] = b1[tid]; b2s[tid] = b2[tid]; }
    if (tid < 16) b3s[tid] = b3[tid];
    for (int e = tid; e < 2688; e += 256) wc1s[e] = Wc1[e];
    for (int e = tid; e < 192; e += 256) wc2s[e] = Wc2[e];
    if (tid < 64) bc1s[tid] = bc1[tid];
    if (tid < 3) bc2s[tid] = bc2[tid];

    // ---------------- ray setup ----------------
    float ox = rays_o[ray*3+0], oy = rays_o[ray*3+1], oz = rays_o[ray*3+2];
    float rdx = rays_d[ray*3+0], rdy = rays_d[ray*3+1], rdz = rays_d[ray*3+2];
    float inv_norm = 1.0f / sqrtf(rdx*rdx + rdy*rdy + rdz*rdz);
    float dx = rdx*inv_norm, dy = rdy*inv_norm, dz = rdz*inv_norm;
    float near_t, far_t;
    {
        float dd;
        dd = (fabsf(dx) < 1e-8f) ? 1e-8f : dx; float i0 = 1.0f/dd;
        dd = (fabsf(dy) < 1e-8f) ? 1e-8f : dy; float i1 = 1.0f/dd;
        dd = (fabsf(dz) < 1e-8f) ? 1e-8f : dz; float i2 = 1.0f/dd;
        float t0x=(-1.f-ox)*i0, t1x=(1.f-ox)*i0;
        float t0y=(-1.f-oy)*i1, t1y=(1.f-oy)*i1;
        float t0z=(-1.f-oz)*i2, t1z=(1.f-oz)*i2;
        float nx=fminf(t0x,t1x), fx=fmaxf(t0x,t1x);
        float ny=fminf(t0y,t1y), fy=fmaxf(t0y,t1y);
        float nz=fminf(t0z,t1z), fz=fmaxf(t0z,t1z);
        near_t = fmaxf(fmaxf(nx, fmaxf(ny, nz)), 0.02f);
        far_t  = fminf(fmaxf(fx, fmaxf(fy, fz)), 1000.f);
        far_t  = fmaxf(far_t, near_t + 0.001f);
    }
    const float dtv = (far_t - near_t) * (1.0f/128.0f);

    // ---------------- posenc -> XsH/XsL (pre-split packed pairs), dirs ----------------
    if (tid < 128) {
        float xv[64];
        float t = near_t + ((float)tid + 0.5f) * dtv;
        xv[0] = ox + t*dx; xv[1] = oy + t*dy; xv[2] = oz + t*dz;
        xv[63] = 0.f;
        float pv[3] = {xv[0], xv[1], xv[2]};
        #pragma unroll
        for (int i = 0; i < 3; i++) {
            float f = 1.f;
            #pragma unroll
            for (int q = 0; q < 10; q++) {
                float s, c;
                sincos_acc(pv[i]*f, &s, &c);
                xv[3  + i*10 + q] = s;
                xv[33 + i*10 + q] = c;
                f *= 2.f;
            }
        }
        #pragma unroll
        for (int p = 0; p < 32; p++) {
            uint32_t hh, ll;
            bf16_split2(xv[2*p], xv[2*p+1], hh, ll);
            XsH[p*130 + tid] = hh;
            XsL[p*130 + tid] = ll;
        }
    } else if (tid < 128 + 27) {
        int j = tid - 128;
        float dv[3] = {dx, dy, dz};
        float v;
        if (j < 3) v = dv[j];
        else if (j < 15) { int jj = j-3;  float s,c; sincos_acc(dv[jj>>2]*(float)(1<<(jj&3)), &s, &c); v = s; }
        else             { int jj = j-15; float s,c; sincos_acc(dv[jj>>2]*(float)(1<<(jj&3)), &s, &c); v = c; }
        dirs[j] = v;
    }

    // wait for P1 (g1): outstanding <= 2 (g2, g3)
    CP_WAIT(2);
    __syncthreads();

    // ---------------- Layer 1: H1 = relu(X @ W1 + b1), chained to regs ----------------
    uint32_t h1h[64], h1l[64];
    #pragma unroll
    for (int h = 0; h < 2; h++) {
        float acc[16][4];
        #pragma unroll
        for (int i = 0; i < 16; i++)
            #pragma unroll
            for (int j = 0; j < 4; j++) acc[i][j] = 0.f;

        #pragma unroll
        for (int kt = 0; kt < 4; kt++) {
            int pb0 = kt*8 + (lane & 3);
            uint32_t ah0 = XsH[pb0*130 + r0];
            uint32_t ah1 = XsH[pb0*130 + r0 + 8];
            uint32_t ah2 = XsH[(pb0+4)*130 + r0];
            uint32_t ah3 = XsH[(pb0+4)*130 + r0 + 8];
            uint32_t al0 = XsL[pb0*130 + r0];
            uint32_t al1 = XsL[pb0*130 + r0 + 8];
            uint32_t al2 = XsL[(pb0+4)*130 + r0];
            uint32_t al3 = XsL[(pb0+4)*130 + r0 + 8];
            #pragma unroll
            for (int i = 0; i < 16; i++) {
                const uint2* pb = WA + (kt*32 + h*16 + i)*32 + lane;
                uint2 bh = *pb;
                MMA(acc[i], ah0, ah1, ah2, ah3, bh.x, bh.y);
                MMA(acc[i], al0, al1, al2, al3, bh.x, bh.y);
                uint2 bl = *(pb + 4096);
                MMA(acc[i], ah0, ah1, ah2, ah3, bl.x, bl.y);
            }
        }
        #pragma unroll
        for (int i = 0; i < 16; i++) {
            int n0 = h*128 + i*8 + qk;
            float2 bb = *(const float2*)(b1s + n0);
            float v0 = fmaxf(acc[i][0] + bb.x, 0.f);
            float v1 = fmaxf(acc[i][1] + bb.y, 0.f);
            float v2 = fmaxf(acc[i][2] + bb.x, 0.f);
            float v3 = fmaxf(acc[i][3] + bb.y, 0.f);
            int idx = (h*16 + i) * 2;
            bf16_split2(v0, v1, h1h[idx],   h1l[idx]);
            bf16_split2(v2, v3, h1h[idx+1], h1l[idx+1]);
        }
    }
    __syncthreads();

    // stage c2 -> A (g4)
    copy64k(sWA, gp + 2*65536, tid);
    // wait g2 (B = P2 h0 p0) and g3 (W3): outstanding <= 1 (g4)
    CP_WAIT(1);
    __syncthreads();

    float geo[2][4];
    #pragma unroll
    for (int nt = 0; nt < 2; nt++)
        #pragma unroll
        for (int j = 0; j < 4; j++) geo[nt][j] = 0.f;

    // ---------------- Layer 2+3 half 0 ----------------
    layer2_half(WB, WA, 0, lane, h1h, h1l, b2s, W3b, geo, qk);
    __syncthreads();

    // stage c3 -> B (g5), c4 -> A (g6)
    copy64k(sWB, gp + 3*65536, tid);
    copy64k(sWA, gp + 4*65536, tid);
    CP_WAIT(1);           // g5 done
    __syncthreads();

    // ---------------- Layer 2+3 half 1 ----------------
    layer2_half(WB, WA, 1, lane, h1h, h1l, b2s, W3b, geo, qk);

    // ---------------- geo -> smem ----------------
    #pragma unroll
    for (int nt = 0; nt < 2; nt++) {
        int c = nt*8 + qk;
        *(float2*)(geos + r0*16 + c)     = make_float2(geo[nt][0], geo[nt][1]);
        *(float2*)(geos + (r0+8)*16 + c) = make_float2(geo[nt][2], geo[nt][3]);
    }
    __syncthreads();

    // ---------------- color head ----------------
    {
        int m = tid & 127;
        float inp[42];
        #pragma unroll
        for (int i = 0; i < 27; i++) inp[i] = dirs[i];
        #pragma unroll
        for (int i = 0; i < 15; i++) inp[27 + i] = geos[m*16 + 1 + i] + b3s[1 + i];
        int j0 = (tid < 128) ? 0 : 32;
        float a0 = 0.f, a1 = 0.f, a2 = 0.f;
        for (int j = j0; j < j0 + 32; j++) {
            float hcc = bc1s[j];
            #pragma unroll
            for (int i = 0; i < 42; i++)
                hcc = fmaf(inp[i], wc1s[i*64 + j], hcc);
            hcc = fmaxf(hcc, 0.f);
            a0 = fmaf(hcc, wc2s[j*3+0], a0);
            a1 = fmaf(hcc, wc2s[j*3+1], a1);
            a2 = fmaf(hcc, wc2s[j*3+2], a2);
        }
        if (tid >= 128) {
            cpart[m*4+0] = a0; cpart[m*4+1] = a1; cpart[m*4+2] = a2;
        }
        __syncthreads();
        if (tid < 128) {
            a0 += cpart[m*4+0] + bc2s[0];
            a1 += cpart[m*4+1] + bc2s[1];
            a2 += cpart[m*4+2] + bc2s[2];
            float sx = geos[m*16] + b3s[0];
            float sigma = (sx > 20.f) ? sx : log1pf(expf(sx));
            float alpha = 1.f - expf(-sigma * dtv);
            comp[m*4+0] = alpha;
            comp[m*4+1] = 1.f / (1.f + expf(-a0));
            comp[m*4+2] = 1.f / (1.f + expf(-a1));
            comp[m*4+3] = 1.f / (1.f + expf(-a2));
        }
    }
    __syncthreads();

    // ---------------- composite: warp-0 parallel scan ----------------
    if (tid < 32) {
        float av[4];
        #pragma unroll
        for (int j = 0; j < 4; j++) av[j] = comp[(lane*4 + j)*4 + 0];
        float q0 = 1.f - av[0] + 1e-10f;
        float q1 = 1.f - av[1] + 1e-10f;
        float q2 = 1.f - av[2] + 1e-10f;
        float q3 = 1.f - av[3] + 1e-10f;
        float inc = ((q0*q1)*(q2*q3));
        #pragma unroll
        for (int off = 1; off < 32; off <<= 1) {
            float t = __shfl_up_sync(0xFFFFFFFF, inc, off);
            if (lane >= off) inc *= t;
        }
        float T = __shfl_up_sync(0xFFFFFFFF, inc, 1);
        if (lane == 0) T = 1.f;
        float wsum = 0.f, dsum = 0.f, r = 0.f, g = 0.f, b = 0.f;
        #pragma unroll
        for (int j = 0; j < 4; j++) {
            int m = lane*4 + j;
            float alpha = av[j];
            float wgt = (T > 1e-4f) ? alpha * T : 0.f;
            wsum += wgt;
            float tsv = near_t + ((float)m + 0.5f) * dtv;
            dsum = fmaf(wgt, tsv, dsum);
            r = fmaf(wgt, comp[m*4+1], r);
            g = fmaf(wgt, comp[m*4+2], g);
            b = fmaf(wgt, comp[m*4+3], b);
            T *= (1.f - alpha + 1e-10f);
        }
        #pragma unroll
        for (int off = 16; off > 0; off >>= 1) {
            wsum += __shfl_xor_sync(0xFFFFFFFF, wsum, off);
            dsum += __shfl_xor_sync(0xFFFFFFFF, dsum, off);
            r    += __shfl_xor_sync(0xFFFFFFFF, r, off);
            g    += __shfl_xor_sync(0xFFFFFFFF, g, off);
            b    += __shfl_xor_sync(0xFFFFFFFF, b, off);
        }
        if (lane == 0) {
            float bgw = 1.f - wsum;
            out[ray*3+0] = r + bgw;
            out[ray*3+1] = g + bgw;
            out[ray*3+2] = b + bgw;
            out[4096*3 + ray] = dsum;
            out[4096*4 + ray] = fminf(fmaxf(wsum, 1e-12f), 1000.f);
        }
    }
}

// ===================== launch =====================
extern "C" void kernel_launch(void* const* d_in, const int* in_sizes, int n_in,
                              void* d_out, int out_size) {
    const float* rays_o = (const float*)d_in[0];
    const float* rays_d = (const float*)d_in[1];
    const float* W1  = (const float*)d_in[2];
    const float* b1  = (const float*)d_in[3];
    const float* W2  = (const float*)d_in[4];
    const float* b2  = (const float*)d_in[5];
    const float* W3  = (const float*)d_in[6];
    const float* b3  = (const float*)d_in[7];
    const float* Wc1 = (const float*)d_in[8];
    const float* bc1 = (const float*)d_in[9];
    const float* Wc2 = (const float*)d_in[10];
    const float* bc2 = (const float*)d_in[11];
    float* out = (float*)d_out;

    prep_pack<<<84, 256>>>(W1, W2, W3);
    cudaFuncSetAttribute(nerf_mma, cudaFuncAttributeMaxDynamicSharedMemorySize, SMEM_BYTES);
    nerf_mma<<<4096, 256, SMEM_BYTES>>>(rays_o, rays_d, b1, b2, b3,
                                        Wc1, bc1, Wc2, bc2, out);
}

// round 5
// speedup vs baseline: 3.2661x; 1.4530x over previous
#include <cuda_runtime.h>
#include <cuda_bf16.h>
#include <math.h>
#include <stdint.h>

// ===================== asm helpers (plain sm_100-safe) =====================
__device__ __forceinline__ uint32_t smem_u32(const void* p) {
    uint32_t a;
    asm("{ .reg .u64 t; cvta.to.shared.u64 t, %1; cvt.u32.u64 %0, t; }" : "=r"(a) : "l"(p));
    return a;
}
#define CP16(dst_u32, src_ptr) \
    asm volatile("cp.async.cg.shared.global [%0], [%1], 16;" :: "r"(dst_u32), "l"(src_ptr) : "memory")
#define CP_COMMIT() asm volatile("cp.async.commit_group;" ::: "memory")
#define CP_WAIT(n)  asm volatile("cp.async.wait_group %0;" :: "n"(n) : "memory")

#define MMA(d, a0, a1, a2, a3, b0, b1) \
    asm("mma.sync.aligned.m16n8k16.row.col.f32.bf16.bf16.f32 " \
        "{%0,%1,%2,%3}, {%4,%5,%6,%7}, {%8,%9}, {%0,%1,%2,%3};" \
        : "+f"((d)[0]), "+f"((d)[1]), "+f"((d)[2]), "+f"((d)[3]) \
        : "r"(a0), "r"(a1), "r"(a2), "r"(a3), "r"(b0), "r"(b1))

// ===================== smem byte offsets =====================
#define SM_WA    0          // 65536  weight buffer A
#define SM_WB    65536      // 65536  weight buffer B
#define SM_W3    131072     // 16384  W3 packed (hi 8K | lo 8K)
#define SM_XH    147456     // 16640  X posenc bf16 packed [32 pairs][130]
#define SM_WC1   164096     // 10752
#define SM_WC2   174848     // 768
#define SM_BC1   175616     // 256
#define SM_BC2   175872     // 16
#define SM_B1    175888     // 1024
#define SM_B2    176912     // 1024
#define SM_B3    177936     // 64
#define SM_DIR   178000     // 128
#define SM_GEO   178128     // 8192  [128][16] fp32
#define SM_COMP  186320     // 2048
#define SM_CPART 188368     // 2048
#define SMEM_BYTES 190416

// packed weight image: chunks 0..4 are 64KB each (hi 32K | lo 32K), P3 is 16KB
__device__ __align__(128) uint32_t g_pack[86016];   // 336KB

__device__ __forceinline__ void bf16_split2(float x, float y, uint32_t& h, uint32_t& l) {
    __nv_bfloat16 hx = __float2bfloat16(x), hy = __float2bfloat16(y);
    h = (uint32_t)__bfloat16_as_ushort(hx) | ((uint32_t)__bfloat16_as_ushort(hy) << 16);
    __nv_bfloat16 lx = __float2bfloat16(x - __bfloat162float(hx));
    __nv_bfloat16 ly = __float2bfloat16(y - __bfloat162float(hy));
    l = (uint32_t)__bfloat16_as_ushort(lx) | ((uint32_t)__bfloat16_as_ushort(ly) << 16);
}
__device__ __forceinline__ uint32_t bf16_pack2(float x, float y) {
    __nv_bfloat16 hx = __float2bfloat16(x), hy = __float2bfloat16(y);
    return (uint32_t)__bfloat16_as_ushort(hx) | ((uint32_t)__bfloat16_as_ushort(hy) << 16);
}

// fp32 Cody-Waite 2-term range reduction mod 2*pi, then sincosf on small arg.
__device__ __forceinline__ void sincos_acc(float phi, float* s, float* c) {
    float k = rintf(phi * 0.15915494309f);
    float r = fmaf(-k, 6.2831854820251465f, phi);      // 2pi hi (fp32)
    r = fmaf(-k, -1.7484556000744263e-07f, r);         // 2pi lo
    sincosf(r, s, c);
}

// ===================== prep kernel: pack weights into fragment order =====================
__global__ void prep_pack(const float* __restrict__ W1, const float* __restrict__ W2,
                          const float* __restrict__ W3) {
    int s = blockIdx.x * 256 + threadIdx.x;
    if (s >= 21504) return;
    int lane = s & 31;
    int qn = lane >> 2, qk = (lane & 3) * 2;
    const float* W; int kbase, n, ldn, kmax; uint32_t base, idx, hsz;
    if (s < 4096) {                       // P1: 4 kt x 32 nt
        int t = s >> 5;
        int nt = t & 31, kt = t >> 5;
        kbase = kt * 16; n = nt * 8 + qn; W = W1; ldn = 256; kmax = 63;
        base = 0; idx = (uint32_t)((kt * 32 + nt) * 32 + lane); hsz = 8192;
    } else if (s < 20480) {               // P2: 4 chunks x (8 ktl x 16 ntl)
        int t = (s - 4096) >> 5;
        int ntl = t & 15, ktl = (t >> 4) & 7, cr = t >> 7;   // cr = h*2 + p
        int h = cr >> 1, p = cr & 1;
        kbase = (p * 8 + ktl) * 16; n = (h * 16 + ntl) * 8 + qn; W = W2; ldn = 256; kmax = 256;
        base = 16384u * (1 + cr); idx = (uint32_t)((ktl * 16 + ntl) * 32 + lane); hsz = 8192;
    } else {                              // P3: 16 kt x 2 nt
        int t = (s - 20480) >> 5;
        int nt = t & 1, kt = t >> 1;
        kbase = kt * 16; n = nt * 8 + qn; W = W3; ldn = 16; kmax = 256;
        base = 81920; idx = (uint32_t)((kt * 2 + nt) * 32 + lane); hsz = 2048;
    }
    int ks[4] = {kbase + qk, kbase + qk + 1, kbase + qk + 8, kbase + qk + 9};
    float e[4];
    #pragma unroll
    for (int j = 0; j < 4; j++) e[j] = (ks[j] < kmax) ? W[ks[j] * ldn + n] : 0.f;
    uint32_t h0, l0, h1, l1;
    bf16_split2(e[0], e[1], h0, l0);
    bf16_split2(e[2], e[3], h1, l1);
    g_pack[base + idx * 2]           = h0;
    g_pack[base + idx * 2 + 1]       = h1;
    g_pack[base + hsz + idx * 2]     = l0;
    g_pack[base + hsz + idx * 2 + 1] = l1;
}

// ===================== copies =====================
__device__ __forceinline__ void copy64k(uint32_t dst, const void* src, int tid) {
    #pragma unroll
    for (int j = 0; j < 16; j++)
        CP16(dst + (uint32_t)(tid + j * 256) * 16, (const char*)src + (tid + j * 256) * 16);
    CP_COMMIT();
}
__device__ __forceinline__ void copy16k(uint32_t dst, const void* src, int tid) {
    #pragma unroll
    for (int j = 0; j < 4; j++)
        CP16(dst + (uint32_t)(tid + j * 256) * 16, (const char*)src + (tid + j * 256) * 16);
    CP_COMMIT();
}

// ===================== layer 2 half (+ fused layer 3), A single bf16 ==========
__device__ __forceinline__ void layer2_half(
    const uint2* Bp0, const uint2* Bp1, int h2, int lane,
    const uint32_t* h1h,
    const float* b2s, const uint2* W3b, float geo[2][4], int qk)
{
    float acc[16][4];
    #pragma unroll
    for (int i = 0; i < 16; i++)
        #pragma unroll
        for (int j = 0; j < 4; j++) acc[i][j] = 0.f;

    #pragma unroll
    for (int p = 0; p < 2; p++) {
        const uint2* B = p ? Bp1 : Bp0;
        if (p == 1) { CP_WAIT(0); __syncthreads(); }
        #pragma unroll
        for (int ktl = 0; ktl < 8; ktl++) {
            int kt = p * 8 + ktl;
            uint32_t a0 = h1h[4*kt], a1 = h1h[4*kt+1], a2 = h1h[4*kt+2], a3 = h1h[4*kt+3];
            #pragma unroll
            for (int i = 0; i < 16; i++) {
                const uint2* pb = B + (ktl * 16 + i) * 32 + lane;
                uint2 bh = *pb;
                MMA(acc[i], a0, a1, a2, a3, bh.x, bh.y);
                uint2 bl = *(pb + 4096);
                MMA(acc[i], a0, a1, a2, a3, bl.x, bl.y);
            }
        }
    }
    // fused epilogue + layer-3 partial (pairs of acc tiles -> 4 A-frag words)
    #pragma unroll
    for (int ii = 0; ii < 8; ii++) {
        int i0 = 2 * ii, i1 = i0 + 1;
        uint32_t s0h, s1h, s2h, s3h;
        {
            int n0 = h2 * 128 + i0 * 8 + qk;
            float2 bb = *(const float2*)(b2s + n0);
            s0h = bf16_pack2(fmaxf(acc[i0][0] + bb.x, 0.f), fmaxf(acc[i0][1] + bb.y, 0.f));
            s1h = bf16_pack2(fmaxf(acc[i0][2] + bb.x, 0.f), fmaxf(acc[i0][3] + bb.y, 0.f));
        }
        {
            int n1 = h2 * 128 + i1 * 8 + qk;
            float2 bb = *(const float2*)(b2s + n1);
            s2h = bf16_pack2(fmaxf(acc[i1][0] + bb.x, 0.f), fmaxf(acc[i1][1] + bb.y, 0.f));
            s3h = bf16_pack2(fmaxf(acc[i1][2] + bb.x, 0.f), fmaxf(acc[i1][3] + bb.y, 0.f));
        }
        int kt3 = h2 * 8 + ii;
        #pragma unroll
        for (int nt = 0; nt < 2; nt++) {
            const uint2* pb = W3b + (kt3 * 2 + nt) * 32 + lane;
            uint2 bh = *pb;
            MMA(geo[nt], s0h, s1h, s2h, s3h, bh.x, bh.y);
            uint2 bl = *(pb + 1024);
            MMA(geo[nt], s0h, s1h, s2h, s3h, bl.x, bl.y);
        }
    }
}

// ===================== main kernel =====================
__global__ void __launch_bounds__(256, 1)
nerf_mma(const float* __restrict__ rays_o, const float* __restrict__ rays_d,
         const float* __restrict__ b1, const float* __restrict__ b2,
         const float* __restrict__ b3,
         const float* __restrict__ Wc1, const float* __restrict__ bc1,
         const float* __restrict__ Wc2, const float* __restrict__ bc2,
         float* __restrict__ out)
{
    extern __shared__ char smem[];
    const int tid = threadIdx.x;
    const int lane = tid & 31;
    const int w = tid >> 5;
    const int ray = blockIdx.x;
    const int qk = (lane & 3) * 2;
    const int r0 = w * 16 + (lane >> 2);

    float* wc1s = (float*)(smem + SM_WC1);
    float* wc2s = (float*)(smem + SM_WC2);
    float* bc1s = (float*)(smem + SM_BC1);
    float* bc2s = (float*)(smem + SM_BC2);
    float* b1s  = (float*)(smem + SM_B1);
    float* b2s  = (float*)(smem + SM_B2);
    float* b3s  = (float*)(smem + SM_B3);
    float* dirs = (float*)(smem + SM_DIR);
    float* geos = (float*)(smem + SM_GEO);
    float* comp = (float*)(smem + SM_COMP);
    float* cpart= (float*)(smem + SM_CPART);
    uint32_t* XsH = (uint32_t*)(smem + SM_XH);
    const uint2* WA  = (const uint2*)(smem + SM_WA);
    const uint2* WB  = (const uint2*)(smem + SM_WB);
    const uint2* W3b = (const uint2*)(smem + SM_W3);

    const uint32_t sWA = smem_u32(smem + SM_WA);
    const uint32_t sWB = smem_u32(smem + SM_WB);
    const uint32_t sW3 = smem_u32(smem + SM_W3);
    const char* gp = (const char*)g_pack;

    // kick off async weight staging: c0->A (g1), c1->B (g2), P3 (g3)
    copy64k(sWA, gp,            tid);
    copy64k(sWB, gp + 65536,    tid);
    copy16k(sW3, gp + 327680,   tid);

    // small constants
    if (tid < 256) { b1s[tid] = b1[tid]; b2s[tid] = b2[tid]; }
    if (tid < 16) b3s[tid] = b3[tid];
    for (int e = tid; e < 2688; e += 256) wc1s[e] = Wc1[e];
    for (int e = tid; e < 192; e += 256) wc2s[e] = Wc2[e];
    if (tid < 64) bc1s[tid] = bc1[tid];
    if (tid < 3) bc2s[tid] = bc2[tid];

    // ---------------- ray setup ----------------
    float ox = rays_o[ray*3+0], oy = rays_o[ray*3+1], oz = rays_o[ray*3+2];
    float rdx = rays_d[ray*3+0], rdy = rays_d[ray*3+1], rdz = rays_d[ray*3+2];
    float inv_norm = 1.0f / sqrtf(rdx*rdx + rdy*rdy + rdz*rdz);
    float dx = rdx*inv_norm, dy = rdy*inv_norm, dz = rdz*inv_norm;
    float near_t, far_t;
    {
        float dd;
        dd = (fabsf(dx) < 1e-8f) ? 1e-8f : dx; float i0 = 1.0f/dd;
        dd = (fabsf(dy) < 1e-8f) ? 1e-8f : dy; float i1 = 1.0f/dd;
        dd = (fabsf(dz) < 1e-8f) ? 1e-8f : dz; float i2 = 1.0f/dd;
        float t0x=(-1.f-ox)*i0, t1x=(1.f-ox)*i0;
        float t0y=(-1.f-oy)*i1, t1y=(1.f-oy)*i1;
        float t0z=(-1.f-oz)*i2, t1z=(1.f-oz)*i2;
        float nx=fminf(t0x,t1x), fx=fmaxf(t0x,t1x);
        float ny=fminf(t0y,t1y), fy=fmaxf(t0y,t1y);
        float nz=fminf(t0z,t1z), fz=fmaxf(t0z,t1z);
        near_t = fmaxf(fmaxf(nx, fmaxf(ny, nz)), 0.02f);
        far_t  = fminf(fmaxf(fx, fmaxf(fy, fz)), 1000.f);
        far_t  = fmaxf(far_t, near_t + 0.001f);
    }
    const float dtv = (far_t - near_t) * (1.0f/128.0f);

    // ---------------- posenc -> XsH (bf16 packed pairs), dirs ----------------
    if (tid < 128) {
        float xv[64];
        float t = near_t + ((float)tid + 0.5f) * dtv;
        xv[0] = ox + t*dx; xv[1] = oy + t*dy; xv[2] = oz + t*dz;
        xv[63] = 0.f;
        float pv[3] = {xv[0], xv[1], xv[2]};
        #pragma unroll
        for (int i = 0; i < 3; i++) {
            float f = 1.f;
            #pragma unroll
            for (int q = 0; q < 10; q++) {
                float s, c;
                sincos_acc(pv[i]*f, &s, &c);
                xv[3  + i*10 + q] = s;
                xv[33 + i*10 + q] = c;
                f *= 2.f;
            }
        }
        #pragma unroll
        for (int p = 0; p < 32; p++)
            XsH[p*130 + tid] = bf16_pack2(xv[2*p], xv[2*p+1]);
    } else if (tid < 128 + 27) {
        int j = tid - 128;
        float dv[3] = {dx, dy, dz};
        float v;
        if (j < 3) v = dv[j];
        else if (j < 15) { int jj = j-3;  float s,c; sincos_acc(dv[jj>>2]*(float)(1<<(jj&3)), &s, &c); v = s; }
        else             { int jj = j-15; float s,c; sincos_acc(dv[jj>>2]*(float)(1<<(jj&3)), &s, &c); v = c; }
        dirs[j] = v;
    }

    // wait for P1 (g1): outstanding <= 2 (g2, g3)
    CP_WAIT(2);
    __syncthreads();

    // ---------------- Layer 1: H1 = relu(X @ W1 + b1) -> regs (bf16 packed) ----
    uint32_t h1h[64];
    #pragma unroll
    for (int h = 0; h < 2; h++) {
        float acc[16][4];
        #pragma unroll
        for (int i = 0; i < 16; i++)
            #pragma unroll
            for (int j = 0; j < 4; j++) acc[i][j] = 0.f;

        #pragma unroll
        for (int kt = 0; kt < 4; kt++) {
            int pb0 = kt*8 + (lane & 3);
            uint32_t ah0 = XsH[pb0*130 + r0];
            uint32_t ah1 = XsH[pb0*130 + r0 + 8];
            uint32_t ah2 = XsH[(pb0+4)*130 + r0];
            uint32_t ah3 = XsH[(pb0+4)*130 + r0 + 8];
            #pragma unroll
            for (int i = 0; i < 16; i++) {
                const uint2* pb = WA + (kt*32 + h*16 + i)*32 + lane;
                uint2 bh = *pb;
                MMA(acc[i], ah0, ah1, ah2, ah3, bh.x, bh.y);
                uint2 bl = *(pb + 4096);
                MMA(acc[i], ah0, ah1, ah2, ah3, bl.x, bl.y);
            }
        }
        #pragma unroll
        for (int i = 0; i < 16; i++) {
            int n0 = h*128 + i*8 + qk;
            float2 bb = *(const float2*)(b1s + n0);
            int idx = (h*16 + i) * 2;
            h1h[idx]   = bf16_pack2(fmaxf(acc[i][0] + bb.x, 0.f), fmaxf(acc[i][1] + bb.y, 0.f));
            h1h[idx+1] = bf16_pack2(fmaxf(acc[i][2] + bb.x, 0.f), fmaxf(acc[i][3] + bb.y, 0.f));
        }
    }
    __syncthreads();

    // stage c2 -> A (g4)
    copy64k(sWA, gp + 2*65536, tid);
    // wait g2 (B = P2 h0 p0) and g3 (W3): outstanding <= 1 (g4)
    CP_WAIT(1);
    __syncthreads();

    float geo[2][4];
    #pragma unroll
    for (int nt = 0; nt < 2; nt++)
        #pragma unroll
        for (int j = 0; j < 4; j++) geo[nt][j] = 0.f;

    // ---------------- Layer 2+3 half 0 ----------------
    layer2_half(WB, WA, 0, lane, h1h, b2s, W3b, geo, qk);
    __syncthreads();

    // stage c3 -> B (g5), c4 -> A (g6)
    copy64k(sWB, gp + 3*65536, tid);
    copy64k(sWA, gp + 4*65536, tid);
    CP_WAIT(1);           // g5 done
    __syncthreads();

    // ---------------- Layer 2+3 half 1 ----------------
    layer2_half(WB, WA, 1, lane, h1h, b2s, W3b, geo, qk);

    // ---------------- geo -> smem ----------------
    #pragma unroll
    for (int nt = 0; nt < 2; nt++) {
        int c = nt*8 + qk;
        *(float2*)(geos + r0*16 + c)     = make_float2(geo[nt][0], geo[nt][1]);
        *(float2*)(geos + (r0+8)*16 + c) = make_float2(geo[nt][2], geo[nt][3]);
    }
    __syncthreads();

    // ---------------- color head ----------------
    {
        int m = tid & 127;
        float inp[42];
        #pragma unroll
        for (int i = 0; i < 27; i++) inp[i] = dirs[i];
        #pragma unroll
        for (int i = 0; i < 15; i++) inp[27 + i] = geos[m*16 + 1 + i] + b3s[1 + i];
        int j0 = (tid < 128) ? 0 : 32;
        float a0 = 0.f, a1 = 0.f, a2 = 0.f;
        for (int j = j0; j < j0 + 32; j++) {
            float hcc = bc1s[j];
            #pragma unroll
            for (int i = 0; i < 42; i++)
                hcc = fmaf(inp[i], wc1s[i*64 + j], hcc);
            hcc = fmaxf(hcc, 0.f);
            a0 = fmaf(hcc, wc2s[j*3+0], a0);
            a1 = fmaf(hcc, wc2s[j*3+1], a1);
            a2 = fmaf(hcc, wc2s[j*3+2], a2);
        }
        if (tid >= 128) {
            cpart[m*4+0] = a0; cpart[m*4+1] = a1; cpart[m*4+2] = a2;
        }
        __syncthreads();
        if (tid < 128) {
            a0 += cpart[m*4+0] + bc2s[0];
            a1 += cpart[m*4+1] + bc2s[1];
            a2 += cpart[m*4+2] + bc2s[2];
            float sx = geos[m*16] + b3s[0];
            float sigma = (sx > 20.f) ? sx : log1pf(expf(sx));
            float alpha = 1.f - expf(-sigma * dtv);
            comp[m*4+0] = alpha;
            comp[m*4+1] = 1.f / (1.f + expf(-a0));
            comp[m*4+2] = 1.f / (1.f + expf(-a1));
            comp[m*4+3] = 1.f / (1.f + expf(-a2));
        }
    }
    __syncthreads();

    // ---------------- composite: warp-0 parallel scan ----------------
    if (tid < 32) {
        float av[4];
        #pragma unroll
        for (int j = 0; j < 4; j++) av[j] = comp[(lane*4 + j)*4 + 0];
        float q0 = 1.f - av[0] + 1e-10f;
        float q1 = 1.f - av[1] + 1e-10f;
        float q2 = 1.f - av[2] + 1e-10f;
        float q3 = 1.f - av[3] + 1e-10f;
        float inc = ((q0*q1)*(q2*q3));
        #pragma unroll
        for (int off = 1; off < 32; off <<= 1) {
            float t = __shfl_up_sync(0xFFFFFFFF, inc, off);
            if (lane >= off) inc *= t;
        }
        float T = __shfl_up_sync(0xFFFFFFFF, inc, 1);
        if (lane == 0) T = 1.f;
        float wsum = 0.f, dsum = 0.f, r = 0.f, g = 0.f, b = 0.f;
        #pragma unroll
        for (int j = 0; j < 4; j++) {
            int m = lane*4 + j;
            float alpha = av[j];
            float wgt = (T > 1e-4f) ? alpha * T : 0.f;
            wsum += wgt;
            float tsv = near_t + ((float)m + 0.5f) * dtv;
            dsum = fmaf(wgt, tsv, dsum);
            r = fmaf(wgt, comp[m*4+1], r);
            g = fmaf(wgt, comp[m*4+2], g);
            b = fmaf(wgt, comp[m*4+3], b);
            T *= (1.f - alpha + 1e-10f);
        }
        #pragma unroll
        for (int off = 16; off > 0; off >>= 1) {
            wsum += __shfl_xor_sync(0xFFFFFFFF, wsum, off);
            dsum += __shfl_xor_sync(0xFFFFFFFF, dsum, off);
            r    += __shfl_xor_sync(0xFFFFFFFF, r, off);
            g    += __shfl_xor_sync(0xFFFFFFFF, g, off);
            b    += __shfl_xor_sync(0xFFFFFFFF, b, off);
        }
        if (lane == 0) {
            float bgw = 1.f - wsum;
            out[ray*3+0] = r + bgw;
            out[ray*3+1] = g + bgw;
            out[ray*3+2] = b + bgw;
            out[4096*3 + ray] = dsum;
            out[4096*4 + ray] = fminf(fmaxf(wsum, 1e-12f), 1000.f);
        }
    }
}

// ===================== launch =====================
extern "C" void kernel_launch(void* const* d_in, const int* in_sizes, int n_in,
                              void* d_out, int out_size) {
    const float* rays_o = (const float*)d_in[0];
    const float* rays_d = (const float*)d_in[1];
    const float* W1  = (const float*)d_in[2];
    const float* b1  = (const float*)d_in[3];
    const float* W2  = (const float*)d_in[4];
    const float* b2  = (const float*)d_in[5];
    const float* W3  = (const float*)d_in[6];
    const float* b3  = (const float*)d_in[7];
    const float* Wc1 = (const float*)d_in[8];
    const float* bc1 = (const float*)d_in[9];
    const float* Wc2 = (const float*)d_in[10];
    const float* bc2 = (const float*)d_in[11];
    float* out = (float*)d_out;

    prep_pack<<<84, 256>>>(W1, W2, W3);
    cudaFuncSetAttribute(nerf_mma, cudaFuncAttributeMaxDynamicSharedMemorySize, SMEM_BYTES);
    nerf_mma<<<4096, 256, SMEM_BYTES>>>(rays_o, rays_d, b1, b2, b3,
                                        Wc1, bc1, Wc2, bc2, out);
}

// round 6
// speedup vs baseline: 4.8995x; 1.5001x over previous
#include <cuda_runtime.h>
#include <cuda_bf16.h>
#include <math.h>
#include <stdint.h>

// ===================== asm helpers =====================
__device__ __forceinline__ uint32_t smem_u32(const void* p) {
    uint32_t a;
    asm("{ .reg .u64 t; cvta.to.shared.u64 t, %1; cvt.u32.u64 %0, t; }" : "=r"(a) : "l"(p));
    return a;
}
#define CP16(dst_u32, src_ptr) \
    asm volatile("cp.async.cg.shared.global [%0], [%1], 16;" :: "r"(dst_u32), "l"(src_ptr) : "memory")
#define CP_COMMIT() asm volatile("cp.async.commit_group;" ::: "memory")
#define CP_WAIT(n)  asm volatile("cp.async.wait_group %0;" :: "n"(n) : "memory")

#define MMA(d, a0, a1, a2, a3, b0, b1) \
    asm("mma.sync.aligned.m16n8k16.row.col.f32.bf16.bf16.f32 " \
        "{%0,%1,%2,%3}, {%4,%5,%6,%7}, {%8,%9}, {%0,%1,%2,%3};" \
        : "+f"((d)[0]), "+f"((d)[1]), "+f"((d)[2]), "+f"((d)[3]) \
        : "r"(a0), "r"(a1), "r"(a2), "r"(a3), "r"(b0), "r"(b1))

// ===================== smem layout =====================
#define SM_P2    0          // 131072   W2 fragments (resident whole kernel until color head)
#define SM_P3    131072     // 8192     W3 fragments
#define SM_H1    139264     // 67584    H1 bf16 pairs [128][132] u32 (phase 2)
#define SM_P1    139264     //   phase 1 alias: W1 fragments (32768)
#define SM_X     172032     //   phase 1 alias: posenc X bf16 pairs [32][132] u32 (16896)
#define SM_B1    206848     // 1024
#define SM_B2    207872     // 1024
#define SM_B3    208896     // 64
#define SM_DIR   208960     // 128
#define SM_RED   209088     // 8192     layer-3 N-half partials
#define SM_COMP  217280     // 2048
#define SM_BC2   219328     // 16
#define SMEM_BYTES 219344
// aliases inside dead P2 region (valid after layer-2 MMAs):
#define SM_WC1   0          // 10752
#define SM_WC2   10752      // 768
#define SM_BC1   11520      // 256
#define SM_CPART 12288      // 6144  (3 groups x 128 x 4 floats)
#define SM_GEOS  18432      // 8192  [128][16] fp32

// packed weight image (bf16 fragment order): P1 32KB | P2 128KB | P3 8KB
__device__ __align__(128) uint32_t g_pack[43008];

__device__ __forceinline__ uint32_t bf16_pack2(float x, float y) {
    __nv_bfloat16 hx = __float2bfloat16(x), hy = __float2bfloat16(y);
    return (uint32_t)__bfloat16_as_ushort(hx) | ((uint32_t)__bfloat16_as_ushort(hy) << 16);
}
__device__ __forceinline__ void sts_bf16(uint32_t addr, float v) {
    uint16_t u = __bfloat16_as_ushort(__float2bfloat16(v));
    asm volatile("st.shared.u16 [%0], %1;" :: "r"(addr), "h"(u));
}
// fp32 Cody-Waite range reduction mod 2*pi, then sincosf on small arg
__device__ __forceinline__ void sincos_acc(float phi, float* s, float* c) {
    float k = rintf(phi * 0.15915494309f);
    float r = fmaf(-k, 6.2831854820251465f, phi);
    r = fmaf(-k, -1.7484556000744263e-07f, r);
    sincosf(r, s, c);
}

// ===================== prep: pack weights into per-lane fragment order =====================
// tile t, lane: uint2 = {pack(W[k0,n],W[k0+1,n]), pack(W[k0+8,n],W[k0+9,n])},
// k0 = kt*16 + 2*(lane&3), n = nt*8 + (lane>>2)
__global__ void prep_pack(const float* __restrict__ W1, const float* __restrict__ W2,
                          const float* __restrict__ W3) {
    int s = blockIdx.x * 256 + threadIdx.x;
    if (s >= 21504) return;
    int lane = s & 31;
    int qn = lane >> 2, qk = (lane & 3) * 2;
    const float* W; int kbase, n, ldn, kmax; uint32_t base, idx;
    if (s < 4096) {                       // P1: 4 kt x 32 nt
        int t = s >> 5;
        kbase = (t >> 5) * 16; n = (t & 31) * 8 + qn; W = W1; ldn = 256; kmax = 63;
        base = 0; idx = (uint32_t)s;
    } else if (s < 20480) {               // P2: 16 kt x 32 nt
        int t = (s - 4096) >> 5;
        kbase = (t >> 5) * 16; n = (t & 31) * 8 + qn; W = W2; ldn = 256; kmax = 256;
        base = 8192; idx = (uint32_t)(s - 4096);
    } else {                              // P3: 16 kt x 2 nt
        int t = (s - 20480) >> 5;
        kbase = (t >> 1) * 16; n = (t & 1) * 8 + qn; W = W3; ldn = 16; kmax = 256;
        base = 40960; idx = (uint32_t)(s - 20480);
    }
    int k0 = kbase + qk;
    float e0 = (k0     < kmax) ? W[(k0)     * ldn + n] : 0.f;
    float e1 = (k0 + 1 < kmax) ? W[(k0 + 1) * ldn + n] : 0.f;
    float e2 = (k0 + 8 < kmax) ? W[(k0 + 8) * ldn + n] : 0.f;
    float e3 = (k0 + 9 < kmax) ? W[(k0 + 9) * ldn + n] : 0.f;
    g_pack[base + idx * 2]     = bf16_pack2(e0, e1);
    g_pack[base + idx * 2 + 1] = bf16_pack2(e2, e3);
}

// ===================== main kernel =====================
__global__ void __launch_bounds__(512, 1)
nerf_mma(const float* __restrict__ rays_o, const float* __restrict__ rays_d,
         const float* __restrict__ b1, const float* __restrict__ b2,
         const float* __restrict__ b3,
         const float* __restrict__ Wc1, const float* __restrict__ bc1,
         const float* __restrict__ Wc2, const float* __restrict__ bc2,
         float* __restrict__ out)
{
    extern __shared__ char smem[];
    const int tid  = threadIdx.x;
    const int lane = tid & 31;
    const int w    = tid >> 5;
    const int mt   = w & 7;
    const int nh   = w >> 3;
    const int la3  = lane & 3;
    const int qk   = la3 * 2;
    const int r0   = mt * 16 + (lane >> 2);
    const int ray  = blockIdx.x;

    const uint32_t sb = smem_u32(smem);
    float* b1s  = (float*)(smem + SM_B1);
    float* b2s  = (float*)(smem + SM_B2);
    float* b3s  = (float*)(smem + SM_B3);
    float* dirs = (float*)(smem + SM_DIR);
    float* comp = (float*)(smem + SM_COMP);
    float* bc2s = (float*)(smem + SM_BC2);
    const uint32_t* Xu  = (const uint32_t*)(smem + SM_X);
    uint32_t* H1u = (uint32_t*)(smem + SM_H1);
    const uint2* P1t = (const uint2*)(smem + SM_P1);
    const uint2* P2t = (const uint2*)(smem + SM_P2);
    const uint2* P3t = (const uint2*)(smem + SM_P3);
    const char* gp = (const char*)g_pack;

    // ---- async weight staging: P1 (g1), P2 (g2), P3 (g3) ----
    {
        uint32_t d1 = sb + SM_P1, d2 = sb + SM_P2, d3 = sb + SM_P3;
        #pragma unroll
        for (int j = 0; j < 4; j++)
            CP16(d1 + (uint32_t)(tid + j * 512) * 16, gp + (tid + j * 512) * 16);
        CP_COMMIT();
        #pragma unroll
        for (int j = 0; j < 16; j++)
            CP16(d2 + (uint32_t)(tid + j * 512) * 16, gp + 32768 + (tid + j * 512) * 16);
        CP_COMMIT();
        CP16(d3 + (uint32_t)tid * 16, gp + 163840 + tid * 16);
        CP_COMMIT();
    }

    // ---- small constants ----
    if (tid < 256) { b1s[tid] = b1[tid]; b2s[tid] = b2[tid]; }
    if (tid < 16) b3s[tid] = b3[tid];
    if (tid < 3)  bc2s[tid] = bc2[tid];

    // ---- ray setup (redundant, all threads) ----
    float ox = rays_o[ray*3+0], oy = rays_o[ray*3+1], oz = rays_o[ray*3+2];
    float rdx = rays_d[ray*3+0], rdy = rays_d[ray*3+1], rdz = rays_d[ray*3+2];
    float inv_norm = 1.0f / sqrtf(rdx*rdx + rdy*rdy + rdz*rdz);
    float dx = rdx*inv_norm, dy = rdy*inv_norm, dz = rdz*inv_norm;
    float near_t, far_t;
    {
        float dd;
        dd = (fabsf(dx) < 1e-8f) ? 1e-8f : dx; float i0 = 1.0f/dd;
        dd = (fabsf(dy) < 1e-8f) ? 1e-8f : dy; float i1 = 1.0f/dd;
        dd = (fabsf(dz) < 1e-8f) ? 1e-8f : dz; float i2 = 1.0f/dd;
        float t0x=(-1.f-ox)*i0, t1x=(1.f-ox)*i0;
        float t0y=(-1.f-oy)*i1, t1y=(1.f-oy)*i1;
        float t0z=(-1.f-oz)*i2, t1z=(1.f-oz)*i2;
        float nx=fminf(t0x,t1x), fx=fmaxf(t0x,t1x);
        float ny=fminf(t0y,t1y), fy=fmaxf(t0y,t1y);
        float nz=fminf(t0z,t1z), fz=fmaxf(t0z,t1z);
        near_t = fmaxf(fmaxf(nx, fmaxf(ny, nz)), 0.02f);
        far_t  = fminf(fmaxf(fx, fmaxf(fy, fz)), 1000.f);
        far_t  = fmaxf(far_t, near_t + 0.001f);
    }
    const float dtv = (far_t - near_t) * (1.0f/128.0f);

    // ---- posenc (4-way split): sample m = tid&127, group g = tid>>7 ----
    {
        const int m = tid & 127, g = tid >> 7;
        float t = near_t + ((float)m + 0.5f) * dtv;
        float px = ox + t*dx, py = oy + t*dy, pz = oz + t*dz;
        const uint32_t xbase = sb + SM_X;
        if (g < 3) {
            float pv = (g == 0) ? px : ((g == 1) ? py : pz);
            float f = 1.f;
            #pragma unroll
            for (int q = 0; q < 10; q++) {
                float s, c;
                sincos_acc(pv * f, &s, &c);
                int j1 = 3 + g*10 + q, j2 = 33 + g*10 + q;
                sts_bf16(xbase + (uint32_t)(((j1 >> 1)*132 + m)*4 + (j1 & 1)*2), s);
                sts_bf16(xbase + (uint32_t)(((j2 >> 1)*132 + m)*4 + (j2 & 1)*2), c);
                f *= 2.f;
            }
        } else {
            // xyz (pairs 0 and 1-lo) + zero pad (pair 31-hi)
            *(uint32_t*)(smem + SM_X + (0*132 + m)*4) = bf16_pack2(px, py);
            sts_bf16(xbase + (uint32_t)((1*132 + m)*4), pz);
            sts_bf16(xbase + (uint32_t)((31*132 + m)*4 + 2), 0.f);
            if (m < 27) {
                int j = m;
                float dv[3] = {dx, dy, dz};
                float v;
                if (j < 3) v = dv[j];
                else if (j < 15) { int jj = j-3;  float s,c; sincos_acc(dv[jj>>2]*(float)(1<<(jj&3)), &s, &c); v = s; }
                else             { int jj = j-15; float s,c; sincos_acc(dv[jj>>2]*(float)(1<<(jj&3)), &s, &c); v = c; }
                dirs[j] = v;
            }
        }
    }

    CP_WAIT(2);            // P1 landed
    __syncthreads();

    // ---------------- Layer 1: acc = X @ W1 (warp: 16 rows x 128-col half) ----
    float acc[16][4];
    #pragma unroll
    for (int i = 0; i < 16; i++)
        #pragma unroll
        for (int j = 0; j < 4; j++) acc[i][j] = 0.f;

    #pragma unroll
    for (int kt = 0; kt < 4; kt++) {
        int pb0 = kt*8 + la3;
        uint32_t a0 = Xu[pb0*132 + r0];
        uint32_t a1 = Xu[pb0*132 + r0 + 8];
        uint32_t a2 = Xu[(pb0+4)*132 + r0];
        uint32_t a3 = Xu[(pb0+4)*132 + r0 + 8];
        #pragma unroll
        for (int i = 0; i < 16; i++) {
            uint2 b = P1t[(kt*32 + nh*16 + i)*32 + lane];
            MMA(acc[i], a0, a1, a2, a3, b.x, b.y);
        }
    }
    CP_WAIT(0);            // P2 + P3 landed
    __syncthreads();       // everyone done reading X / P1

    // epilogue: H1 = relu(acc + b1) -> SMEM bf16 pairs (overwrites P1/X region)
    #pragma unroll
    for (int i = 0; i < 16; i++) {
        int n0 = nh*128 + i*8 + qk;
        float2 bb = *(const float2*)(b1s + n0);
        int kp = nh*64 + i*4 + la3;
        H1u[kp*132 + r0]     = bf16_pack2(fmaxf(acc[i][0] + bb.x, 0.f), fmaxf(acc[i][1] + bb.y, 0.f));
        H1u[kp*132 + r0 + 8] = bf16_pack2(fmaxf(acc[i][2] + bb.x, 0.f), fmaxf(acc[i][3] + bb.y, 0.f));
    }
    __syncthreads();

    // ---------------- Layer 2: acc = H1 @ W2 (16 K-tiles) ----------------
    #pragma unroll
    for (int i = 0; i < 16; i++)
        #pragma unroll
        for (int j = 0; j < 4; j++) acc[i][j] = 0.f;

    #pragma unroll
    for (int kt = 0; kt < 16; kt++) {
        int pb0 = kt*8 + la3;
        uint32_t a0 = H1u[pb0*132 + r0];
        uint32_t a1 = H1u[pb0*132 + r0 + 8];
        uint32_t a2 = H1u[(pb0+4)*132 + r0];
        uint32_t a3 = H1u[(pb0+4)*132 + r0 + 8];
        #pragma unroll
        for (int i = 0; i < 16; i++) {
            uint2 b = P2t[(kt*32 + nh*16 + i)*32 + lane];
            MMA(acc[i], a0, a1, a2, a3, b.x, b.y);
        }
    }
    // epilogue -> H2 A-fragments in regs
    uint32_t h2f[32];
    #pragma unroll
    for (int i = 0; i < 16; i++) {
        int n0 = nh*128 + i*8 + qk;
        float2 bb = *(const float2*)(b2s + n0);
        h2f[2*i]   = bf16_pack2(fmaxf(acc[i][0] + bb.x, 0.f), fmaxf(acc[i][1] + bb.y, 0.f));
        h2f[2*i+1] = bf16_pack2(fmaxf(acc[i][2] + bb.x, 0.f), fmaxf(acc[i][3] + bb.y, 0.f));
    }
    __syncthreads();       // everyone done reading P2

    // kick color-head weight copies into dead P2 region (g4)
    {
        for (int ofs = tid*16; ofs < 10752; ofs += 512*16)
            CP16(sb + SM_WC1 + (uint32_t)ofs, (const char*)Wc1 + ofs);
        if (tid < 48) CP16(sb + SM_WC2 + (uint32_t)tid*16, (const char*)Wc2 + tid*16);
        if (tid < 16) CP16(sb + SM_BC1 + (uint32_t)tid*16, (const char*)bc1 + tid*16);
        CP_COMMIT();
    }

    // ---------------- Layer 3: geo partial (each warp: its K-half) ----------------
    float geo[2][4];
    #pragma unroll
    for (int nt = 0; nt < 2; nt++)
        #pragma unroll
        for (int j = 0; j < 4; j++) geo[nt][j] = 0.f;

    #pragma unroll
    for (int ii = 0; ii < 8; ii++) {
        int kt3 = nh*8 + ii;
        uint32_t a0 = h2f[4*ii], a1 = h2f[4*ii+1], a2 = h2f[4*ii+2], a3 = h2f[4*ii+3];
        #pragma unroll
        for (int nt = 0; nt < 2; nt++) {
            uint2 b = P3t[(kt3*2 + nt)*32 + lane];
            MMA(geo[nt], a0, a1, a2, a3, b.x, b.y);
        }
    }
    // N-half reduction via SMEM
    if (nh == 1) {
        float* red = (float*)(smem + SM_RED) + (tid - 256)*8;
        #pragma unroll
        for (int nt = 0; nt < 2; nt++)
            #pragma unroll
            for (int j = 0; j < 4; j++) red[nt*4 + j] = geo[nt][j];
    }
    __syncthreads();
    if (nh == 0) {
        float* red = (float*)(smem + SM_RED) + tid*8;
        float* geos = (float*)(smem + SM_GEOS);
        #pragma unroll
        for (int nt = 0; nt < 2; nt++) {
            int c = nt*8 + qk;
            geos[r0*16 + c]       = geo[nt][0] + red[nt*4+0];
            geos[r0*16 + c + 1]   = geo[nt][1] + red[nt*4+1];
            geos[(r0+8)*16 + c]   = geo[nt][2] + red[nt*4+2];
            geos[(r0+8)*16 + c+1] = geo[nt][3] + red[nt*4+3];
        }
    }
    CP_WAIT(0);
    __syncthreads();

    // ---------------- color head (4-way split over j) ----------------
    {
        const float* wc1s = (const float*)(smem + SM_WC1);
        const float* wc2s = (const float*)(smem + SM_WC2);
        const float* bc1s = (const float*)(smem + SM_BC1);
        const float* geos = (const float*)(smem + SM_GEOS);
        float* cpart = (float*)(smem + SM_CPART);
        const int m = tid & 127, g = tid >> 7;
        float inp[42];
        #pragma unroll
        for (int i = 0; i < 27; i++) inp[i] = dirs[i];
        #pragma unroll
        for (int i = 0; i < 15; i++) inp[27+i] = geos[m*16 + 1 + i] + b3s[1 + i];
        float a0 = 0.f, a1 = 0.f, a2 = 0.f;
        const int j0 = g * 16;
        for (int j = j0; j < j0 + 16; j++) {
            float h = bc1s[j];
            #pragma unroll
            for (int i = 0; i < 42; i++)
                h = fmaf(inp[i], wc1s[i*64 + j], h);
            h = fmaxf(h, 0.f);
            a0 = fmaf(h, wc2s[j*3+0], a0);
            a1 = fmaf(h, wc2s[j*3+1], a1);
            a2 = fmaf(h, wc2s[j*3+2], a2);
        }
        if (g > 0) {
            float* cp = cpart + ((g-1)*128 + m)*4;
            cp[0] = a0; cp[1] = a1; cp[2] = a2;
        }
        __syncthreads();
        if (g == 0) {
            #pragma unroll
            for (int gg = 0; gg < 3; gg++) {
                const float* cp = cpart + (gg*128 + m)*4;
                a0 += cp[0]; a1 += cp[1]; a2 += cp[2];
            }
            a0 += bc2s[0]; a1 += bc2s[1]; a2 += bc2s[2];
            float sx = geos[m*16] + b3s[0];
            float sigma = (sx > 20.f) ? sx : log1pf(expf(sx));
            float alpha = 1.f - expf(-sigma * dtv);
            comp[m*4+0] = alpha;
            comp[m*4+1] = 1.f / (1.f + expf(-a0));
            comp[m*4+2] = 1.f / (1.f + expf(-a1));
            comp[m*4+3] = 1.f / (1.f + expf(-a2));
        }
    }
    __syncthreads();

    // ---------------- composite: warp-0 parallel scan ----------------
    if (tid < 32) {
        float av[4];
        #pragma unroll
        for (int j = 0; j < 4; j++) av[j] = comp[(lane*4 + j)*4 + 0];
        float q0 = 1.f - av[0] + 1e-10f;
        float q1 = 1.f - av[1] + 1e-10f;
        float q2 = 1.f - av[2] + 1e-10f;
        float q3 = 1.f - av[3] + 1e-10f;
        float inc = ((q0*q1)*(q2*q3));
        #pragma unroll
        for (int off = 1; off < 32; off <<= 1) {
            float t = __shfl_up_sync(0xFFFFFFFF, inc, off);
            if (lane >= off) inc *= t;
        }
        float T = __shfl_up_sync(0xFFFFFFFF, inc, 1);
        if (lane == 0) T = 1.f;
        float wsum = 0.f, dsum = 0.f, r = 0.f, g = 0.f, b = 0.f;
        #pragma unroll
        for (int j = 0; j < 4; j++) {
            int m = lane*4 + j;
            float alpha = av[j];
            float wgt = (T > 1e-4f) ? alpha * T : 0.f;
            wsum += wgt;
            float tsv = near_t + ((float)m + 0.5f) * dtv;
            dsum = fmaf(wgt, tsv, dsum);
            r = fmaf(wgt, comp[m*4+1], r);
            g = fmaf(wgt, comp[m*4+2], g);
            b = fmaf(wgt, comp[m*4+3], b);
            T *= (1.f - alpha + 1e-10f);
        }
        #pragma unroll
        for (int off = 16; off > 0; off >>= 1) {
            wsum += __shfl_xor_sync(0xFFFFFFFF, wsum, off);
            dsum += __shfl_xor_sync(0xFFFFFFFF, dsum, off);
            r    += __shfl_xor_sync(0xFFFFFFFF, r, off);
            g    += __shfl_xor_sync(0xFFFFFFFF, g, off);
            b    += __shfl_xor_sync(0xFFFFFFFF, b, off);
        }
        if (lane == 0) {
            float bgw = 1.f - wsum;
            out[ray*3+0] = r + bgw;
            out[ray*3+1] = g + bgw;
            out[ray*3+2] = b + bgw;
            out[4096*3 + ray] = dsum;
            out[4096*4 + ray] = fminf(fmaxf(wsum, 1e-12f), 1000.f);
        }
    }
}

// ===================== launch =====================
extern "C" void kernel_launch(void* const* d_in, const int* in_sizes, int n_in,
                              void* d_out, int out_size) {
    const float* rays_o = (const float*)d_in[0];
    const float* rays_d = (const float*)d_in[1];
    const float* W1  = (const float*)d_in[2];
    const float* b1  = (const float*)d_in[3];
    const float* W2  = (const float*)d_in[4];
    const float* b2  = (const float*)d_in[5];
    const float* W3  = (const float*)d_in[6];
    const float* b3  = (const float*)d_in[7];
    const float* Wc1 = (const float*)d_in[8];
    const float* bc1 = (const float*)d_in[9];
    const float* Wc2 = (const float*)d_in[10];
    const float* bc2 = (const float*)d_in[11];
    float* out = (float*)d_out;

    prep_pack<<<84, 256>>>(W1, W2, W3);
    cudaFuncSetAttribute(nerf_mma, cudaFuncAttributeMaxDynamicSharedMemorySize, SMEM_BYTES);
    nerf_mma<<<4096, 512, SMEM_BYTES>>>(rays_o, rays_d, b1, b2, b3,
                                        Wc1, bc1, Wc2, bc2, out);
}

// round 7
// speedup vs baseline: 4.9598x; 1.0123x over previous
#include <cuda_runtime.h>
#include <cuda_bf16.h>
#include <math.h>
#include <stdint.h>

// ===================== asm helpers =====================
__device__ __forceinline__ uint32_t smem_u32(const void* p) {
    uint32_t a;
    asm("{ .reg .u64 t; cvta.to.shared.u64 t, %1; cvt.u32.u64 %0, t; }" : "=r"(a) : "l"(p));
    return a;
}
#define CP16(dst_u32, src_ptr) \
    asm volatile("cp.async.cg.shared.global [%0], [%1], 16;" :: "r"(dst_u32), "l"(src_ptr) : "memory")
#define CP_COMMIT() asm volatile("cp.async.commit_group;" ::: "memory")
#define CP_WAIT(n)  asm volatile("cp.async.wait_group %0;" :: "n"(n) : "memory")

#define MMA(d, a0, a1, a2, a3, b0, b1) \
    asm("mma.sync.aligned.m16n8k16.row.col.f32.bf16.bf16.f32 " \
        "{%0,%1,%2,%3}, {%4,%5,%6,%7}, {%8,%9}, {%0,%1,%2,%3};" \
        : "+f"((d)[0]), "+f"((d)[1]), "+f"((d)[2]), "+f"((d)[3]) \
        : "r"(a0), "r"(a1), "r"(a2), "r"(a3), "r"(b0), "r"(b1))

// ===================== smem layout =====================
#define SM_P2    0          // 131072   W2 fragments
#define SM_P3    131072     // 8192     W3 fragments
#define SM_H1    139264     // 67584    H1 bf16 pairs [128][132] u32 (phase 2)
#define SM_P1    139264     //   phase 1 alias: W1 fragments (32768)
#define SM_X     172032     //   phase 1 alias: posenc X bf16 pairs [32][132] u32
#define SM_B1    206848     // 1024
#define SM_B2    207872     // 1024
#define SM_B3    208896     // 64
#define SM_DIR   208960     // 128
#define SM_COMP  209088     // 2048
#define SM_BC2   211136     // 16
#define SMEM_BYTES 211152
// aliases inside dead P2 region (valid after layer-2 MMAs):
#define SM_WC1   0          // 10752
#define SM_WC2   10752      // 768
#define SM_BC1   11520      // 256
#define SM_CPART 12288      // 6144  (3 groups x 128 x 4 floats)
#define SM_GEOS  18432      // 8192  [128][16] fp32
#define SM_RED   32768      // 24576 (3 groups x 128 x 16 fp32) layer-3 partials

// packed weight image (bf16 fragment order): P1 32KB | P2 128KB | P3 8KB
__device__ __align__(128) uint32_t g_pack[43008];

__device__ __forceinline__ uint32_t bf16_pack2(float x, float y) {
    __nv_bfloat16 hx = __float2bfloat16(x), hy = __float2bfloat16(y);
    return (uint32_t)__bfloat16_as_ushort(hx) | ((uint32_t)__bfloat16_as_ushort(hy) << 16);
}
__device__ __forceinline__ void sts_bf16(uint32_t addr, float v) {
    uint16_t u = __bfloat16_as_ushort(__float2bfloat16(v));
    asm volatile("st.shared.u16 [%0], %1;" :: "r"(addr), "h"(u));
}
__device__ __forceinline__ void sincos_acc(float phi, float* s, float* c) {
    float k = rintf(phi * 0.15915494309f);
    float r = fmaf(-k, 6.2831854820251465f, phi);
    r = fmaf(-k, -1.7484556000744263e-07f, r);
    sincosf(r, s, c);
}

// ===================== prep: pack weights into per-lane fragment order =====================
__global__ void prep_pack(const float* __restrict__ W1, const float* __restrict__ W2,
                          const float* __restrict__ W3) {
    int s = blockIdx.x * 256 + threadIdx.x;
    if (s >= 21504) return;
    int lane = s & 31;
    int qn = lane >> 2, qk = (lane & 3) * 2;
    const float* W; int kbase, n, ldn, kmax; uint32_t base, idx;
    if (s < 4096) {                       // P1: 4 kt x 32 nt
        int t = s >> 5;
        kbase = (t >> 5) * 16; n = (t & 31) * 8 + qn; W = W1; ldn = 256; kmax = 63;
        base = 0; idx = (uint32_t)s;
    } else if (s < 20480) {               // P2: 16 kt x 32 nt
        int t = (s - 4096) >> 5;
        kbase = (t >> 5) * 16; n = (t & 31) * 8 + qn; W = W2; ldn = 256; kmax = 256;
        base = 8192; idx = (uint32_t)(s - 4096);
    } else {                              // P3: 16 kt x 2 nt
        int t = (s - 20480) >> 5;
        kbase = (t >> 1) * 16; n = (t & 1) * 8 + qn; W = W3; ldn = 16; kmax = 256;
        base = 40960; idx = (uint32_t)(s - 20480);
    }
    int k0 = kbase + qk;
    float e0 = (k0     < kmax) ? W[(k0)     * ldn + n] : 0.f;
    float e1 = (k0 + 1 < kmax) ? W[(k0 + 1) * ldn + n] : 0.f;
    float e2 = (k0 + 8 < kmax) ? W[(k0 + 8) * ldn + n] : 0.f;
    float e3 = (k0 + 9 < kmax) ? W[(k0 + 9) * ldn + n] : 0.f;
    g_pack[base + idx * 2]     = bf16_pack2(e0, e1);
    g_pack[base + idx * 2 + 1] = bf16_pack2(e2, e3);
}

// ===================== main kernel =====================
__global__ void __launch_bounds__(512, 1)
nerf_mma(const float* __restrict__ rays_o, const float* __restrict__ rays_d,
         const float* __restrict__ b1, const float* __restrict__ b2,
         const float* __restrict__ b3,
         const float* __restrict__ Wc1, const float* __restrict__ bc1,
         const float* __restrict__ Wc2, const float* __restrict__ bc2,
         float* __restrict__ out)
{
    extern __shared__ char smem[];
    const int tid  = threadIdx.x;
    const int lane = tid & 31;
    const int w    = tid >> 5;
    const int mt   = w & 3;               // M-tile (32 rows)
    const int nq   = w >> 2;              // N-quarter (64 cols)
    const int la3  = lane & 3;
    const int qk   = la3 * 2;
    const int r0   = mt * 32 + (lane >> 2);
    const int ray  = blockIdx.x;

    const uint32_t sb = smem_u32(smem);
    float* b1s  = (float*)(smem + SM_B1);
    float* b2s  = (float*)(smem + SM_B2);
    float* b3s  = (float*)(smem + SM_B3);
    float* dirs = (float*)(smem + SM_DIR);
    float* comp = (float*)(smem + SM_COMP);
    float* bc2s = (float*)(smem + SM_BC2);
    const uint32_t* Xu  = (const uint32_t*)(smem + SM_X);
    uint32_t* H1u = (uint32_t*)(smem + SM_H1);
    const uint2* P1t = (const uint2*)(smem + SM_P1);
    const uint2* P2t = (const uint2*)(smem + SM_P2);
    const uint2* P3t = (const uint2*)(smem + SM_P3);
    const char* gp = (const char*)g_pack;

    // ---- async weight staging: P1 (g1), P2 (g2), P3 (g3) ----
    {
        uint32_t d1 = sb + SM_P1, d2 = sb + SM_P2, d3 = sb + SM_P3;
        #pragma unroll
        for (int j = 0; j < 4; j++)
            CP16(d1 + (uint32_t)(tid + j * 512) * 16, gp + (tid + j * 512) * 16);
        CP_COMMIT();
        #pragma unroll
        for (int j = 0; j < 16; j++)
            CP16(d2 + (uint32_t)(tid + j * 512) * 16, gp + 32768 + (tid + j * 512) * 16);
        CP_COMMIT();
        CP16(d3 + (uint32_t)tid * 16, gp + 163840 + tid * 16);
        CP_COMMIT();
    }

    // ---- small constants ----
    if (tid < 256) { b1s[tid] = b1[tid]; b2s[tid] = b2[tid]; }
    if (tid < 16) b3s[tid] = b3[tid];
    if (tid < 3)  bc2s[tid] = bc2[tid];

    // ---- ray setup ----
    float ox = rays_o[ray*3+0], oy = rays_o[ray*3+1], oz = rays_o[ray*3+2];
    float rdx = rays_d[ray*3+0], rdy = rays_d[ray*3+1], rdz = rays_d[ray*3+2];
    float inv_norm = 1.0f / sqrtf(rdx*rdx + rdy*rdy + rdz*rdz);
    float dx = rdx*inv_norm, dy = rdy*inv_norm, dz = rdz*inv_norm;
    float near_t, far_t;
    {
        float dd;
        dd = (fabsf(dx) < 1e-8f) ? 1e-8f : dx; float i0 = 1.0f/dd;
        dd = (fabsf(dy) < 1e-8f) ? 1e-8f : dy; float i1 = 1.0f/dd;
        dd = (fabsf(dz) < 1e-8f) ? 1e-8f : dz; float i2 = 1.0f/dd;
        float t0x=(-1.f-ox)*i0, t1x=(1.f-ox)*i0;
        float t0y=(-1.f-oy)*i1, t1y=(1.f-oy)*i1;
        float t0z=(-1.f-oz)*i2, t1z=(1.f-oz)*i2;
        float nx=fminf(t0x,t1x), fx=fmaxf(t0x,t1x);
        float ny=fminf(t0y,t1y), fy=fmaxf(t0y,t1y);
        float nz=fminf(t0z,t1z), fz=fmaxf(t0z,t1z);
        near_t = fmaxf(fmaxf(nx, fmaxf(ny, nz)), 0.02f);
        far_t  = fminf(fmaxf(fx, fmaxf(fy, fz)), 1000.f);
        far_t  = fmaxf(far_t, near_t + 0.001f);
    }
    const float dtv = (far_t - near_t) * (1.0f/128.0f);

    // ---- posenc (4-way split) ----
    {
        const int m = tid & 127, g = tid >> 7;
        float t = near_t + ((float)m + 0.5f) * dtv;
        float px = ox + t*dx, py = oy + t*dy, pz = oz + t*dz;
        const uint32_t xbase = sb + SM_X;
        if (g < 3) {
            float pv = (g == 0) ? px : ((g == 1) ? py : pz);
            float f = 1.f;
            #pragma unroll
            for (int q = 0; q < 10; q++) {
                float s, c;
                sincos_acc(pv * f, &s, &c);
                int j1 = 3 + g*10 + q, j2 = 33 + g*10 + q;
                sts_bf16(xbase + (uint32_t)(((j1 >> 1)*132 + m)*4 + (j1 & 1)*2), s);
                sts_bf16(xbase + (uint32_t)(((j2 >> 1)*132 + m)*4 + (j2 & 1)*2), c);
                f *= 2.f;
            }
        } else {
            *(uint32_t*)(smem + SM_X + (0*132 + m)*4) = bf16_pack2(px, py);
            sts_bf16(xbase + (uint32_t)((1*132 + m)*4), pz);
            sts_bf16(xbase + (uint32_t)((31*132 + m)*4 + 2), 0.f);
            if (m < 27) {
                int j = m;
                float dv[3] = {dx, dy, dz};
                float v;
                if (j < 3) v = dv[j];
                else if (j < 15) { int jj = j-3;  float s,c; sincos_acc(dv[jj>>2]*(float)(1<<(jj&3)), &s, &c); v = s; }
                else             { int jj = j-15; float s,c; sincos_acc(dv[jj>>2]*(float)(1<<(jj&3)), &s, &c); v = c; }
                dirs[j] = v;
            }
        }
    }

    CP_WAIT(2);            // P1 landed
    __syncthreads();

    // ---------------- Layer 1: warp = 32 rows x 64 cols ----------------
    float acc[2][8][4];
    #pragma unroll
    for (int rb = 0; rb < 2; rb++)
        #pragma unroll
        for (int ct = 0; ct < 8; ct++)
            #pragma unroll
            for (int j = 0; j < 4; j++) acc[rb][ct][j] = 0.f;

    #pragma unroll
    for (int kt = 0; kt < 4; kt++) {
        int pb0 = kt*8 + la3;
        uint32_t af[2][4];
        #pragma unroll
        for (int rb = 0; rb < 2; rb++) {
            int rr = r0 + rb*16;
            af[rb][0] = Xu[pb0*132 + rr];
            af[rb][1] = Xu[pb0*132 + rr + 8];
            af[rb][2] = Xu[(pb0+4)*132 + rr];
            af[rb][3] = Xu[(pb0+4)*132 + rr + 8];
        }
        #pragma unroll
        for (int ct = 0; ct < 8; ct++) {
            uint2 b = P1t[(kt*32 + nq*8 + ct)*32 + lane];
            #pragma unroll
            for (int rb = 0; rb < 2; rb++)
                MMA(acc[rb][ct], af[rb][0], af[rb][1], af[rb][2], af[rb][3], b.x, b.y);
        }
    }
    CP_WAIT(0);            // P2 + P3 landed
    __syncthreads();       // everyone done reading X / P1

    // epilogue: H1 = relu(acc + b1) -> SMEM bf16 pairs (overwrites P1/X region)
    #pragma unroll
    for (int ct = 0; ct < 8; ct++) {
        int n0 = nq*64 + ct*8 + qk;
        float2 bb = *(const float2*)(b1s + n0);
        int kp = nq*32 + ct*4 + la3;
        #pragma unroll
        for (int rb = 0; rb < 2; rb++) {
            int rr = r0 + rb*16;
            H1u[kp*132 + rr]     = bf16_pack2(fmaxf(acc[rb][ct][0] + bb.x, 0.f), fmaxf(acc[rb][ct][1] + bb.y, 0.f));
            H1u[kp*132 + rr + 8] = bf16_pack2(fmaxf(acc[rb][ct][2] + bb.x, 0.f), fmaxf(acc[rb][ct][3] + bb.y, 0.f));
        }
    }
    __syncthreads();

    // ---------------- Layer 2: 16 K-tiles ----------------
    #pragma unroll
    for (int rb = 0; rb < 2; rb++)
        #pragma unroll
        for (int ct = 0; ct < 8; ct++)
            #pragma unroll
            for (int j = 0; j < 4; j++) acc[rb][ct][j] = 0.f;

    #pragma unroll
    for (int kt = 0; kt < 16; kt++) {
        int pb0 = kt*8 + la3;
        uint32_t af[2][4];
        #pragma unroll
        for (int rb = 0; rb < 2; rb++) {
            int rr = r0 + rb*16;
            af[rb][0] = H1u[pb0*132 + rr];
            af[rb][1] = H1u[pb0*132 + rr + 8];
            af[rb][2] = H1u[(pb0+4)*132 + rr];
            af[rb][3] = H1u[(pb0+4)*132 + rr + 8];
        }
        #pragma unroll
        for (int ct = 0; ct < 8; ct++) {
            uint2 b = P2t[(kt*32 + nq*8 + ct)*32 + lane];
            #pragma unroll
            for (int rb = 0; rb < 2; rb++)
                MMA(acc[rb][ct], af[rb][0], af[rb][1], af[rb][2], af[rb][3], b.x, b.y);
        }
    }
    __syncthreads();       // everyone done reading P2

    // kick color-head weight copies into dead P2 region (g4)
    {
        for (int ofs = tid*16; ofs < 10752; ofs += 512*16)
            CP16(sb + SM_WC1 + (uint32_t)ofs, (const char*)Wc1 + ofs);
        if (tid < 48) CP16(sb + SM_WC2 + (uint32_t)tid*16, (const char*)Wc2 + tid*16);
        if (tid < 16) CP16(sb + SM_BC1 + (uint32_t)tid*16, (const char*)bc1 + tid*16);
        CP_COMMIT();
    }

    // ---------------- Layer 3: warp handles K-range nq*64..+64 of its 32 rows ---
    float geo[2][2][4];    // [rb][nt]
    #pragma unroll
    for (int rb = 0; rb < 2; rb++)
        #pragma unroll
        for (int nt = 0; nt < 2; nt++)
            #pragma unroll
            for (int j = 0; j < 4; j++) geo[rb][nt][j] = 0.f;

    #pragma unroll
    for (int ii = 0; ii < 4; ii++) {
        int kt3 = nq*4 + ii;
        uint2 bq[2];
        bq[0] = P3t[(kt3*2 + 0)*32 + lane];
        bq[1] = P3t[(kt3*2 + 1)*32 + lane];
        int n0 = nq*64 + (2*ii)*8 + qk;
        float2 bb0 = *(const float2*)(b2s + n0);
        float2 bb1 = *(const float2*)(b2s + n0 + 8);
        #pragma unroll
        for (int rb = 0; rb < 2; rb++) {
            uint32_t a0 = bf16_pack2(fmaxf(acc[rb][2*ii][0] + bb0.x, 0.f),  fmaxf(acc[rb][2*ii][1] + bb0.y, 0.f));
            uint32_t a1 = bf16_pack2(fmaxf(acc[rb][2*ii][2] + bb0.x, 0.f),  fmaxf(acc[rb][2*ii][3] + bb0.y, 0.f));
            uint32_t a2 = bf16_pack2(fmaxf(acc[rb][2*ii+1][0] + bb1.x, 0.f), fmaxf(acc[rb][2*ii+1][1] + bb1.y, 0.f));
            uint32_t a3 = bf16_pack2(fmaxf(acc[rb][2*ii+1][2] + bb1.x, 0.f), fmaxf(acc[rb][2*ii+1][3] + bb1.y, 0.f));
            MMA(geo[rb][0], a0, a1, a2, a3, bq[0].x, bq[0].y);
            MMA(geo[rb][1], a0, a1, a2, a3, bq[1].x, bq[1].y);
        }
    }

    // 4-way K reduction via SMEM (dead P2 region)
    if (nq > 0) {
        float* red = (float*)(smem + SM_RED) + (nq - 1) * 2048;
        #pragma unroll
        for (int rb = 0; rb < 2; rb++)
            #pragma unroll
            for (int nt = 0; nt < 2; nt++) {
                int c = nt*8 + qk;
                int rr = r0 + rb*16;
                red[rr*16 + c]       = geo[rb][nt][0];
                red[rr*16 + c + 1]   = geo[rb][nt][1];
                red[(rr+8)*16 + c]   = geo[rb][nt][2];
                red[(rr+8)*16 + c+1] = geo[rb][nt][3];
            }
    }
    __syncthreads();
    if (nq == 0) {
        float* red  = (float*)(smem + SM_RED);
        float* geos = (float*)(smem + SM_GEOS);
        #pragma unroll
        for (int rb = 0; rb < 2; rb++)
            #pragma unroll
            for (int nt = 0; nt < 2; nt++) {
                int c = nt*8 + qk;
                int rr = r0 + rb*16;
                geos[rr*16 + c]       = geo[rb][nt][0] + red[rr*16+c]        + red[2048 + rr*16+c]        + red[4096 + rr*16+c];
                geos[rr*16 + c + 1]   = geo[rb][nt][1] + red[rr*16+c+1]      + red[2048 + rr*16+c+1]      + red[4096 + rr*16+c+1];
                geos[(rr+8)*16 + c]   = geo[rb][nt][2] + red[(rr+8)*16+c]    + red[2048 + (rr+8)*16+c]    + red[4096 + (rr+8)*16+c];
                geos[(rr+8)*16 + c+1] = geo[rb][nt][3] + red[(rr+8)*16+c+1]  + red[2048 + (rr+8)*16+c+1]  + red[4096 + (rr+8)*16+c+1];
            }
    }
    CP_WAIT(0);
    __syncthreads();

    // ---------------- color head (4-way split over j) ----------------
    {
        const float* wc1s = (const float*)(smem + SM_WC1);
        const float* wc2s = (const float*)(smem + SM_WC2);
        const float* bc1s = (const float*)(smem + SM_BC1);
        const float* geos = (const float*)(smem + SM_GEOS);
        float* cpart = (float*)(smem + SM_CPART);
        const int m = tid & 127, g = tid >> 7;
        float inp[42];
        #pragma unroll
        for (int i = 0; i < 27; i++) inp[i] = dirs[i];
        #pragma unroll
        for (int i = 0; i < 15; i++) inp[27+i] = geos[m*16 + 1 + i] + b3s[1 + i];
        float a0 = 0.f, a1 = 0.f, a2 = 0.f;
        const int j0 = g * 16;
        for (int j = j0; j < j0 + 16; j++) {
            float h = bc1s[j];
            #pragma unroll
            for (int i = 0; i < 42; i++)
                h = fmaf(inp[i], wc1s[i*64 + j], h);
            h = fmaxf(h, 0.f);
            a0 = fmaf(h, wc2s[j*3+0], a0);
            a1 = fmaf(h, wc2s[j*3+1], a1);
            a2 = fmaf(h, wc2s[j*3+2], a2);
        }
        if (g > 0) {
            float* cp = cpart + ((g-1)*128 + m)*4;
            cp[0] = a0; cp[1] = a1; cp[2] = a2;
        }
        __syncthreads();
        if (g == 0) {
            #pragma unroll
            for (int gg = 0; gg < 3; gg++) {
                const float* cp = cpart + (gg*128 + m)*4;
                a0 += cp[0]; a1 += cp[1]; a2 += cp[2];
            }
            a0 += bc2s[0]; a1 += bc2s[1]; a2 += bc2s[2];
            float sx = geos[m*16] + b3s[0];
            float sigma = (sx > 20.f) ? sx : log1pf(expf(sx));
            float alpha = 1.f - expf(-sigma * dtv);
            comp[m*4+0] = alpha;
            comp[m*4+1] = 1.f / (1.f + expf(-a0));
            comp[m*4+2] = 1.f / (1.f + expf(-a1));
            comp[m*4+3] = 1.f / (1.f + expf(-a2));
        }
    }
    __syncthreads();

    // ---------------- composite: warp-0 parallel scan ----------------
    if (tid < 32) {
        float av[4];
        #pragma unroll
        for (int j = 0; j < 4; j++) av[j] = comp[(lane*4 + j)*4 + 0];
        float q0 = 1.f - av[0] + 1e-10f;
        float q1 = 1.f - av[1] + 1e-10f;
        float q2 = 1.f - av[2] + 1e-10f;
        float q3 = 1.f - av[3] + 1e-10f;
        float inc = ((q0*q1)*(q2*q3));
        #pragma unroll
        for (int off = 1; off < 32; off <<= 1) {
            float t = __shfl_up_sync(0xFFFFFFFF, inc, off);
            if (lane >= off) inc *= t;
        }
        float T = __shfl_up_sync(0xFFFFFFFF, inc, 1);
        if (lane == 0) T = 1.f;
        float wsum = 0.f, dsum = 0.f, r = 0.f, g = 0.f, b = 0.f;
        #pragma unroll
        for (int j = 0; j < 4; j++) {
            int m = lane*4 + j;
            float alpha = av[j];
            float wgt = (T > 1e-4f) ? alpha * T : 0.f;
            wsum += wgt;
            float tsv = near_t + ((float)m + 0.5f) * dtv;
            dsum = fmaf(wgt, tsv, dsum);
            r = fmaf(wgt, comp[m*4+1], r);
            g = fmaf(wgt, comp[m*4+2], g);
            b = fmaf(wgt, comp[m*4+3], b);
            T *= (1.f - alpha + 1e-10f);
        }
        #pragma unroll
        for (int off = 16; off > 0; off >>= 1) {
            wsum += __shfl_xor_sync(0xFFFFFFFF, wsum, off);
            dsum += __shfl_xor_sync(0xFFFFFFFF, dsum, off);
            r    += __shfl_xor_sync(0xFFFFFFFF, r, off);
            g    += __shfl_xor_sync(0xFFFFFFFF, g, off);
            b    += __shfl_xor_sync(0xFFFFFFFF, b, off);
        }
        if (lane == 0) {
            float bgw = 1.f - wsum;
            out[ray*3+0] = r + bgw;
            out[ray*3+1] = g + bgw;
            out[ray*3+2] = b + bgw;
            out[4096*3 + ray] = dsum;
            out[4096*4 + ray] = fminf(fmaxf(wsum, 1e-12f), 1000.f);
        }
    }
}

// ===================== launch =====================
extern "C" void kernel_launch(void* const* d_in, const int* in_sizes, int n_in,
                              void* d_out, int out_size) {
    const float* rays_o = (const float*)d_in[0];
    const float* rays_d = (const float*)d_in[1];
    const float* W1  = (const float*)d_in[2];
    const float* b1  = (const float*)d_in[3];
    const float* W2  = (const float*)d_in[4];
    const float* b2  = (const float*)d_in[5];
    const float* W3  = (const float*)d_in[6];
    const float* b3  = (const float*)d_in[7];
    const float* Wc1 = (const float*)d_in[8];
    const float* bc1 = (const float*)d_in[9];
    const float* Wc2 = (const float*)d_in[10];
    const float* bc2 = (const float*)d_in[11];
    float* out = (float*)d_out;

    prep_pack<<<84, 256>>>(W1, W2, W3);
    cudaFuncSetAttribute(nerf_mma, cudaFuncAttributeMaxDynamicSharedMemorySize, SMEM_BYTES);
    nerf_mma<<<4096, 512, SMEM_BYTES>>>(rays_o, rays_d, b1, b2, b3,
                                        Wc1, bc1, Wc2, bc2, out);
}

// round 8
// speedup vs baseline: 4.9884x; 1.0058x over previous
#include <cuda_runtime.h>
#include <cuda_bf16.h>
#include <math.h>
#include <stdint.h>

// ===================== asm helpers =====================
__device__ __forceinline__ uint32_t smem_u32(const void* p) {
    uint32_t a;
    asm("{ .reg .u64 t; cvta.to.shared.u64 t, %1; cvt.u32.u64 %0, t; }" : "=r"(a) : "l"(p));
    return a;
}
#define CP16(dst_u32, src_ptr) \
    asm volatile("cp.async.cg.shared.global [%0], [%1], 16;" :: "r"(dst_u32), "l"(src_ptr) : "memory")
#define CP_COMMIT() asm volatile("cp.async.commit_group;" ::: "memory")
#define CP_WAIT(n)  asm volatile("cp.async.wait_group %0;" :: "n"(n) : "memory")

#define MMA(d, a0, a1, a2, a3, b0, b1) \
    asm("mma.sync.aligned.m16n8k16.row.col.f32.bf16.bf16.f32 " \
        "{%0,%1,%2,%3}, {%4,%5,%6,%7}, {%8,%9}, {%0,%1,%2,%3};" \
        : "+f"((d)[0]), "+f"((d)[1]), "+f"((d)[2]), "+f"((d)[3]) \
        : "r"(a0), "r"(a1), "r"(a2), "r"(a3), "r"(b0), "r"(b1))

// stride (in u32) for X / H1 pair arrays: 136 -> bank = 8*la3 + q, conflict-free
#define XS 136

// ===================== smem layout =====================
#define SM_P2    0          // 131072   W2 fragments (uint4-paired)
#define SM_P3    131072     // 8192     W3 fragments (uint4-paired)
#define SM_H1    139264     // 69632    H1 bf16 pairs [128][136] u32 (phase 2)
#define SM_P1    139264     //   phase 1 alias: W1 fragments (32768)
#define SM_X     172032     //   phase 1 alias: posenc X bf16 pairs [32][136] u32 (17408)
#define SM_B1    208896     // 1024
#define SM_B2    209920     // 1024
#define SM_B3    210944     // 64
#define SM_DIR   211008     // 128
#define SM_COMP  211136     // 2048
#define SM_BC2   213184     // 16
#define SMEM_BYTES 213200
// aliases inside dead P2 region (valid after layer-2 MMAs):
#define SM_WC1   0          // 10752
#define SM_WC2   10752      // 768
#define SM_BC1   11520      // 256
#define SM_CPART 12288      // 6144  (3 groups x 128 x 4 floats)
#define SM_GEOS  18432      // 8192  [128][16] fp32
#define SM_RED   32768      // 24576 (3 groups x 128 x 16 fp32) layer-3 partials

// packed weight image (bf16 fragment order, uint4-paired): P1 32KB | P2 128KB | P3 8KB
__device__ __align__(128) uint32_t g_pack[43008];

__device__ __forceinline__ uint32_t bf16_pack2(float x, float y) {
    __nv_bfloat16 hx = __float2bfloat16(x), hy = __float2bfloat16(y);
    return (uint32_t)__bfloat16_as_ushort(hx) | ((uint32_t)__bfloat16_as_ushort(hy) << 16);
}
__device__ __forceinline__ void sts_bf16(uint32_t addr, float v) {
    uint16_t u = __bfloat16_as_ushort(__float2bfloat16(v));
    asm volatile("st.shared.u16 [%0], %1;" :: "r"(addr), "h"(u));
}
__device__ __forceinline__ void sincos_acc(float phi, float* s, float* c) {
    float k = rintf(phi * 0.15915494309f);
    float r = fmaf(-k, 6.2831854820251465f, phi);
    r = fmaf(-k, -1.7484556000744263e-07f, r);
    sincosf(r, s, c);
}

// ===================== prep: pack weights, N-tile pairs contiguous per lane ==
// For tile (kt, nt): lane's uint2 = {pack(W[k0,n],W[k0+1,n]), pack(W[k0+8,n],W[k0+9,n])}
// stored at u32 offset ((kt*ntp + (nt>>1))*32 + lane)*4 + (nt&1)*2  -> uint4 per pair
__global__ void prep_pack(const float* __restrict__ W1, const float* __restrict__ W2,
                          const float* __restrict__ W3) {
    int s = blockIdx.x * 256 + threadIdx.x;
    if (s >= 21504) return;
    int lane = s & 31;
    int qn = lane >> 2, qk = (lane & 3) * 2;
    const float* W; int kbase, n, ldn, kmax; uint32_t base, idx;
    if (s < 4096) {                       // P1: 4 kt x 32 nt (16 pairs)
        int t = s >> 5;
        int kt = t >> 5, nt = t & 31;
        kbase = kt * 16; n = nt * 8 + qn; W = W1; ldn = 256; kmax = 63;
        base = 0; idx = (uint32_t)(((kt * 16 + (nt >> 1)) * 32 + lane) * 4 + (nt & 1) * 2);
    } else if (s < 20480) {               // P2: 16 kt x 32 nt (16 pairs)
        int t = (s - 4096) >> 5;
        int kt = t >> 5, nt = t & 31;
        kbase = kt * 16; n = nt * 8 + qn; W = W2; ldn = 256; kmax = 256;
        base = 8192; idx = (uint32_t)(((kt * 16 + (nt >> 1)) * 32 + lane) * 4 + (nt & 1) * 2);
    } else {                              // P3: 16 kt x 2 nt (1 pair)
        int t = (s - 20480) >> 5;
        int kt = t >> 1, nt = t & 1;
        kbase = kt * 16; n = nt * 8 + qn; W = W3; ldn = 16; kmax = 256;
        base = 40960; idx = (uint32_t)((kt * 32 + lane) * 4 + nt * 2);
    }
    int k0 = kbase + qk;
    float e0 = (k0     < kmax) ? W[(k0)     * ldn + n] : 0.f;
    float e1 = (k0 + 1 < kmax) ? W[(k0 + 1) * ldn + n] : 0.f;
    float e2 = (k0 + 8 < kmax) ? W[(k0 + 8) * ldn + n] : 0.f;
    float e3 = (k0 + 9 < kmax) ? W[(k0 + 9) * ldn + n] : 0.f;
    g_pack[base + idx]     = bf16_pack2(e0, e1);
    g_pack[base + idx + 1] = bf16_pack2(e2, e3);
}

// ===================== main kernel =====================
__global__ void __launch_bounds__(512, 1)
nerf_mma(const float* __restrict__ rays_o, const float* __restrict__ rays_d,
         const float* __restrict__ b1, const float* __restrict__ b2,
         const float* __restrict__ b3,
         const float* __restrict__ Wc1, const float* __restrict__ bc1,
         const float* __restrict__ Wc2, const float* __restrict__ bc2,
         float* __restrict__ out)
{
    extern __shared__ char smem[];
    const int tid  = threadIdx.x;
    const int lane = tid & 31;
    const int w    = tid >> 5;
    const int mt   = w & 3;               // M-tile (32 rows)
    const int nq   = w >> 2;              // N-quarter (64 cols)
    const int la3  = lane & 3;
    const int qk   = la3 * 2;
    const int r0   = mt * 32 + (lane >> 2);
    const int ray  = blockIdx.x;

    const uint32_t sb = smem_u32(smem);
    float* b1s  = (float*)(smem + SM_B1);
    float* b2s  = (float*)(smem + SM_B2);
    float* b3s  = (float*)(smem + SM_B3);
    float* dirs = (float*)(smem + SM_DIR);
    float* comp = (float*)(smem + SM_COMP);
    float* bc2s = (float*)(smem + SM_BC2);
    const uint32_t* Xu  = (const uint32_t*)(smem + SM_X);
    uint32_t* H1u = (uint32_t*)(smem + SM_H1);
    const uint4* P1q = (const uint4*)(smem + SM_P1);
    const uint4* P2q = (const uint4*)(smem + SM_P2);
    const uint4* P3q = (const uint4*)(smem + SM_P3);
    const char* gp = (const char*)g_pack;

    // ---- async weight staging: P1 (g1), P2 (g2), P3 (g3) ----
    {
        uint32_t d1 = sb + SM_P1, d2 = sb + SM_P2, d3 = sb + SM_P3;
        #pragma unroll
        for (int j = 0; j < 4; j++)
            CP16(d1 + (uint32_t)(tid + j * 512) * 16, gp + (tid + j * 512) * 16);
        CP_COMMIT();
        #pragma unroll
        for (int j = 0; j < 16; j++)
            CP16(d2 + (uint32_t)(tid + j * 512) * 16, gp + 32768 + (tid + j * 512) * 16);
        CP_COMMIT();
        CP16(d3 + (uint32_t)tid * 16, gp + 163840 + tid * 16);
        CP_COMMIT();
    }

    // ---- small constants ----
    if (tid < 256) { b1s[tid] = b1[tid]; b2s[tid] = b2[tid]; }
    if (tid < 16) b3s[tid] = b3[tid];
    if (tid < 3)  bc2s[tid] = bc2[tid];

    // ---- ray setup ----
    float ox = rays_o[ray*3+0], oy = rays_o[ray*3+1], oz = rays_o[ray*3+2];
    float rdx = rays_d[ray*3+0], rdy = rays_d[ray*3+1], rdz = rays_d[ray*3+2];
    float inv_norm = 1.0f / sqrtf(rdx*rdx + rdy*rdy + rdz*rdz);
    float dx = rdx*inv_norm, dy = rdy*inv_norm, dz = rdz*inv_norm;
    float near_t, far_t;
    {
        float dd;
        dd = (fabsf(dx) < 1e-8f) ? 1e-8f : dx; float i0 = 1.0f/dd;
        dd = (fabsf(dy) < 1e-8f) ? 1e-8f : dy; float i1 = 1.0f/dd;
        dd = (fabsf(dz) < 1e-8f) ? 1e-8f : dz; float i2 = 1.0f/dd;
        float t0x=(-1.f-ox)*i0, t1x=(1.f-ox)*i0;
        float t0y=(-1.f-oy)*i1, t1y=(1.f-oy)*i1;
        float t0z=(-1.f-oz)*i2, t1z=(1.f-oz)*i2;
        float nx=fminf(t0x,t1x), fx=fmaxf(t0x,t1x);
        float ny=fminf(t0y,t1y), fy=fmaxf(t0y,t1y);
        float nz=fminf(t0z,t1z), fz=fmaxf(t0z,t1z);
        near_t = fmaxf(fmaxf(nx, fmaxf(ny, nz)), 0.02f);
        far_t  = fminf(fmaxf(fx, fmaxf(fy, fz)), 1000.f);
        far_t  = fmaxf(far_t, near_t + 0.001f);
    }
    const float dtv = (far_t - near_t) * (1.0f/128.0f);

    // ---- posenc (4-way split), stride XS=136 ----
    {
        const int m = tid & 127, g = tid >> 7;
        float t = near_t + ((float)m + 0.5f) * dtv;
        float px = ox + t*dx, py = oy + t*dy, pz = oz + t*dz;
        const uint32_t xbase = sb + SM_X;
        if (g < 3) {
            float pv = (g == 0) ? px : ((g == 1) ? py : pz);
            float f = 1.f;
            #pragma unroll
            for (int q = 0; q < 10; q++) {
                float s, c;
                sincos_acc(pv * f, &s, &c);
                int j1 = 3 + g*10 + q, j2 = 33 + g*10 + q;
                sts_bf16(xbase + (uint32_t)(((j1 >> 1)*XS + m)*4 + (j1 & 1)*2), s);
                sts_bf16(xbase + (uint32_t)(((j2 >> 1)*XS + m)*4 + (j2 & 1)*2), c);
                f *= 2.f;
            }
        } else {
            *(uint32_t*)(smem + SM_X + (0*XS + m)*4) = bf16_pack2(px, py);
            sts_bf16(xbase + (uint32_t)((1*XS + m)*4), pz);
            sts_bf16(xbase + (uint32_t)((31*XS + m)*4 + 2), 0.f);
            if (m < 27) {
                int j = m;
                float dv[3] = {dx, dy, dz};
                float v;
                if (j < 3) v = dv[j];
                else if (j < 15) { int jj = j-3;  float s,c; sincos_acc(dv[jj>>2]*(float)(1<<(jj&3)), &s, &c); v = s; }
                else             { int jj = j-15; float s,c; sincos_acc(dv[jj>>2]*(float)(1<<(jj&3)), &s, &c); v = c; }
                dirs[j] = v;
            }
        }
    }

    CP_WAIT(2);            // P1 landed
    __syncthreads();

    // ---------------- Layer 1: warp = 32 rows x 64 cols ----------------
    float acc[2][8][4];
    #pragma unroll
    for (int rb = 0; rb < 2; rb++)
        #pragma unroll
        for (int ct = 0; ct < 8; ct++)
            #pragma unroll
            for (int j = 0; j < 4; j++) acc[rb][ct][j] = 0.f;

    #pragma unroll
    for (int kt = 0; kt < 4; kt++) {
        int pb0 = kt*8 + la3;
        uint32_t af[2][4];
        #pragma unroll
        for (int rb = 0; rb < 2; rb++) {
            int rr = r0 + rb*16;
            af[rb][0] = Xu[pb0*XS + rr];
            af[rb][1] = Xu[pb0*XS + rr + 8];
            af[rb][2] = Xu[(pb0+4)*XS + rr];
            af[rb][3] = Xu[(pb0+4)*XS + rr + 8];
        }
        #pragma unroll
        for (int ctp = 0; ctp < 4; ctp++) {
            uint4 b = P1q[(kt*16 + nq*4 + ctp)*32 + lane];
            #pragma unroll
            for (int rb = 0; rb < 2; rb++) {
                MMA(acc[rb][2*ctp],   af[rb][0], af[rb][1], af[rb][2], af[rb][3], b.x, b.y);
                MMA(acc[rb][2*ctp+1], af[rb][0], af[rb][1], af[rb][2], af[rb][3], b.z, b.w);
            }
        }
    }
    CP_WAIT(0);            // P2 + P3 landed
    __syncthreads();       // everyone done reading X / P1

    // epilogue: H1 = relu(acc + b1) -> SMEM bf16 pairs (overwrites P1/X region)
    #pragma unroll
    for (int ct = 0; ct < 8; ct++) {
        int n0 = nq*64 + ct*8 + qk;
        float2 bb = *(const float2*)(b1s + n0);
        int kp = nq*32 + ct*4 + la3;
        #pragma unroll
        for (int rb = 0; rb < 2; rb++) {
            int rr = r0 + rb*16;
            H1u[kp*XS + rr]     = bf16_pack2(fmaxf(acc[rb][ct][0] + bb.x, 0.f), fmaxf(acc[rb][ct][1] + bb.y, 0.f));
            H1u[kp*XS + rr + 8] = bf16_pack2(fmaxf(acc[rb][ct][2] + bb.x, 0.f), fmaxf(acc[rb][ct][3] + bb.y, 0.f));
        }
    }
    __syncthreads();

    // ---------------- Layer 2: 16 K-tiles ----------------
    #pragma unroll
    for (int rb = 0; rb < 2; rb++)
        #pragma unroll
        for (int ct = 0; ct < 8; ct++)
            #pragma unroll
            for (int j = 0; j < 4; j++) acc[rb][ct][j] = 0.f;

    #pragma unroll
    for (int kt = 0; kt < 16; kt++) {
        int pb0 = kt*8 + la3;
        uint32_t af[2][4];
        #pragma unroll
        for (int rb = 0; rb < 2; rb++) {
            int rr = r0 + rb*16;
            af[rb][0] = H1u[pb0*XS + rr];
            af[rb][1] = H1u[pb0*XS + rr + 8];
            af[rb][2] = H1u[(pb0+4)*XS + rr];
            af[rb][3] = H1u[(pb0+4)*XS + rr + 8];
        }
        #pragma unroll
        for (int ctp = 0; ctp < 4; ctp++) {
            uint4 b = P2q[(kt*16 + nq*4 + ctp)*32 + lane];
            #pragma unroll
            for (int rb = 0; rb < 2; rb++) {
                MMA(acc[rb][2*ctp],   af[rb][0], af[rb][1], af[rb][2], af[rb][3], b.x, b.y);
                MMA(acc[rb][2*ctp+1], af[rb][0], af[rb][1], af[rb][2], af[rb][3], b.z, b.w);
            }
        }
    }
    __syncthreads();       // everyone done reading P2

    // kick color-head weight copies into dead P2 region (g4)
    {
        for (int ofs = tid*16; ofs < 10752; ofs += 512*16)
            CP16(sb + SM_WC1 + (uint32_t)ofs, (const char*)Wc1 + ofs);
        if (tid < 48) CP16(sb + SM_WC2 + (uint32_t)tid*16, (const char*)Wc2 + tid*16);
        if (tid < 16) CP16(sb + SM_BC1 + (uint32_t)tid*16, (const char*)bc1 + tid*16);
        CP_COMMIT();
    }

    // ---------------- Layer 3: warp handles K-range nq*64..+64 of its 32 rows ---
    float geo[2][2][4];    // [rb][nt]
    #pragma unroll
    for (int rb = 0; rb < 2; rb++)
        #pragma unroll
        for (int nt = 0; nt < 2; nt++)
            #pragma unroll
            for (int j = 0; j < 4; j++) geo[rb][nt][j] = 0.f;

    #pragma unroll
    for (int ii = 0; ii < 4; ii++) {
        int kt3 = nq*4 + ii;
        uint4 bq = P3q[kt3*32 + lane];
        int n0 = nq*64 + (2*ii)*8 + qk;
        float2 bb0 = *(const float2*)(b2s + n0);
        float2 bb1 = *(const float2*)(b2s + n0 + 8);
        #pragma unroll
        for (int rb = 0; rb < 2; rb++) {
            uint32_t a0 = bf16_pack2(fmaxf(acc[rb][2*ii][0] + bb0.x, 0.f),  fmaxf(acc[rb][2*ii][1] + bb0.y, 0.f));
            uint32_t a1 = bf16_pack2(fmaxf(acc[rb][2*ii][2] + bb0.x, 0.f),  fmaxf(acc[rb][2*ii][3] + bb0.y, 0.f));
            uint32_t a2 = bf16_pack2(fmaxf(acc[rb][2*ii+1][0] + bb1.x, 0.f), fmaxf(acc[rb][2*ii+1][1] + bb1.y, 0.f));
            uint32_t a3 = bf16_pack2(fmaxf(acc[rb][2*ii+1][2] + bb1.x, 0.f), fmaxf(acc[rb][2*ii+1][3] + bb1.y, 0.f));
            MMA(geo[rb][0], a0, a1, a2, a3, bq.x, bq.y);
            MMA(geo[rb][1], a0, a1, a2, a3, bq.z, bq.w);
        }
    }

    // 4-way K reduction via SMEM (dead P2 region)
    if (nq > 0) {
        float* red = (float*)(smem + SM_RED) + (nq - 1) * 2048;
        #pragma unroll
        for (int rb = 0; rb < 2; rb++)
            #pragma unroll
            for (int nt = 0; nt < 2; nt++) {
                int c = nt*8 + qk;
                int rr = r0 + rb*16;
                red[rr*16 + c]       = geo[rb][nt][0];
                red[rr*16 + c + 1]   = geo[rb][nt][1];
                red[(rr+8)*16 + c]   = geo[rb][nt][2];
                red[(rr+8)*16 + c+1] = geo[rb][nt][3];
            }
    }
    __syncthreads();
    if (nq == 0) {
        float* red  = (float*)(smem + SM_RED);
        float* geos = (float*)(smem + SM_GEOS);
        #pragma unroll
        for (int rb = 0; rb < 2; rb++)
            #pragma unroll
            for (int nt = 0; nt < 2; nt++) {
                int c = nt*8 + qk;
                int rr = r0 + rb*16;
                geos[rr*16 + c]       = geo[rb][nt][0] + red[rr*16+c]        + red[2048 + rr*16+c]        + red[4096 + rr*16+c];
                geos[rr*16 + c + 1]   = geo[rb][nt][1] + red[rr*16+c+1]      + red[2048 + rr*16+c+1]      + red[4096 + rr*16+c+1];
                geos[(rr+8)*16 + c]   = geo[rb][nt][2] + red[(rr+8)*16+c]    + red[2048 + (rr+8)*16+c]    + red[4096 + (rr+8)*16+c];
                geos[(rr+8)*16 + c+1] = geo[rb][nt][3] + red[(rr+8)*16+c+1]  + red[2048 + (rr+8)*16+c+1]  + red[4096 + (rr+8)*16+c+1];
            }
    }
    CP_WAIT(0);
    __syncthreads();

    // ---------------- color head (4-way split over j) ----------------
    {
        const float* wc1s = (const float*)(smem + SM_WC1);
        const float* wc2s = (const float*)(smem + SM_WC2);
        const float* bc1s = (const float*)(smem + SM_BC1);
        const float* geos = (const float*)(smem + SM_GEOS);
        float* cpart = (float*)(smem + SM_CPART);
        const int m = tid & 127, g = tid >> 7;
        float inp[42];
        #pragma unroll
        for (int i = 0; i < 27; i++) inp[i] = dirs[i];
        #pragma unroll
        for (int i = 0; i < 15; i++) inp[27+i] = geos[m*16 + 1 + i] + b3s[1 + i];
        float a0 = 0.f, a1 = 0.f, a2 = 0.f;
        const int j0 = g * 16;
        for (int j = j0; j < j0 + 16; j++) {
            float h = bc1s[j];
            #pragma unroll
            for (int i = 0; i < 42; i++)
                h = fmaf(inp[i], wc1s[i*64 + j], h);
            h = fmaxf(h, 0.f);
            a0 = fmaf(h, wc2s[j*3+0], a0);
            a1 = fmaf(h, wc2s[j*3+1], a1);
            a2 = fmaf(h, wc2s[j*3+2], a2);
        }
        if (g > 0) {
            float* cp = cpart + ((g-1)*128 + m)*4;
            cp[0] = a0; cp[1] = a1; cp[2] = a2;
        }
        __syncthreads();
        if (g == 0) {
            #pragma unroll
            for (int gg = 0; gg < 3; gg++) {
                const float* cp = cpart + (gg*128 + m)*4;
                a0 += cp[0]; a1 += cp[1]; a2 += cp[2];
            }
            a0 += bc2s[0]; a1 += bc2s[1]; a2 += bc2s[2];
            float sx = geos[m*16] + b3s[0];
            float sigma = (sx > 20.f) ? sx : log1pf(expf(sx));
            float alpha = 1.f - expf(-sigma * dtv);
            comp[m*4+0] = alpha;
            comp[m*4+1] = 1.f / (1.f + expf(-a0));
            comp[m*4+2] = 1.f / (1.f + expf(-a1));
            comp[m*4+3] = 1.f / (1.f + expf(-a2));
        }
    }
    __syncthreads();

    // ---------------- composite: warp-0 parallel scan ----------------
    if (tid < 32) {
        float av[4];
        #pragma unroll
        for (int j = 0; j < 4; j++) av[j] = comp[(lane*4 + j)*4 + 0];
        float q0 = 1.f - av[0] + 1e-10f;
        float q1 = 1.f - av[1] + 1e-10f;
        float q2 = 1.f - av[2] + 1e-10f;
        float q3 = 1.f - av[3] + 1e-10f;
        float inc = ((q0*q1)*(q2*q3));
        #pragma unroll
        for (int off = 1; off < 32; off <<= 1) {
            float t = __shfl_up_sync(0xFFFFFFFF, inc, off);
            if (lane >= off) inc *= t;
        }
        float T = __shfl_up_sync(0xFFFFFFFF, inc, 1);
        if (lane == 0) T = 1.f;
        float wsum = 0.f, dsum = 0.f, r = 0.f, g = 0.f, b = 0.f;
        #pragma unroll
        for (int j = 0; j < 4; j++) {
            int m = lane*4 + j;
            float alpha = av[j];
            float wgt = (T > 1e-4f) ? alpha * T : 0.f;
            wsum += wgt;
            float tsv = near_t + ((float)m + 0.5f) * dtv;
            dsum = fmaf(wgt, tsv, dsum);
            r = fmaf(wgt, comp[m*4+1], r);
            g = fmaf(wgt, comp[m*4+2], g);
            b = fmaf(wgt, comp[m*4+3], b);
            T *= (1.f - alpha + 1e-10f);
        }
        #pragma unroll
        for (int off = 16; off > 0; off >>= 1) {
            wsum += __shfl_xor_sync(0xFFFFFFFF, wsum, off);
            dsum += __shfl_xor_sync(0xFFFFFFFF, dsum, off);
            r    += __shfl_xor_sync(0xFFFFFFFF, r, off);
            g    += __shfl_xor_sync(0xFFFFFFFF, g, off);
            b    += __shfl_xor_sync(0xFFFFFFFF, b, off);
        }
        if (lane == 0) {
            float bgw = 1.f - wsum;
            out[ray*3+0] = r + bgw;
            out[ray*3+1] = g + bgw;
            out[ray*3+2] = b + bgw;
            out[4096*3 + ray] = dsum;
            out[4096*4 + ray] = fminf(fmaxf(wsum, 1e-12f), 1000.f);
        }
    }
}

// ===================== launch =====================
extern "C" void kernel_launch(void* const* d_in, const int* in_sizes, int n_in,
                              void* d_out, int out_size) {
    const float* rays_o = (const float*)d_in[0];
    const float* rays_d = (const float*)d_in[1];
    const float* W1  = (const float*)d_in[2];
    const float* b1  = (const float*)d_in[3];
    const float* W2  = (const float*)d_in[4];
    const float* b2  = (const float*)d_in[5];
    const float* W3  = (const float*)d_in[6];
    const float* b3  = (const float*)d_in[7];
    const float* Wc1 = (const float*)d_in[8];
    const float* bc1 = (const float*)d_in[9];
    const float* Wc2 = (const float*)d_in[10];
    const float* bc2 = (const float*)d_in[11];
    float* out = (float*)d_out;

    prep_pack<<<84, 256>>>(W1, W2, W3);
    cudaFuncSetAttribute(nerf_mma, cudaFuncAttributeMaxDynamicSharedMemorySize, SMEM_BYTES);
    nerf_mma<<<4096, 512, SMEM_BYTES>>>(rays_o, rays_d, b1, b2, b3,
                                        Wc1, bc1, Wc2, bc2, out);
}

// round 9
// speedup vs baseline: 6.2226x; 1.2474x over previous
#include <cuda_runtime.h>
#include <cuda_bf16.h>
#include <math.h>
#include <stdint.h>

// ===================== asm helpers =====================
__device__ __forceinline__ uint32_t smem_u32(const void* p) {
    uint32_t a;
    asm("{ .reg .u64 t; cvta.to.shared.u64 t, %1; cvt.u32.u64 %0, t; }" : "=r"(a) : "l"(p));
    return a;
}
#define CP16(dst_u32, src_ptr) \
    asm volatile("cp.async.cg.shared.global [%0], [%1], 16;" :: "r"(dst_u32), "l"(src_ptr) : "memory")
#define CP_COMMIT() asm volatile("cp.async.commit_group;" ::: "memory")
#define CP_WAIT(n)  asm volatile("cp.async.wait_group %0;" :: "n"(n) : "memory")

#define MMA(d, a0, a1, a2, a3, b0, b1) \
    asm("mma.sync.aligned.m16n8k16.row.col.f32.bf16.bf16.f32 " \
        "{%0,%1,%2,%3}, {%4,%5,%6,%7}, {%8,%9}, {%0,%1,%2,%3};" \
        : "+f"((d)[0]), "+f"((d)[1]), "+f"((d)[2]), "+f"((d)[3]) \
        : "r"(a0), "r"(a1), "r"(a2), "r"(a3), "r"(b0), "r"(b1))

// stride (in u32) for X / H1 pair arrays: 136 -> bank = 8*la3 + q, conflict-free
#define XS 136

// ===================== smem layout =====================
#define SM_P2    0          // 131072   W2 fragments (uint4-paired)
#define SM_P3    131072     // 8192     W3 fragments
#define SM_H1    139264     // 69632    H1 bf16 pairs [128][136] u32 (phase 2)
#define SM_P1    139264     //   phase 1 alias: W1 fragments (32768)
#define SM_X     172032     //   phase 1 alias: posenc X bf16 pairs [32][136] u32
#define SM_B1    208896     // 1024
#define SM_B2    209920     // 1024
#define SM_B3    210944     // 64
#define SM_DIR   211008     // 128
#define SM_COMP  211136     // 2048
#define SM_BC2   213184     // 16
#define SMEM_BYTES 213200
// aliases inside dead P2 region (valid after layer-2 MMAs):
#define SM_RED   0          // 71680  (7 x 128 x 20 fp32) layer-3 partials
#define SM_WC1   71680      // 10752
#define SM_WC2   82432      // 768
#define SM_BC1   83200      // 256
#define SM_DIRC  83456      // 256   dircontrib[64]
#define SM_CPART 83712      // 14336 (7 groups x 128 x 4 floats)
#define SM_GEOS  98048      // 8448  [16][132] fp32 (transposed)

// packed weight image (bf16 fragment order, uint4-paired): P1 32KB | P2 128KB | P3 8KB
__device__ __align__(128) uint32_t g_pack[43008];

__device__ __forceinline__ uint32_t bf16_pack2(float x, float y) {
    __nv_bfloat16 hx = __float2bfloat16(x), hy = __float2bfloat16(y);
    return (uint32_t)__bfloat16_as_ushort(hx) | ((uint32_t)__bfloat16_as_ushort(hy) << 16);
}
__device__ __forceinline__ void sts_bf16(uint32_t addr, float v) {
    uint16_t u = __bfloat16_as_ushort(__float2bfloat16(v));
    asm volatile("st.shared.u16 [%0], %1;" :: "r"(addr), "h"(u));
}
__device__ __forceinline__ void sincos_acc(float phi, float* s, float* c) {
    float k = rintf(phi * 0.15915494309f);
    float r = fmaf(-k, 6.2831854820251465f, phi);
    r = fmaf(-k, -1.7484556000744263e-07f, r);
    sincosf(r, s, c);
}

// ===================== prep: pack weights, N-tile pairs per uint4 =====================
__global__ void prep_pack(const float* __restrict__ W1, const float* __restrict__ W2,
                          const float* __restrict__ W3) {
    int s = blockIdx.x * 256 + threadIdx.x;
    if (s >= 21504) return;
    int lane = s & 31;
    int qn = lane >> 2, qk = (lane & 3) * 2;
    const float* W; int kbase, n, ldn, kmax; uint32_t base, idx;
    if (s < 4096) {                       // P1: 4 kt x 32 nt
        int t = s >> 5;
        int kt = t >> 5, nt = t & 31;
        kbase = kt * 16; n = nt * 8 + qn; W = W1; ldn = 256; kmax = 63;
        base = 0; idx = (uint32_t)(((kt * 16 + (nt >> 1)) * 32 + lane) * 4 + (nt & 1) * 2);
    } else if (s < 20480) {               // P2: 16 kt x 32 nt
        int t = (s - 4096) >> 5;
        int kt = t >> 5, nt = t & 31;
        kbase = kt * 16; n = nt * 8 + qn; W = W2; ldn = 256; kmax = 256;
        base = 8192; idx = (uint32_t)(((kt * 16 + (nt >> 1)) * 32 + lane) * 4 + (nt & 1) * 2);
    } else {                              // P3: 16 kt x 2 nt
        int t = (s - 20480) >> 5;
        int kt = t >> 1, nt = t & 1;
        kbase = kt * 16; n = nt * 8 + qn; W = W3; ldn = 16; kmax = 256;
        base = 40960; idx = (uint32_t)((kt * 32 + lane) * 4 + nt * 2);
    }
    int k0 = kbase + qk;
    float e0 = (k0     < kmax) ? W[(k0)     * ldn + n] : 0.f;
    float e1 = (k0 + 1 < kmax) ? W[(k0 + 1) * ldn + n] : 0.f;
    float e2 = (k0 + 8 < kmax) ? W[(k0 + 8) * ldn + n] : 0.f;
    float e3 = (k0 + 9 < kmax) ? W[(k0 + 9) * ldn + n] : 0.f;
    g_pack[base + idx]     = bf16_pack2(e0, e1);
    g_pack[base + idx + 1] = bf16_pack2(e2, e3);
}

// ===================== main kernel: 1024 threads, 32 warps =====================
__global__ void __launch_bounds__(1024, 1)
nerf_mma(const float* __restrict__ rays_o, const float* __restrict__ rays_d,
         const float* __restrict__ b1, const float* __restrict__ b2,
         const float* __restrict__ b3,
         const float* __restrict__ Wc1, const float* __restrict__ bc1,
         const float* __restrict__ Wc2, const float* __restrict__ bc2,
         float* __restrict__ out)
{
    extern __shared__ char smem[];
    const int tid  = threadIdx.x;
    const int lane = tid & 31;
    const int w    = tid >> 5;
    const int mt   = w & 3;               // M-tile (32 rows)
    const int nq   = w >> 2;              // N-eighth (32 cols)
    const int la3  = lane & 3;
    const int qk   = la3 * 2;
    const int r0   = mt * 32 + (lane >> 2);
    const int ray  = blockIdx.x;

    const uint32_t sb = smem_u32(smem);
    float* b1s  = (float*)(smem + SM_B1);
    float* b2s  = (float*)(smem + SM_B2);
    float* b3s  = (float*)(smem + SM_B3);
    float* dirs = (float*)(smem + SM_DIR);
    float* comp = (float*)(smem + SM_COMP);
    float* bc2s = (float*)(smem + SM_BC2);
    const uint32_t* Xu  = (const uint32_t*)(smem + SM_X);
    uint32_t* H1u = (uint32_t*)(smem + SM_H1);
    const uint4* P1q = (const uint4*)(smem + SM_P1);
    const uint4* P2q = (const uint4*)(smem + SM_P2);
    const uint4* P3q = (const uint4*)(smem + SM_P3);
    const char* gp = (const char*)g_pack;

    // ---- async weight staging: P1 (g1), P2 (g2), P3 (g3) ----
    {
        uint32_t d1 = sb + SM_P1, d2 = sb + SM_P2, d3 = sb + SM_P3;
        #pragma unroll
        for (int j = 0; j < 2; j++)
            CP16(d1 + (uint32_t)(tid + j * 1024) * 16, gp + (tid + j * 1024) * 16);
        CP_COMMIT();
        #pragma unroll
        for (int j = 0; j < 8; j++)
            CP16(d2 + (uint32_t)(tid + j * 1024) * 16, gp + 32768 + (tid + j * 1024) * 16);
        CP_COMMIT();
        if (tid < 512) CP16(d3 + (uint32_t)tid * 16, gp + 163840 + tid * 16);
        CP_COMMIT();
    }

    // ---- small constants ----
    if (tid < 256) { b1s[tid] = b1[tid]; b2s[tid] = b2[tid]; }
    if (tid < 16) b3s[tid] = b3[tid];
    if (tid < 3)  bc2s[tid] = bc2[tid];

    // ---- ray setup (redundant, all threads) ----
    float ox = rays_o[ray*3+0], oy = rays_o[ray*3+1], oz = rays_o[ray*3+2];
    float rdx = rays_d[ray*3+0], rdy = rays_d[ray*3+1], rdz = rays_d[ray*3+2];
    float inv_norm = 1.0f / sqrtf(rdx*rdx + rdy*rdy + rdz*rdz);
    float dx = rdx*inv_norm, dy = rdy*inv_norm, dz = rdz*inv_norm;
    float near_t, far_t;
    {
        float dd;
        dd = (fabsf(dx) < 1e-8f) ? 1e-8f : dx; float i0 = 1.0f/dd;
        dd = (fabsf(dy) < 1e-8f) ? 1e-8f : dy; float i1 = 1.0f/dd;
        dd = (fabsf(dz) < 1e-8f) ? 1e-8f : dz; float i2 = 1.0f/dd;
        float t0x=(-1.f-ox)*i0, t1x=(1.f-ox)*i0;
        float t0y=(-1.f-oy)*i1, t1y=(1.f-oy)*i1;
        float t0z=(-1.f-oz)*i2, t1z=(1.f-oz)*i2;
        float nx=fminf(t0x,t1x), fx=fmaxf(t0x,t1x);
        float ny=fminf(t0y,t1y), fy=fmaxf(t0y,t1y);
        float nz=fminf(t0z,t1z), fz=fmaxf(t0z,t1z);
        near_t = fmaxf(fmaxf(nx, fmaxf(ny, nz)), 0.02f);
        far_t  = fminf(fmaxf(fx, fmaxf(fy, fz)), 1000.f);
        far_t  = fmaxf(far_t, near_t + 0.001f);
    }
    const float dtv = (far_t - near_t) * (1.0f/128.0f);

    // ---- posenc (8-way split over groups g = tid>>7) ----
    {
        const int m = tid & 127, g = tid >> 7;
        float t = near_t + ((float)m + 0.5f) * dtv;
        float px = ox + t*dx, py = oy + t*dy, pz = oz + t*dz;
        const uint32_t xbase = sb + SM_X;
        if (g < 6) {
            int ci = g >> 1, half = g & 1;
            float pv = (ci == 0) ? px : ((ci == 1) ? py : pz);
            float f = half ? 32.f : 1.f;
            #pragma unroll
            for (int q = 0; q < 5; q++) {
                int qq = half*5 + q;
                float s, c;
                sincos_acc(pv * f, &s, &c);
                int j1 = 3 + ci*10 + qq, j2 = 33 + ci*10 + qq;
                sts_bf16(xbase + (uint32_t)(((j1 >> 1)*XS + m)*4 + (j1 & 1)*2), s);
                sts_bf16(xbase + (uint32_t)(((j2 >> 1)*XS + m)*4 + (j2 & 1)*2), c);
                f *= 2.f;
            }
        } else if (g == 6) {
            *(uint32_t*)(smem + SM_X + (0*XS + m)*4) = bf16_pack2(px, py);
            sts_bf16(xbase + (uint32_t)((1*XS + m)*4), pz);
            sts_bf16(xbase + (uint32_t)((31*XS + m)*4 + 2), 0.f);
        } else {
            if (m < 27) {
                int j = m;
                float dv[3] = {dx, dy, dz};
                float v;
                if (j < 3) v = dv[j];
                else if (j < 15) { int jj = j-3;  float s,c; sincos_acc(dv[jj>>2]*(float)(1<<(jj&3)), &s, &c); v = s; }
                else             { int jj = j-15; float s,c; sincos_acc(dv[jj>>2]*(float)(1<<(jj&3)), &s, &c); v = c; }
                dirs[j] = v;
            }
        }
    }

    CP_WAIT(2);            // P1 landed
    __syncthreads();

    // ---------------- Layer 1: warp = 32 rows x 32 cols ----------------
    float acc[2][4][4];
    #pragma unroll
    for (int rb = 0; rb < 2; rb++)
        #pragma unroll
        for (int ct = 0; ct < 4; ct++)
            #pragma unroll
            for (int j = 0; j < 4; j++) acc[rb][ct][j] = 0.f;

    #pragma unroll
    for (int kt = 0; kt < 4; kt++) {
        int pb0 = kt*8 + la3;
        uint32_t af[2][4];
        #pragma unroll
        for (int rb = 0; rb < 2; rb++) {
            int rr = r0 + rb*16;
            af[rb][0] = Xu[pb0*XS + rr];
            af[rb][1] = Xu[pb0*XS + rr + 8];
            af[rb][2] = Xu[(pb0+4)*XS + rr];
            af[rb][3] = Xu[(pb0+4)*XS + rr + 8];
        }
        uint4 p0 = P1q[(kt*16 + nq*2)*32 + lane];
        uint4 p1 = P1q[(kt*16 + nq*2 + 1)*32 + lane];
        #pragma unroll
        for (int rb = 0; rb < 2; rb++) {
            MMA(acc[rb][0], af[rb][0], af[rb][1], af[rb][2], af[rb][3], p0.x, p0.y);
            MMA(acc[rb][1], af[rb][0], af[rb][1], af[rb][2], af[rb][3], p0.z, p0.w);
            MMA(acc[rb][2], af[rb][0], af[rb][1], af[rb][2], af[rb][3], p1.x, p1.y);
            MMA(acc[rb][3], af[rb][0], af[rb][1], af[rb][2], af[rb][3], p1.z, p1.w);
        }
    }
    CP_WAIT(0);            // P2 + P3 landed
    __syncthreads();       // everyone done reading X / P1

    // epilogue: H1 = relu(acc + b1) -> SMEM bf16 pairs (overwrites P1/X region)
    #pragma unroll
    for (int ct = 0; ct < 4; ct++) {
        int n0 = nq*32 + ct*8 + qk;
        float2 bb = *(const float2*)(b1s + n0);
        int kp = nq*16 + ct*4 + la3;
        #pragma unroll
        for (int rb = 0; rb < 2; rb++) {
            int rr = r0 + rb*16;
            H1u[kp*XS + rr]     = bf16_pack2(fmaxf(acc[rb][ct][0] + bb.x, 0.f), fmaxf(acc[rb][ct][1] + bb.y, 0.f));
            H1u[kp*XS + rr + 8] = bf16_pack2(fmaxf(acc[rb][ct][2] + bb.x, 0.f), fmaxf(acc[rb][ct][3] + bb.y, 0.f));
        }
    }
    __syncthreads();

    // ---------------- Layer 2: 16 K-tiles ----------------
    #pragma unroll
    for (int rb = 0; rb < 2; rb++)
        #pragma unroll
        for (int ct = 0; ct < 4; ct++)
            #pragma unroll
            for (int j = 0; j < 4; j++) acc[rb][ct][j] = 0.f;

    #pragma unroll
    for (int kt = 0; kt < 16; kt++) {
        int pb0 = kt*8 + la3;
        uint32_t af[2][4];
        #pragma unroll
        for (int rb = 0; rb < 2; rb++) {
            int rr = r0 + rb*16;
            af[rb][0] = H1u[pb0*XS + rr];
            af[rb][1] = H1u[pb0*XS + rr + 8];
            af[rb][2] = H1u[(pb0+4)*XS + rr];
            af[rb][3] = H1u[(pb0+4)*XS + rr + 8];
        }
        uint4 p0 = P2q[(kt*16 + nq*2)*32 + lane];
        uint4 p1 = P2q[(kt*16 + nq*2 + 1)*32 + lane];
        #pragma unroll
        for (int rb = 0; rb < 2; rb++) {
            MMA(acc[rb][0], af[rb][0], af[rb][1], af[rb][2], af[rb][3], p0.x, p0.y);
            MMA(acc[rb][1], af[rb][0], af[rb][1], af[rb][2], af[rb][3], p0.z, p0.w);
            MMA(acc[rb][2], af[rb][0], af[rb][1], af[rb][2], af[rb][3], p1.x, p1.y);
            MMA(acc[rb][3], af[rb][0], af[rb][1], af[rb][2], af[rb][3], p1.z, p1.w);
        }
    }
    __syncthreads();       // everyone done reading P2

    // kick color-head weight copies into dead P2 region (g4)
    {
        if (tid < 672) CP16(sb + SM_WC1 + (uint32_t)tid*16, (const char*)Wc1 + tid*16);
        if (tid < 48)  CP16(sb + SM_WC2 + (uint32_t)tid*16, (const char*)Wc2 + tid*16);
        if (tid < 16)  CP16(sb + SM_BC1 + (uint32_t)tid*16, (const char*)bc1 + tid*16);
        CP_COMMIT();
    }

    // ---------------- Layer 3: warp owns K-range nq*32..+32 of its 32 rows ------
    float geo[2][2][4];    // [rb][nt]
    #pragma unroll
    for (int rb = 0; rb < 2; rb++)
        #pragma unroll
        for (int nt = 0; nt < 2; nt++)
            #pragma unroll
            for (int j = 0; j < 4; j++) geo[rb][nt][j] = 0.f;

    #pragma unroll
    for (int ii = 0; ii < 2; ii++) {
        int kt3 = nq*2 + ii;
        uint4 bq = P3q[kt3*32 + lane];
        int n0 = nq*32 + (2*ii)*8 + qk;
        float2 bb0 = *(const float2*)(b2s + n0);
        float2 bb1 = *(const float2*)(b2s + n0 + 8);
        #pragma unroll
        for (int rb = 0; rb < 2; rb++) {
            uint32_t a0 = bf16_pack2(fmaxf(acc[rb][2*ii][0] + bb0.x, 0.f),  fmaxf(acc[rb][2*ii][1] + bb0.y, 0.f));
            uint32_t a1 = bf16_pack2(fmaxf(acc[rb][2*ii][2] + bb0.x, 0.f),  fmaxf(acc[rb][2*ii][3] + bb0.y, 0.f));
            uint32_t a2 = bf16_pack2(fmaxf(acc[rb][2*ii+1][0] + bb1.x, 0.f), fmaxf(acc[rb][2*ii+1][1] + bb1.y, 0.f));
            uint32_t a3 = bf16_pack2(fmaxf(acc[rb][2*ii+1][2] + bb1.x, 0.f), fmaxf(acc[rb][2*ii+1][3] + bb1.y, 0.f));
            MMA(geo[rb][0], a0, a1, a2, a3, bq.x, bq.y);
            MMA(geo[rb][1], a0, a1, a2, a3, bq.z, bq.w);
        }
    }

    // 8-way K reduction via SMEM (dead P2 region, stride 20 pad)
    if (nq > 0) {
        float* red = (float*)(smem + SM_RED) + (nq - 1) * 2560;
        #pragma unroll
        for (int rb = 0; rb < 2; rb++)
            #pragma unroll
            for (int nt = 0; nt < 2; nt++) {
                int c = nt*8 + qk;
                int rr = r0 + rb*16;
                red[rr*20 + c]       = geo[rb][nt][0];
                red[rr*20 + c + 1]   = geo[rb][nt][1];
                red[(rr+8)*20 + c]   = geo[rb][nt][2];
                red[(rr+8)*20 + c+1] = geo[rb][nt][3];
            }
    }
    __syncthreads();
    if (nq == 0) {
        const float* red = (const float*)(smem + SM_RED);
        float* geos = (float*)(smem + SM_GEOS);   // transposed [16][132]
        #pragma unroll
        for (int rb = 0; rb < 2; rb++)
            #pragma unroll
            for (int nt = 0; nt < 2; nt++) {
                int c = nt*8 + qk;
                #pragma unroll
                for (int hv = 0; hv < 2; hv++) {
                    int rr = r0 + rb*16 + hv*8;
                    float v0 = geo[rb][nt][2*hv+0];
                    float v1 = geo[rb][nt][2*hv+1];
                    #pragma unroll
                    for (int gg = 0; gg < 7; gg++) {
                        v0 += red[gg*2560 + rr*20 + c];
                        v1 += red[gg*2560 + rr*20 + c + 1];
                    }
                    geos[c*132 + rr]     = v0;
                    geos[(c+1)*132 + rr] = v1;
                }
            }
    }
    CP_WAIT(0);
    __syncthreads();

    // ---------------- color head ----------------
    {
        const float* wc1s = (const float*)(smem + SM_WC1);
        const float* wc2s = (const float*)(smem + SM_WC2);
        const float* bc1s = (const float*)(smem + SM_BC1);
        const float* geos = (const float*)(smem + SM_GEOS);
        float* dc   = (float*)(smem + SM_DIRC);
        float* cpart= (float*)(smem + SM_CPART);

        // phase A: dircontrib[j] (ray-constant), 64 threads
        if (tid < 64) {
            int j = tid;
            float h = bc1s[j];
            #pragma unroll
            for (int i = 0; i < 27; i++)
                h = fmaf(dirs[i], wc1s[i*64 + j], h);
            dc[j] = h;
        }
        __syncthreads();

        // phase B: 8 groups x 8 j's; fea[15] in regs
        const int m = tid & 127, g = tid >> 7;
        float fea[15];
        #pragma unroll
        for (int i = 0; i < 15; i++) fea[i] = geos[(1+i)*132 + m] + b3s[1+i];
        float a0 = 0.f, a1 = 0.f, a2 = 0.f;
        const int j0 = g * 8;
        #pragma unroll
        for (int jj = 0; jj < 8; jj++) {
            int j = j0 + jj;
            float h = dc[j];
            #pragma unroll
            for (int i = 0; i < 15; i++)
                h = fmaf(fea[i], wc1s[(27+i)*64 + j], h);
            h = fmaxf(h, 0.f);
            a0 = fmaf(h, wc2s[j*3+0], a0);
            a1 = fmaf(h, wc2s[j*3+1], a1);
            a2 = fmaf(h, wc2s[j*3+2], a2);
        }
        if (g > 0) {
            float* cp = cpart + ((g-1)*128 + m)*4;
            cp[0] = a0; cp[1] = a1; cp[2] = a2;
        }
        __syncthreads();
        if (g == 0) {
            #pragma unroll
            for (int gg = 0; gg < 7; gg++) {
                const float* cp = cpart + (gg*128 + m)*4;
                a0 += cp[0]; a1 += cp[1]; a2 += cp[2];
            }
            a0 += bc2s[0]; a1 += bc2s[1]; a2 += bc2s[2];
            float sx = geos[0*132 + m] + b3s[0];
            float sigma = (sx > 20.f) ? sx : log1pf(expf(sx));
            float alpha = 1.f - expf(-sigma * dtv);
            comp[m*4+0] = alpha;
            comp[m*4+1] = 1.f / (1.f + expf(-a0));
            comp[m*4+2] = 1.f / (1.f + expf(-a1));
            comp[m*4+3] = 1.f / (1.f + expf(-a2));
        }
    }
    __syncthreads();

    // ---------------- composite: warp-0 parallel scan ----------------
    if (tid < 32) {
        float av[4];
        #pragma unroll
        for (int j = 0; j < 4; j++) av[j] = comp[(lane*4 + j)*4 + 0];
        float q0 = 1.f - av[0] + 1e-10f;
        float q1 = 1.f - av[1] + 1e-10f;
        float q2 = 1.f - av[2] + 1e-10f;
        float q3 = 1.f - av[3] + 1e-10f;
        float inc = ((q0*q1)*(q2*q3));
        #pragma unroll
        for (int off = 1; off < 32; off <<= 1) {
            float t = __shfl_up_sync(0xFFFFFFFF, inc, off);
            if (lane >= off) inc *= t;
        }
        float T = __shfl_up_sync(0xFFFFFFFF, inc, 1);
        if (lane == 0) T = 1.f;
        float wsum = 0.f, dsum = 0.f, r = 0.f, g = 0.f, b = 0.f;
        #pragma unroll
        for (int j = 0; j < 4; j++) {
            int m = lane*4 + j;
            float alpha = av[j];
            float wgt = (T > 1e-4f) ? alpha * T : 0.f;
            wsum += wgt;
            float tsv = near_t + ((float)m + 0.5f) * dtv;
            dsum = fmaf(wgt, tsv, dsum);
            r = fmaf(wgt, comp[m*4+1], r);
            g = fmaf(wgt, comp[m*4+2], g);
            b = fmaf(wgt, comp[m*4+3], b);
            T *= (1.f - alpha + 1e-10f);
        }
        #pragma unroll
        for (int off = 16; off > 0; off >>= 1) {
            wsum += __shfl_xor_sync(0xFFFFFFFF, wsum, off);
            dsum += __shfl_xor_sync(0xFFFFFFFF, dsum, off);
            r    += __shfl_xor_sync(0xFFFFFFFF, r, off);
            g    += __shfl_xor_sync(0xFFFFFFFF, g, off);
            b    += __shfl_xor_sync(0xFFFFFFFF, b, off);
        }
        if (lane == 0) {
            float bgw = 1.f - wsum;
            out[ray*3+0] = r + bgw;
            out[ray*3+1] = g + bgw;
            out[ray*3+2] = b + bgw;
            out[4096*3 + ray] = dsum;
            out[4096*4 + ray] = fminf(fmaxf(wsum, 1e-12f), 1000.f);
        }
    }
}

// ===================== launch =====================
extern "C" void kernel_launch(void* const* d_in, const int* in_sizes, int n_in,
                              void* d_out, int out_size) {
    const float* rays_o = (const float*)d_in[0];
    const float* rays_d = (const float*)d_in[1];
    const float* W1  = (const float*)d_in[2];
    const float* b1  = (const float*)d_in[3];
    const float* W2  = (const float*)d_in[4];
    const float* b2  = (const float*)d_in[5];
    const float* W3  = (const float*)d_in[6];
    const float* b3  = (const float*)d_in[7];
    const float* Wc1 = (const float*)d_in[8];
    const float* bc1 = (const float*)d_in[9];
    const float* Wc2 = (const float*)d_in[10];
    const float* bc2 = (const float*)d_in[11];
    float* out = (float*)d_out;

    prep_pack<<<84, 256>>>(W1, W2, W3);
    cudaFuncSetAttribute(nerf_mma, cudaFuncAttributeMaxDynamicSharedMemorySize, SMEM_BYTES);
    nerf_mma<<<4096, 1024, SMEM_BYTES>>>(rays_o, rays_d, b1, b2, b3,
                                         Wc1, bc1, Wc2, bc2, out);
}

// round 10
// speedup vs baseline: 6.2668x; 1.0071x over previous
#include <cuda_runtime.h>
#include <cuda_bf16.h>
#include <math.h>
#include <stdint.h>

// ===================== asm helpers =====================
__device__ __forceinline__ uint32_t smem_u32(const void* p) {
    uint32_t a;
    asm("{ .reg .u64 t; cvta.to.shared.u64 t, %1; cvt.u32.u64 %0, t; }" : "=r"(a) : "l"(p));
    return a;
}
#define CP16(dst_u32, src_ptr) \
    asm volatile("cp.async.cg.shared.global [%0], [%1], 16;" :: "r"(dst_u32), "l"(src_ptr) : "memory")
#define CP_COMMIT() asm volatile("cp.async.commit_group;" ::: "memory")
#define CP_WAIT(n)  asm volatile("cp.async.wait_group %0;" :: "n"(n) : "memory")

#define MMA(d, a0, a1, a2, a3, b0, b1) \
    asm("mma.sync.aligned.m16n8k16.row.col.f32.bf16.bf16.f32 " \
        "{%0,%1,%2,%3}, {%4,%5,%6,%7}, {%8,%9}, {%0,%1,%2,%3};" \
        : "+f"((d)[0]), "+f"((d)[1]), "+f"((d)[2]), "+f"((d)[3]) \
        : "r"(a0), "r"(a1), "r"(a2), "r"(a3), "r"(b0), "r"(b1))

// ===================== smem layout =====================
#define SM_P2    0          // 131072   W2 fragments (uint4-paired)
#define SM_P3    131072     // 8192     W3 fragments
#define SM_H1F   139264     // 65536    H1 A-fragments [16kt][4mt][2rb][32][4]u32 (phase 2)
#define SM_P1    139264     //   phase-1 alias: W1 fragments (32768)
#define SM_XF    172032     //   phase-1 alias: X A-fragments [4kt][4mt][2rb][32][4]u32 (16384)
#define SM_B1    204800     // 1024
#define SM_B2    205824     // 1024
#define SM_B3    206848     // 64
#define SM_DIR   206912     // 128
#define SM_COMP  207040     // 2048
#define SM_BC2   209088     // 16
#define SMEM_BYTES 209104
// aliases inside dead P2 region (valid after layer-2 MMAs):
#define SM_RED   0          // 71680  (7 x 128 x 20 fp32) layer-3 partials
#define SM_WC1   71680      // 10752
#define SM_WC2   82432      // 768
#define SM_BC1   83200      // 256
#define SM_DIRC  83456      // 256   dircontrib[64]
#define SM_CPART 83712      // 14336 (7 groups x 128 x 4 floats)
#define SM_GEOS  98048      // 8448  [16][132] fp32 (transposed)

// packed weight image (bf16 fragment order, uint4-paired): P1 32KB | P2 128KB | P3 8KB
__device__ __align__(128) uint32_t g_pack[43008];

__device__ __forceinline__ uint32_t bf16_pack2(float x, float y) {
    __nv_bfloat16 hx = __float2bfloat16(x), hy = __float2bfloat16(y);
    return (uint32_t)__bfloat16_as_ushort(hx) | ((uint32_t)__bfloat16_as_ushort(hy) << 16);
}
__device__ __forceinline__ void sts_bf16(uint32_t addr, float v) {
    uint16_t u = __bfloat16_as_ushort(__float2bfloat16(v));
    asm volatile("st.shared.u16 [%0], %1;" :: "r"(addr), "h"(u));
}
__device__ __forceinline__ void sincos_acc(float phi, float* s, float* c) {
    float k = rintf(phi * 0.15915494309f);
    float r = fmaf(-k, 6.2831854820251465f, phi);
    r = fmaf(-k, -1.7484556000744263e-07f, r);
    sincosf(r, s, c);
}

// byte address (relative) of feature j of sample m inside an A-fragment array
__device__ __forceinline__ uint32_t xf_addr(int m, int j) {
    int p = j >> 1;
    int kt = p >> 3;
    int mtx = m >> 5;
    int lm = m & 31;
    int rb = lm >> 4;
    int l16 = lm & 15;
    int rowbit = l16 >> 3;
    int lane = (l16 & 7) * 4 + (p & 3);
    int jj = ((p >> 2) & 1) * 2 + rowbit;
    return (uint32_t)(((((kt * 4 + mtx) * 2 + rb) * 32 + lane) * 4 + jj) * 4 + (j & 1) * 2);
}

// ===================== prep: pack weights, N-tile pairs per uint4 =====================
__global__ void prep_pack(const float* __restrict__ W1, const float* __restrict__ W2,
                          const float* __restrict__ W3) {
    int s = blockIdx.x * 256 + threadIdx.x;
    if (s >= 21504) return;
    int lane = s & 31;
    int qn = lane >> 2, qk = (lane & 3) * 2;
    const float* W; int kbase, n, ldn, kmax; uint32_t base, idx;
    if (s < 4096) {                       // P1: 4 kt x 32 nt
        int t = s >> 5;
        int kt = t >> 5, nt = t & 31;
        kbase = kt * 16; n = nt * 8 + qn; W = W1; ldn = 256; kmax = 63;
        base = 0; idx = (uint32_t)(((kt * 16 + (nt >> 1)) * 32 + lane) * 4 + (nt & 1) * 2);
    } else if (s < 20480) {               // P2: 16 kt x 32 nt
        int t = (s - 4096) >> 5;
        int kt = t >> 5, nt = t & 31;
        kbase = kt * 16; n = nt * 8 + qn; W = W2; ldn = 256; kmax = 256;
        base = 8192; idx = (uint32_t)(((kt * 16 + (nt >> 1)) * 32 + lane) * 4 + (nt & 1) * 2);
    } else {                              // P3: 16 kt x 2 nt
        int t = (s - 20480) >> 5;
        int kt = t >> 1, nt = t & 1;
        kbase = kt * 16; n = nt * 8 + qn; W = W3; ldn = 16; kmax = 256;
        base = 40960; idx = (uint32_t)((kt * 32 + lane) * 4 + nt * 2);
    }
    int k0 = kbase + qk;
    float e0 = (k0     < kmax) ? W[(k0)     * ldn + n] : 0.f;
    float e1 = (k0 + 1 < kmax) ? W[(k0 + 1) * ldn + n] : 0.f;
    float e2 = (k0 + 8 < kmax) ? W[(k0 + 8) * ldn + n] : 0.f;
    float e3 = (k0 + 9 < kmax) ? W[(k0 + 9) * ldn + n] : 0.f;
    g_pack[base + idx]     = bf16_pack2(e0, e1);
    g_pack[base + idx + 1] = bf16_pack2(e2, e3);
}

// ===================== main kernel: 1024 threads, 32 warps =====================
__global__ void __launch_bounds__(1024, 1)
nerf_mma(const float* __restrict__ rays_o, const float* __restrict__ rays_d,
         const float* __restrict__ b1, const float* __restrict__ b2,
         const float* __restrict__ b3,
         const float* __restrict__ Wc1, const float* __restrict__ bc1,
         const float* __restrict__ Wc2, const float* __restrict__ bc2,
         float* __restrict__ out)
{
    extern __shared__ char smem[];
    const int tid  = threadIdx.x;
    const int lane = tid & 31;
    const int w    = tid >> 5;
    const int mt   = w & 3;               // M-tile (32 rows)
    const int nq   = w >> 2;              // N-eighth (32 cols)
    const int la3  = lane & 3;
    const int qk   = la3 * 2;
    const int r0   = mt * 32 + (lane >> 2);
    const int ray  = blockIdx.x;

    const uint32_t sb = smem_u32(smem);
    float* b1s  = (float*)(smem + SM_B1);
    float* b2s  = (float*)(smem + SM_B2);
    float* b3s  = (float*)(smem + SM_B3);
    float* dirs = (float*)(smem + SM_DIR);
    float* comp = (float*)(smem + SM_COMP);
    float* bc2s = (float*)(smem + SM_BC2);
    const uint4* P1q = (const uint4*)(smem + SM_P1);
    const uint4* P2q = (const uint4*)(smem + SM_P2);
    const uint4* P3q = (const uint4*)(smem + SM_P3);
    const char* gp = (const char*)g_pack;

    // ---- async weight staging: P1 (g1), P2 (g2), P3 (g3) ----
    {
        uint32_t d1 = sb + SM_P1, d2 = sb + SM_P2, d3 = sb + SM_P3;
        #pragma unroll
        for (int j = 0; j < 2; j++)
            CP16(d1 + (uint32_t)(tid + j * 1024) * 16, gp + (tid + j * 1024) * 16);
        CP_COMMIT();
        #pragma unroll
        for (int j = 0; j < 8; j++)
            CP16(d2 + (uint32_t)(tid + j * 1024) * 16, gp + 32768 + (tid + j * 1024) * 16);
        CP_COMMIT();
        if (tid < 512) CP16(d3 + (uint32_t)tid * 16, gp + 163840 + tid * 16);
        CP_COMMIT();
    }

    // ---- small constants ----
    if (tid < 256) { b1s[tid] = b1[tid]; b2s[tid] = b2[tid]; }
    if (tid < 16) b3s[tid] = b3[tid];
    if (tid < 3)  bc2s[tid] = bc2[tid];

    // ---- ray setup (redundant, all threads) ----
    float ox = rays_o[ray*3+0], oy = rays_o[ray*3+1], oz = rays_o[ray*3+2];
    float rdx = rays_d[ray*3+0], rdy = rays_d[ray*3+1], rdz = rays_d[ray*3+2];
    float inv_norm = 1.0f / sqrtf(rdx*rdx + rdy*rdy + rdz*rdz);
    float dx = rdx*inv_norm, dy = rdy*inv_norm, dz = rdz*inv_norm;
    float near_t, far_t;
    {
        float dd;
        dd = (fabsf(dx) < 1e-8f) ? 1e-8f : dx; float i0 = 1.0f/dd;
        dd = (fabsf(dy) < 1e-8f) ? 1e-8f : dy; float i1 = 1.0f/dd;
        dd = (fabsf(dz) < 1e-8f) ? 1e-8f : dz; float i2 = 1.0f/dd;
        float t0x=(-1.f-ox)*i0, t1x=(1.f-ox)*i0;
        float t0y=(-1.f-oy)*i1, t1y=(1.f-oy)*i1;
        float t0z=(-1.f-oz)*i2, t1z=(1.f-oz)*i2;
        float nx=fminf(t0x,t1x), fx=fmaxf(t0x,t1x);
        float ny=fminf(t0y,t1y), fy=fmaxf(t0y,t1y);
        float nz=fminf(t0z,t1z), fz=fmaxf(t0z,t1z);
        near_t = fmaxf(fmaxf(nx, fmaxf(ny, nz)), 0.02f);
        far_t  = fminf(fmaxf(fx, fmaxf(fy, fz)), 1000.f);
        far_t  = fmaxf(far_t, near_t + 0.001f);
    }
    const float dtv = (far_t - near_t) * (1.0f/128.0f);

    // ---- posenc (8-way split over groups g = tid>>7), writes A-fragment layout --
    {
        const int m = tid & 127, g = tid >> 7;
        float t = near_t + ((float)m + 0.5f) * dtv;
        float px = ox + t*dx, py = oy + t*dy, pz = oz + t*dz;
        const uint32_t xbase = sb + SM_XF;
        if (g < 6) {
            int ci = g >> 1, half = g & 1;
            float pv = (ci == 0) ? px : ((ci == 1) ? py : pz);
            float f = half ? 32.f : 1.f;
            #pragma unroll
            for (int q = 0; q < 5; q++) {
                int qq = half*5 + q;
                float s, c;
                sincos_acc(pv * f, &s, &c);
                sts_bf16(xbase + xf_addr(m, 3 + ci*10 + qq), s);
                sts_bf16(xbase + xf_addr(m, 33 + ci*10 + qq), c);
                f *= 2.f;
            }
        } else if (g == 6) {
            sts_bf16(xbase + xf_addr(m, 0), px);
            sts_bf16(xbase + xf_addr(m, 1), py);
            sts_bf16(xbase + xf_addr(m, 2), pz);
            sts_bf16(xbase + xf_addr(m, 63), 0.f);
        } else {
            if (m < 27) {
                int j = m;
                float dv[3] = {dx, dy, dz};
                float v;
                if (j < 3) v = dv[j];
                else if (j < 15) { int jj = j-3;  float s,c; sincos_acc(dv[jj>>2]*(float)(1<<(jj&3)), &s, &c); v = s; }
                else             { int jj = j-15; float s,c; sincos_acc(dv[jj>>2]*(float)(1<<(jj&3)), &s, &c); v = c; }
                dirs[j] = v;
            }
        }
    }

    CP_WAIT(2);            // P1 landed
    __syncthreads();

    // ---------------- Layer 1: warp = 32 rows x 32 cols ----------------
    float acc[2][4][4];
    #pragma unroll
    for (int rb = 0; rb < 2; rb++)
        #pragma unroll
        for (int ct = 0; ct < 4; ct++)
            #pragma unroll
            for (int j = 0; j < 4; j++) acc[rb][ct][j] = 0.f;

    {
        const uint4* pA = (const uint4*)(smem + SM_XF) + mt*64 + lane;
        #pragma unroll
        for (int kt = 0; kt < 4; kt++) {
            uint4 a0 = pA[kt*256];
            uint4 a1 = pA[kt*256 + 32];
            uint4 p0 = P1q[(kt*16 + nq*2)*32 + lane];
            uint4 p1 = P1q[(kt*16 + nq*2 + 1)*32 + lane];
            MMA(acc[0][0], a0.x, a0.y, a0.z, a0.w, p0.x, p0.y);
            MMA(acc[0][1], a0.x, a0.y, a0.z, a0.w, p0.z, p0.w);
            MMA(acc[0][2], a0.x, a0.y, a0.z, a0.w, p1.x, p1.y);
            MMA(acc[0][3], a0.x, a0.y, a0.z, a0.w, p1.z, p1.w);
            MMA(acc[1][0], a1.x, a1.y, a1.z, a1.w, p0.x, p0.y);
            MMA(acc[1][1], a1.x, a1.y, a1.z, a1.w, p0.z, p0.w);
            MMA(acc[1][2], a1.x, a1.y, a1.z, a1.w, p1.x, p1.y);
            MMA(acc[1][3], a1.x, a1.y, a1.z, a1.w, p1.z, p1.w);
        }
    }
    CP_WAIT(0);            // P2 + P3 landed
    __syncthreads();       // everyone done reading XF / P1

    // epilogue: H1 = relu(acc + b1) -> A-fragment layout (overwrites P1/XF region)
    #pragma unroll
    for (int ct = 0; ct < 4; ct++) {
        int n0 = nq*32 + ct*8 + qk;
        float2 bb = *(const float2*)(b1s + n0);
        int kt = nq*2 + (ct >> 1);
        int j0 = (ct & 1) * 2;
        #pragma unroll
        for (int rb = 0; rb < 2; rb++) {
            uint32_t v0 = bf16_pack2(fmaxf(acc[rb][ct][0] + bb.x, 0.f), fmaxf(acc[rb][ct][1] + bb.y, 0.f));
            uint32_t v1 = bf16_pack2(fmaxf(acc[rb][ct][2] + bb.x, 0.f), fmaxf(acc[rb][ct][3] + bb.y, 0.f));
            uint32_t idx = (uint32_t)((((kt*4 + mt)*2 + rb)*32 + lane)*4 + j0);
            *(uint2*)(smem + SM_H1F + idx*4) = make_uint2(v0, v1);
        }
    }
    __syncthreads();

    // ---------------- Layer 2: 16 K-tiles ----------------
    #pragma unroll
    for (int rb = 0; rb < 2; rb++)
        #pragma unroll
        for (int ct = 0; ct < 4; ct++)
            #pragma unroll
            for (int j = 0; j < 4; j++) acc[rb][ct][j] = 0.f;

    {
        const uint4* pA = (const uint4*)(smem + SM_H1F) + mt*64 + lane;
        #pragma unroll
        for (int kt = 0; kt < 16; kt++) {
            uint4 a0 = pA[kt*256];
            uint4 a1 = pA[kt*256 + 32];
            uint4 p0 = P2q[(kt*16 + nq*2)*32 + lane];
            uint4 p1 = P2q[(kt*16 + nq*2 + 1)*32 + lane];
            MMA(acc[0][0], a0.x, a0.y, a0.z, a0.w, p0.x, p0.y);
            MMA(acc[0][1], a0.x, a0.y, a0.z, a0.w, p0.z, p0.w);
            MMA(acc[0][2], a0.x, a0.y, a0.z, a0.w, p1.x, p1.y);
            MMA(acc[0][3], a0.x, a0.y, a0.z, a0.w, p1.z, p1.w);
            MMA(acc[1][0], a1.x, a1.y, a1.z, a1.w, p0.x, p0.y);
            MMA(acc[1][1], a1.x, a1.y, a1.z, a1.w, p0.z, p0.w);
            MMA(acc[1][2], a1.x, a1.y, a1.z, a1.w, p1.x, p1.y);
            MMA(acc[1][3], a1.x, a1.y, a1.z, a1.w, p1.z, p1.w);
        }
    }
    __syncthreads();       // everyone done reading P2

    // kick color-head weight copies into dead P2 region (g4)
    {
        if (tid < 672) CP16(sb + SM_WC1 + (uint32_t)tid*16, (const char*)Wc1 + tid*16);
        if (tid < 48)  CP16(sb + SM_WC2 + (uint32_t)tid*16, (const char*)Wc2 + tid*16);
        if (tid < 16)  CP16(sb + SM_BC1 + (uint32_t)tid*16, (const char*)bc1 + tid*16);
        CP_COMMIT();
    }

    // ---------------- Layer 3: warp owns K-range nq*32..+32 of its 32 rows ------
    float geo[2][2][4];    // [rb][nt]
    #pragma unroll
    for (int rb = 0; rb < 2; rb++)
        #pragma unroll
        for (int nt = 0; nt < 2; nt++)
            #pragma unroll
            for (int j = 0; j < 4; j++) geo[rb][nt][j] = 0.f;

    #pragma unroll
    for (int ii = 0; ii < 2; ii++) {
        int kt3 = nq*2 + ii;
        uint4 bq = P3q[kt3*32 + lane];
        int n0 = nq*32 + (2*ii)*8 + qk;
        float2 bb0 = *(const float2*)(b2s + n0);
        float2 bb1 = *(const float2*)(b2s + n0 + 8);
        #pragma unroll
        for (int rb = 0; rb < 2; rb++) {
            uint32_t a0 = bf16_pack2(fmaxf(acc[rb][2*ii][0] + bb0.x, 0.f),  fmaxf(acc[rb][2*ii][1] + bb0.y, 0.f));
            uint32_t a1 = bf16_pack2(fmaxf(acc[rb][2*ii][2] + bb0.x, 0.f),  fmaxf(acc[rb][2*ii][3] + bb0.y, 0.f));
            uint32_t a2 = bf16_pack2(fmaxf(acc[rb][2*ii+1][0] + bb1.x, 0.f), fmaxf(acc[rb][2*ii+1][1] + bb1.y, 0.f));
            uint32_t a3 = bf16_pack2(fmaxf(acc[rb][2*ii+1][2] + bb1.x, 0.f), fmaxf(acc[rb][2*ii+1][3] + bb1.y, 0.f));
            MMA(geo[rb][0], a0, a1, a2, a3, bq.x, bq.y);
            MMA(geo[rb][1], a0, a1, a2, a3, bq.z, bq.w);
        }
    }

    // 8-way K reduction via SMEM (dead P2 region, stride 20 pad)
    if (nq > 0) {
        float* red = (float*)(smem + SM_RED) + (nq - 1) * 2560;
        #pragma unroll
        for (int rb = 0; rb < 2; rb++)
            #pragma unroll
            for (int nt = 0; nt < 2; nt++) {
                int c = nt*8 + qk;
                int rr = r0 + rb*16;
                red[rr*20 + c]       = geo[rb][nt][0];
                red[rr*20 + c + 1]   = geo[rb][nt][1];
                red[(rr+8)*20 + c]   = geo[rb][nt][2];
                red[(rr+8)*20 + c+1] = geo[rb][nt][3];
            }
    }
    __syncthreads();
    if (nq == 0) {
        const float* red = (const float*)(smem + SM_RED);
        float* geos = (float*)(smem + SM_GEOS);   // transposed [16][132]
        #pragma unroll
        for (int rb = 0; rb < 2; rb++)
            #pragma unroll
            for (int nt = 0; nt < 2; nt++) {
                int c = nt*8 + qk;
                #pragma unroll
                for (int hv = 0; hv < 2; hv++) {
                    int rr = r0 + rb*16 + hv*8;
                    float v0 = geo[rb][nt][2*hv+0];
                    float v1 = geo[rb][nt][2*hv+1];
                    #pragma unroll
                    for (int gg = 0; gg < 7; gg++) {
                        v0 += red[gg*2560 + rr*20 + c];
                        v1 += red[gg*2560 + rr*20 + c + 1];
                    }
                    geos[c*132 + rr]     = v0;
                    geos[(c+1)*132 + rr] = v1;
                }
            }
    }
    CP_WAIT(0);
    __syncthreads();

    // ---------------- color head ----------------
    {
        const float* wc1s = (const float*)(smem + SM_WC1);
        const float* wc2s = (const float*)(smem + SM_WC2);
        const float* bc1s = (const float*)(smem + SM_BC1);
        const float* geos = (const float*)(smem + SM_GEOS);
        float* dc   = (float*)(smem + SM_DIRC);
        float* cpart= (float*)(smem + SM_CPART);

        // phase A: dircontrib[j] (ray-constant), 64 threads
        if (tid < 64) {
            int j = tid;
            float h = bc1s[j];
            #pragma unroll
            for (int i = 0; i < 27; i++)
                h = fmaf(dirs[i], wc1s[i*64 + j], h);
            dc[j] = h;
        }
        __syncthreads();

        // phase B: 8 groups x 8 j's; fea[15] in regs
        const int m = tid & 127, g = tid >> 7;
        float fea[15];
        #pragma unroll
        for (int i = 0; i < 15; i++) fea[i] = geos[(1+i)*132 + m] + b3s[1+i];
        float a0 = 0.f, a1 = 0.f, a2 = 0.f;
        const int j0 = g * 8;
        #pragma unroll
        for (int jj = 0; jj < 8; jj++) {
            int j = j0 + jj;
            float h = dc[j];
            #pragma unroll
            for (int i = 0; i < 15; i++)
                h = fmaf(fea[i], wc1s[(27+i)*64 + j], h);
            h = fmaxf(h, 0.f);
            a0 = fmaf(h, wc2s[j*3+0], a0);
            a1 = fmaf(h, wc2s[j*3+1], a1);
            a2 = fmaf(h, wc2s[j*3+2], a2);
        }
        if (g > 0) {
            float* cp = cpart + ((g-1)*128 + m)*4;
            cp[0] = a0; cp[1] = a1; cp[2] = a2;
        }
        __syncthreads();
        if (g == 0) {
            #pragma unroll
            for (int gg = 0; gg < 7; gg++) {
                const float* cp = cpart + (gg*128 + m)*4;
                a0 += cp[0]; a1 += cp[1]; a2 += cp[2];
            }
            a0 += bc2s[0]; a1 += bc2s[1]; a2 += bc2s[2];
            float sx = geos[0*132 + m] + b3s[0];
            float sigma = (sx > 20.f) ? sx : log1pf(expf(sx));
            float alpha = 1.f - expf(-sigma * dtv);
            comp[m*4+0] = alpha;
            comp[m*4+1] = 1.f / (1.f + expf(-a0));
            comp[m*4+2] = 1.f / (1.f + expf(-a1));
            comp[m*4+3] = 1.f / (1.f + expf(-a2));
        }
    }
    __syncthreads();

    // ---------------- composite: warp-0 parallel scan ----------------
    if (tid < 32) {
        float av[4];
        #pragma unroll
        for (int j = 0; j < 4; j++) av[j] = comp[(lane*4 + j)*4 + 0];
        float q0 = 1.f - av[0] + 1e-10f;
        float q1 = 1.f - av[1] + 1e-10f;
        float q2 = 1.f - av[2] + 1e-10f;
        float q3 = 1.f - av[3] + 1e-10f;
        float inc = ((q0*q1)*(q2*q3));
        #pragma unroll
        for (int off = 1; off < 32; off <<= 1) {
            float t = __shfl_up_sync(0xFFFFFFFF, inc, off);
            if (lane >= off) inc *= t;
        }
        float T = __shfl_up_sync(0xFFFFFFFF, inc, 1);
        if (lane == 0) T = 1.f;
        float wsum = 0.f, dsum = 0.f, r = 0.f, g = 0.f, b = 0.f;
        #pragma unroll
        for (int j = 0; j < 4; j++) {
            int m = lane*4 + j;
            float alpha = av[j];
            float wgt = (T > 1e-4f) ? alpha * T : 0.f;
            wsum += wgt;
            float tsv = near_t + ((float)m + 0.5f) * dtv;
            dsum = fmaf(wgt, tsv, dsum);
            r = fmaf(wgt, comp[m*4+1], r);
            g = fmaf(wgt, comp[m*4+2], g);
            b = fmaf(wgt, comp[m*4+3], b);
            T *= (1.f - alpha + 1e-10f);
        }
        #pragma unroll
        for (int off = 16; off > 0; off >>= 1) {
            wsum += __shfl_xor_sync(0xFFFFFFFF, wsum, off);
            dsum += __shfl_xor_sync(0xFFFFFFFF, dsum, off);
            r    += __shfl_xor_sync(0xFFFFFFFF, r, off);
            g    += __shfl_xor_sync(0xFFFFFFFF, g, off);
            b    += __shfl_xor_sync(0xFFFFFFFF, b, off);
        }
        if (lane == 0) {
            float bgw = 1.f - wsum;
            out[ray*3+0] = r + bgw;
            out[ray*3+1] = g + bgw;
            out[ray*3+2] = b + bgw;
            out[4096*3 + ray] = dsum;
            out[4096*4 + ray] = fminf(fmaxf(wsum, 1e-12f), 1000.f);
        }
    }
}

// ===================== launch =====================
extern "C" void kernel_launch(void* const* d_in, const int* in_sizes, int n_in,
                              void* d_out, int out_size) {
    const float* rays_o = (const float*)d_in[0];
    const float* rays_d = (const float*)d_in[1];
    const float* W1  = (const float*)d_in[2];
    const float* b1  = (const float*)d_in[3];
    const float* W2  = (const float*)d_in[4];
    const float* b2  = (const float*)d_in[5];
    const float* W3  = (const float*)d_in[6];
    const float* b3  = (const float*)d_in[7];
    const float* Wc1 = (const float*)d_in[8];
    const float* bc1 = (const float*)d_in[9];
    const float* Wc2 = (const float*)d_in[10];
    const float* bc2 = (const float*)d_in[11];
    float* out = (float*)d_out;

    prep_pack<<<84, 256>>>(W1, W2, W3);
    cudaFuncSetAttribute(nerf_mma, cudaFuncAttributeMaxDynamicSharedMemorySize, SMEM_BYTES);
    nerf_mma<<<4096, 1024, SMEM_BYTES>>>(rays_o, rays_d, b1, b2, b3,
                                         Wc1, bc1, Wc2, bc2, out);
}